// round 2
// baseline (speedup 1.0000x reference)
#include <cuda_runtime.h>
#include <cuda_bf16.h>
#include <math.h>

// ---------------------------------------------------------------------------
// Scratch (device globals; no allocation allowed)
// ---------------------------------------------------------------------------
__device__ float g_proj_lang[32 * 64 * 512];    // [B][Nl][q(256)|k(256)]
__device__ float g_proj_vis [32 * 256 * 512];   // [B][Nv][q(256)|k(256)]
__device__ float g_sim      [2 * 32 * 32];      // [v2t | t2v]

// ---------------------------------------------------------------------------
// Kernel A: projection GEMM  out[m][n] = X[m][:]·W[n][:] + bias[n], n in [0,512)
// X: [M,256] row-major, W: in_proj_weight [768,256] (rows 0..511 used)
// ---------------------------------------------------------------------------
__global__ void __launch_bounds__(256) proj_kernel(const float* __restrict__ X,
                                                   const float* __restrict__ W,
                                                   const float* __restrict__ bias,
                                                   int which)
{
    float* out = which ? g_proj_vis : g_proj_lang;
    __shared__ float As[32][68];
    __shared__ float Bs[32][68];

    const int bm = blockIdx.y * 64;
    const int bn = blockIdx.x * 64;
    const int tid  = threadIdx.x;
    const int trow = tid >> 4;   // 0..15
    const int tcol = tid & 15;   // 0..15

    float cc[4][4] = {};

    for (int k0 = 0; k0 < 256; k0 += 32) {
        #pragma unroll
        for (int it = 0; it < 2; ++it) {
            int id = tid + it * 256;       // 0..511
            int r  = id >> 3;              // 0..63
            int qc = id & 7;               // 0..7
            float4 va = *(const float4*)(X + (size_t)(bm + r) * 256 + k0 + qc * 4);
            As[qc*4+0][r] = va.x; As[qc*4+1][r] = va.y;
            As[qc*4+2][r] = va.z; As[qc*4+3][r] = va.w;
            float4 vb = *(const float4*)(W + (size_t)(bn + r) * 256 + k0 + qc * 4);
            Bs[qc*4+0][r] = vb.x; Bs[qc*4+1][r] = vb.y;
            Bs[qc*4+2][r] = vb.z; Bs[qc*4+3][r] = vb.w;
        }
        __syncthreads();
        #pragma unroll
        for (int k = 0; k < 32; ++k) {
            float4 a = *(const float4*)&As[k][trow * 4];
            float4 b = *(const float4*)&Bs[k][tcol * 4];
            cc[0][0] += a.x*b.x; cc[0][1] += a.x*b.y; cc[0][2] += a.x*b.z; cc[0][3] += a.x*b.w;
            cc[1][0] += a.y*b.x; cc[1][1] += a.y*b.y; cc[1][2] += a.y*b.z; cc[1][3] += a.y*b.w;
            cc[2][0] += a.z*b.x; cc[2][1] += a.z*b.y; cc[2][2] += a.z*b.z; cc[2][3] += a.z*b.w;
            cc[3][0] += a.w*b.x; cc[3][1] += a.w*b.y; cc[3][2] += a.w*b.z; cc[3][3] += a.w*b.w;
        }
        __syncthreads();
    }

    #pragma unroll
    for (int x = 0; x < 4; ++x) {
        #pragma unroll
        for (int y = 0; y < 4; ++y) {
            int m = bm + trow * 4 + x;
            int n = bn + tcol * 4 + y;
            out[(size_t)m * 512 + n] = cc[x][y] + bias[n];
        }
    }
}

// ---------------------------------------------------------------------------
// Kernel B: fused pairwise similarity
//   sim[i][j] = mean_a( mean(top3_b( mean_h softmax_b(q_ia·k_jb / 8) )) ) * 100
// One block per (i,j). k-chunk (64 targets x 256 floats) in swizzled SMEM.
// Each warp processes 2 anchors; lane owns b = c*64 + {lane, lane+32}.
// ---------------------------------------------------------------------------
__device__ __forceinline__ void load_k_chunk(float* ks, const float* pt, int c)
{
    const int tid = threadIdx.x;
    #pragma unroll
    for (int it = 0; it < 16; ++it) {
        int id = tid + it * 256;          // 0..4095 float4 slots
        int r  = id >> 6;                 // row 0..63
        int q  = id & 63;                 // quad 0..63
        float4 v = *(const float4*)(pt + (size_t)(c * 64 + r) * 512 + 256 + q * 4);
        ((float4*)ks)[r * 64 + (q ^ (r & 7))] = v;   // XOR-8 swizzle
    }
}

template<int NA, int NT>
__global__ void __launch_bounds__(256) sim_kernel()
{
    constexpr int NCHUNK = NT / 64;
    constexpr int NB     = 2 * NCHUNK;        // score regs per head per anchor

    extern __shared__ float smem[];
    float* ks   = smem;                        // 64 * 256 floats (swizzled)
    float* qs   = smem + 64 * 256;             // 8 warps * 2 anchors * 256
    float* wacc = qs + 8 * 2 * 256;            // 8

    const int i    = blockIdx.y;
    const int j    = blockIdx.x;
    const int tid  = threadIdx.x;
    const int w    = tid >> 5;
    const int lane = tid & 31;

    const float* pa = ((NA == 256) ? g_proj_vis : g_proj_lang) + (size_t)i * NA * 512;
    const float* pt = ((NA == 256) ? g_proj_lang : g_proj_vis) + (size_t)j * NT * 512;

    float acc = 0.f;

    if (NCHUNK == 1) { load_k_chunk(ks, pt, 0); __syncthreads(); }

    const int PASSES = NA / 16;
    for (int pass = 0; pass < PASSES; ++pass) {
        const int a0 = pass * 16 + w * 2;
        {   // stage 2 anchors' q into warp-private smem
            const float4* s0 = (const float4*)(pa + (size_t)a0 * 512);
            const float4* s1 = (const float4*)(pa + (size_t)(a0 + 1) * 512);
            float4* d0 = (float4*)(qs + (w * 2 + 0) * 256);
            float4* d1 = (float4*)(qs + (w * 2 + 1) * 256);
            d0[lane] = s0[lane]; d0[lane + 32] = s0[lane + 32];
            d1[lane] = s1[lane]; d1[lane + 32] = s1[lane + 32];
        }
        __syncwarp();

        float s[2][4][NB];
        #pragma unroll
        for (int a = 0; a < 2; ++a)
            #pragma unroll
            for (int h = 0; h < 4; ++h)
                #pragma unroll
                for (int bi = 0; bi < NB; ++bi) s[a][h][bi] = 0.f;

        for (int c = 0; c < NCHUNK; ++c) {
            if (NCHUNK > 1) { __syncthreads(); load_k_chunk(ks, pt, c); __syncthreads(); }

            const float4* q0p = (const float4*)(qs + (w * 2 + 0) * 256);
            const float4* q1p = (const float4*)(qs + (w * 2 + 1) * 256);
            const float4* kp  = (const float4*)ks;
            const int swz = lane & 7;

            #pragma unroll
            for (int h = 0; h < 4; ++h) {
                #pragma unroll
                for (int dq = 0; dq < 16; ++dq) {
                    const int col = h * 16 + dq;
                    float4 q0 = q0p[col];
                    float4 q1 = q1p[col];
                    float4 kA = kp[lane * 64 + (col ^ swz)];
                    float4 kB = kp[(lane + 32) * 64 + (col ^ swz)];
                    s[0][h][2*c+0] += q0.x*kA.x + q0.y*kA.y + q0.z*kA.z + q0.w*kA.w;
                    s[0][h][2*c+1] += q0.x*kB.x + q0.y*kB.y + q0.z*kB.z + q0.w*kB.w;
                    s[1][h][2*c+0] += q1.x*kA.x + q1.y*kA.y + q1.z*kA.z + q1.w*kA.w;
                    s[1][h][2*c+1] += q1.x*kB.x + q1.y*kB.y + q1.z*kB.z + q1.w*kB.w;
                }
            }
        }

        // scale 1/sqrt(hd) = 0.125
        #pragma unroll
        for (int a = 0; a < 2; ++a)
            #pragma unroll
            for (int h = 0; h < 4; ++h)
                #pragma unroll
                for (int bi = 0; bi < NB; ++bi) s[a][h][bi] *= 0.125f;

        #pragma unroll
        for (int a = 0; a < 2; ++a) {
            float am[NB];
            #pragma unroll
            for (int bi = 0; bi < NB; ++bi) am[bi] = 0.f;

            #pragma unroll
            for (int h = 0; h < 4; ++h) {
                float m = s[a][h][0];
                #pragma unroll
                for (int bi = 1; bi < NB; ++bi) m = fmaxf(m, s[a][h][bi]);
                #pragma unroll
                for (int off = 16; off; off >>= 1)
                    m = fmaxf(m, __shfl_xor_sync(0xffffffffu, m, off));
                float e[NB]; float Z = 0.f;
                #pragma unroll
                for (int bi = 0; bi < NB; ++bi) { e[bi] = __expf(s[a][h][bi] - m); Z += e[bi]; }
                #pragma unroll
                for (int off = 16; off; off >>= 1)
                    Z += __shfl_xor_sync(0xffffffffu, Z, off);
                float r = 0.25f / Z;   // includes mean over 4 heads
                #pragma unroll
                for (int bi = 0; bi < NB; ++bi) am[bi] += e[bi] * r;
            }

            // top-3 over the NT values of am (spread across the warp)
            unsigned msk = 0; float sum3 = 0.f;
            #pragma unroll
            for (int rr = 0; rr < 3; ++rr) {
                float bv = -1e30f; int bg = lane;
                #pragma unroll
                for (int bi = 0; bi < NB; ++bi)
                    if (!((msk >> bi) & 1u) && am[bi] > bv) { bv = am[bi]; bg = (bi << 5) | lane; }
                #pragma unroll
                for (int off = 16; off; off >>= 1) {
                    float ov = __shfl_xor_sync(0xffffffffu, bv, off);
                    int   og = __shfl_xor_sync(0xffffffffu, bg, off);
                    if (ov > bv || (ov == bv && og > bg)) { bv = ov; bg = og; }
                }
                if ((bg & 31) == lane) msk |= 1u << (bg >> 5);
                sum3 += bv;
            }
            acc += sum3;   // warp-uniform
        }
    }

    if (lane == 0) wacc[w] = acc;
    __syncthreads();
    if (tid == 0) {
        float tot = 0.f;
        #pragma unroll
        for (int x = 0; x < 8; ++x) tot += wacc[x];
        float* simout = g_sim + ((NA == 256) ? 0 : 1024);
        simout[i * 32 + j] = tot * (100.f / (3.f * (float)NA));
    }
}

// ---------------------------------------------------------------------------
// Kernel C: contrastive loss from the two 32x32 sim matrices
// ---------------------------------------------------------------------------
__global__ void loss_kernel(float* __restrict__ out)
{
    __shared__ float red[64];
    const int t   = threadIdx.x;         // 0..63
    const int dir = t >> 5;
    const int row = t & 31;
    const float* S = g_sim + dir * 1024;

    float pos = S[row * 33];
    float t1 = -1e30f, t2 = -1e30f, t3 = -1e30f;
    for (int j = 0; j < 32; ++j) {
        if (j == row) continue;
        float v = S[row * 32 + j];
        if      (v > t1) { t3 = t2; t2 = t1; t1 = v; }
        else if (v > t2) { t3 = t2; t2 = v; }
        else if (v > t3) { t3 = v; }
    }
    const float invT = 1.0f / 0.07f;
    float l0 = pos * invT, l1 = t1 * invT, l2 = t2 * invT, l3 = t3 * invT;
    float m  = fmaxf(fmaxf(l0, l1), fmaxf(l2, l3));
    float Z  = expf(l0 - m) + expf(l1 - m) + expf(l2 - m) + expf(l3 - m);
    red[t] = -(l0 - m - logf(Z));
    __syncthreads();
    if (t == 0) {
        float s0 = 0.f, s1 = 0.f;
        for (int r = 0; r < 32; ++r) { s0 += red[r]; s1 += red[32 + r]; }
        out[0] = 0.5f * (s0 / 32.f) + 0.5f * (s1 / 32.f);
    }
}

// ---------------------------------------------------------------------------
// Launch
// ---------------------------------------------------------------------------
extern "C" void kernel_launch(void* const* d_in, const int* in_sizes, int n_in,
                              void* d_out, int out_size)
{
    const float* lang = (const float*)d_in[0];   // [32,64,256]
    const float* vis  = (const float*)d_in[1];   // [32,256,256]
    const float* W    = (const float*)d_in[2];   // [768,256]
    const float* bias = (const float*)d_in[3];   // [768]

    proj_kernel<<<dim3(8, 32),  256>>>(lang, W, bias, 0);
    proj_kernel<<<dim3(8, 128), 256>>>(vis,  W, bias, 1);

    const size_t shmem = (size_t)(64 * 256 + 8 * 2 * 256 + 8) * sizeof(float); // ~80KB
    cudaFuncSetAttribute(sim_kernel<256, 64>,
                         cudaFuncAttributeMaxDynamicSharedMemorySize, (int)shmem);
    cudaFuncSetAttribute(sim_kernel<64, 256>,
                         cudaFuncAttributeMaxDynamicSharedMemorySize, (int)shmem);

    sim_kernel<256, 64><<<dim3(32, 32), 256, shmem>>>();   // v2t: anchor=vis, target=lang
    sim_kernel<64, 256><<<dim3(32, 32), 256, shmem>>>();   // t2v: anchor=lang, target=vis

    loss_kernel<<<1, 64>>>((float*)d_out);
}

// round 3
// speedup vs baseline: 2.2684x; 2.2684x over previous
#include <cuda_runtime.h>
#include <cuda_bf16.h>
#include <math.h>
#include <stdint.h>

// ---------------------------------------------------------------------------
// Scratch (device globals; no allocation allowed)
// ---------------------------------------------------------------------------
__device__ float g_proj_lang[32 * 64 * 512];            // [B*Nl][q(256)|k(256)]
__device__ float g_proj_vis [32 * 256 * 512];           // [B*Nv][q(256)|k(256)]
__device__ float g_sc_v2t   [8192ull * 4 * 2048];       // [vis_tok][h][lang_tok]
__device__ float g_sc_t2v   [2048ull * 4 * 8192];       // [lang_tok][h][vis_tok]
__device__ float g_sim      [2 * 32 * 32];              // [v2t | t2v]

// ---------------------------------------------------------------------------
// Kernel A: projection GEMM  out[m][n] = X[m][:]·W[n][:] + bias[n], n in [0,512)
// ---------------------------------------------------------------------------
__global__ void __launch_bounds__(256) proj_kernel(const float* __restrict__ X,
                                                   const float* __restrict__ W,
                                                   const float* __restrict__ bias,
                                                   int which)
{
    float* out = which ? g_proj_vis : g_proj_lang;
    __shared__ float As[32][68];
    __shared__ float Bs[32][68];

    const int bm = blockIdx.y * 64;
    const int bn = blockIdx.x * 64;
    const int tid  = threadIdx.x;
    const int trow = tid >> 4;
    const int tcol = tid & 15;

    float cc[4][4] = {};

    for (int k0 = 0; k0 < 256; k0 += 32) {
        #pragma unroll
        for (int it = 0; it < 2; ++it) {
            int id = tid + it * 256;
            int r  = id >> 3;
            int qc = id & 7;
            float4 va = *(const float4*)(X + (size_t)(bm + r) * 256 + k0 + qc * 4);
            As[qc*4+0][r] = va.x; As[qc*4+1][r] = va.y;
            As[qc*4+2][r] = va.z; As[qc*4+3][r] = va.w;
            float4 vb = *(const float4*)(W + (size_t)(bn + r) * 256 + k0 + qc * 4);
            Bs[qc*4+0][r] = vb.x; Bs[qc*4+1][r] = vb.y;
            Bs[qc*4+2][r] = vb.z; Bs[qc*4+3][r] = vb.w;
        }
        __syncthreads();
        #pragma unroll
        for (int k = 0; k < 32; ++k) {
            float4 a = *(const float4*)&As[k][trow * 4];
            float4 b = *(const float4*)&Bs[k][tcol * 4];
            cc[0][0] += a.x*b.x; cc[0][1] += a.x*b.y; cc[0][2] += a.x*b.z; cc[0][3] += a.x*b.w;
            cc[1][0] += a.y*b.x; cc[1][1] += a.y*b.y; cc[1][2] += a.y*b.z; cc[1][3] += a.y*b.w;
            cc[2][0] += a.z*b.x; cc[2][1] += a.z*b.y; cc[2][2] += a.z*b.z; cc[2][3] += a.z*b.w;
            cc[3][0] += a.w*b.x; cc[3][1] += a.w*b.y; cc[3][2] += a.w*b.z; cc[3][3] += a.w*b.w;
        }
        __syncthreads();
    }

    #pragma unroll
    for (int x = 0; x < 4; ++x) {
        #pragma unroll
        for (int y = 0; y < 4; ++y) {
            int m = bm + trow * 4 + x;
            int n = bn + tcol * 4 + y;
            out[(size_t)m * 512 + n] = cc[x][y] + bias[n];
        }
    }
}

// ---------------------------------------------------------------------------
// tf32 helpers
// ---------------------------------------------------------------------------
__device__ __forceinline__ uint32_t f2tf32(float v) {
    uint32_t r;
    asm("cvt.rna.tf32.f32 %0, %1;" : "=r"(r) : "f"(v));
    return r;
}

__device__ __forceinline__ void mma_tf32(float c[4],
                                         uint32_t a0, uint32_t a1, uint32_t a2, uint32_t a3,
                                         uint32_t b0, uint32_t b1)
{
    asm volatile(
        "mma.sync.aligned.m16n8k8.row.col.f32.tf32.tf32.f32 "
        "{%0,%1,%2,%3}, {%4,%5,%6,%7}, {%8,%9}, {%0,%1,%2,%3};\n"
        : "+f"(c[0]), "+f"(c[1]), "+f"(c[2]), "+f"(c[3])
        : "r"(a0), "r"(a1), "r"(a2), "r"(a3), "r"(b0), "r"(b1));
}

// ---------------------------------------------------------------------------
// Kernel B: score GEMM (tf32 tensor cores)
//   out[m][h][n] = 0.125 * sum_d Q[m][h*64+d] * K[n][256 + h*64+d]
// Block tile: 128(m) x 64(n), full K=64 in smem. Grid (Ntot/64, M/128, 4).
// ---------------------------------------------------------------------------
__global__ void __launch_bounds__(256) score_gemm(const float* __restrict__ Q,
                                                  const float* __restrict__ K,
                                                  float* __restrict__ out,
                                                  int Ntot)
{
    extern __shared__ uint32_t smemU[];
    uint32_t* As = smemU;               // [128][68]
    uint32_t* Bs = smemU + 128 * 68;    // [64][68]

    const int n0  = blockIdx.x * 64;
    const int m0  = blockIdx.y * 128;
    const int h   = blockIdx.z;
    const int tid = threadIdx.x;
    const int w    = tid >> 5;
    const int lane = tid & 31;

    // Load A tile: 128 rows x 16 float4
    #pragma unroll
    for (int it = 0; it < 8; ++it) {
        int id = tid + it * 256;
        int r  = id >> 4;
        int q  = id & 15;
        float4 v = *(const float4*)(Q + (size_t)(m0 + r) * 512 + h * 64 + q * 4);
        uint32_t* d = As + r * 68 + q * 4;
        d[0] = f2tf32(v.x); d[1] = f2tf32(v.y); d[2] = f2tf32(v.z); d[3] = f2tf32(v.w);
    }
    // Load B tile: 64 rows x 16 float4 (k-part at offset 256)
    #pragma unroll
    for (int it = 0; it < 4; ++it) {
        int id = tid + it * 256;
        int r  = id >> 4;
        int q  = id & 15;
        float4 v = *(const float4*)(K + (size_t)(n0 + r) * 512 + 256 + h * 64 + q * 4);
        uint32_t* d = Bs + r * 68 + q * 4;
        d[0] = f2tf32(v.x); d[1] = f2tf32(v.y); d[2] = f2tf32(v.z); d[3] = f2tf32(v.w);
    }
    __syncthreads();

    const int wm = (w & 3) * 32;    // warp m offset (0..96)
    const int wn = (w >> 2) * 32;   // warp n offset (0 or 32)
    const uint32_t* Aw = As + wm * 68;
    const uint32_t* Bw = Bs + wn * 68;
    const int qrow = lane >> 2;     // 0..7
    const int qcol = lane & 3;      // 0..3

    float c[2][4][4] = {};

    #pragma unroll
    for (int kk = 0; kk < 8; ++kk) {
        uint32_t a[2][4];
        #pragma unroll
        for (int mt = 0; mt < 2; ++mt) {
            const uint32_t* p = Aw + (mt * 16 + qrow) * 68 + kk * 8 + qcol;
            a[mt][0] = p[0];
            a[mt][1] = p[8 * 68];
            a[mt][2] = p[4];
            a[mt][3] = p[8 * 68 + 4];
        }
        uint32_t b[4][2];
        #pragma unroll
        for (int nt = 0; nt < 4; ++nt) {
            const uint32_t* p = Bw + (nt * 8 + qrow) * 68 + kk * 8 + qcol;
            b[nt][0] = p[0];
            b[nt][1] = p[4];
        }
        #pragma unroll
        for (int mt = 0; mt < 2; ++mt)
            #pragma unroll
            for (int nt = 0; nt < 4; ++nt)
                mma_tf32(c[mt][nt], a[mt][0], a[mt][1], a[mt][2], a[mt][3],
                         b[nt][0], b[nt][1]);
    }

    // Epilogue: scale by 1/sqrt(64) = 0.125, store
    #pragma unroll
    for (int mt = 0; mt < 2; ++mt) {
        #pragma unroll
        for (int nt = 0; nt < 4; ++nt) {
            int row = m0 + wm + mt * 16 + qrow;
            int col = n0 + wn + nt * 8 + qcol * 2;
            float* o0 = out + ((size_t)row * 4 + h) * (size_t)Ntot + col;
            float* o1 = o0 + (size_t)8 * 4 * (size_t)Ntot;
            *(float2*)o0 = make_float2(c[mt][nt][0] * 0.125f, c[mt][nt][1] * 0.125f);
            *(float2*)o1 = make_float2(c[mt][nt][2] * 0.125f, c[mt][nt][3] * 0.125f);
        }
    }
}

// ---------------------------------------------------------------------------
// Kernel C: softmax + head-mean + top3 + anchor-mean -> sim[i][j]
// One block per (i,j). Warp w handles anchors a = w, w+8, ...
// Lane owns targets b = bi*32 + lane (bi < NB = NT/32).
// ---------------------------------------------------------------------------
template<int NT>
__global__ void __launch_bounds__(256) softmax_kernel(const float* __restrict__ sc,
                                                      int NA, int Ntot,
                                                      float* __restrict__ simout)
{
    constexpr int NB = NT / 32;
    __shared__ float wacc[8];

    const int i    = blockIdx.y;
    const int j    = blockIdx.x;
    const int tid  = threadIdx.x;
    const int w    = tid >> 5;
    const int lane = tid & 31;

    float acc = 0.f;

    for (int a = w; a < NA; a += 8) {
        const float* base = sc + ((size_t)(i * NA + a) * 4) * (size_t)Ntot
                               + (size_t)j * NT + lane;
        float s[4][NB];
        #pragma unroll
        for (int h = 0; h < 4; ++h)
            #pragma unroll
            for (int bi = 0; bi < NB; ++bi)
                s[h][bi] = base[(size_t)h * Ntot + bi * 32];

        float am[NB];
        #pragma unroll
        for (int bi = 0; bi < NB; ++bi) am[bi] = 0.f;

        #pragma unroll
        for (int h = 0; h < 4; ++h) {
            float m = s[h][0];
            #pragma unroll
            for (int bi = 1; bi < NB; ++bi) m = fmaxf(m, s[h][bi]);
            #pragma unroll
            for (int off = 16; off; off >>= 1)
                m = fmaxf(m, __shfl_xor_sync(0xffffffffu, m, off));
            float e[NB]; float Z = 0.f;
            #pragma unroll
            for (int bi = 0; bi < NB; ++bi) { e[bi] = __expf(s[h][bi] - m); Z += e[bi]; }
            #pragma unroll
            for (int off = 16; off; off >>= 1)
                Z += __shfl_xor_sync(0xffffffffu, Z, off);
            float r = 0.25f / Z;   // includes mean over 4 heads
            #pragma unroll
            for (int bi = 0; bi < NB; ++bi) am[bi] += e[bi] * r;
        }

        // top-3 over NT values spread across warp
        unsigned msk = 0; float sum3 = 0.f;
        #pragma unroll
        for (int rr = 0; rr < 3; ++rr) {
            float bv = -1e30f; int bg = lane;
            #pragma unroll
            for (int bi = 0; bi < NB; ++bi)
                if (!((msk >> bi) & 1u) && am[bi] > bv) { bv = am[bi]; bg = (bi << 5) | lane; }
            #pragma unroll
            for (int off = 16; off; off >>= 1) {
                float ov = __shfl_xor_sync(0xffffffffu, bv, off);
                int   og = __shfl_xor_sync(0xffffffffu, bg, off);
                if (ov > bv || (ov == bv && og > bg)) { bv = ov; bg = og; }
            }
            if ((bg & 31) == lane) msk |= 1u << (bg >> 5);
            sum3 += bv;
        }
        acc += sum3;   // warp-uniform
    }

    if (lane == 0) wacc[w] = acc;
    __syncthreads();
    if (tid == 0) {
        float tot = 0.f;
        #pragma unroll
        for (int x = 0; x < 8; ++x) tot += wacc[x];
        simout[i * 32 + j] = tot * (100.f / (3.f * (float)NA));
    }
}

// ---------------------------------------------------------------------------
// Kernel D: contrastive loss from the two 32x32 sim matrices
// ---------------------------------------------------------------------------
__global__ void loss_kernel(float* __restrict__ out)
{
    __shared__ float red[64];
    const int t   = threadIdx.x;
    const int dir = t >> 5;
    const int row = t & 31;
    const float* S = g_sim + dir * 1024;

    float pos = S[row * 33];
    float t1 = -1e30f, t2 = -1e30f, t3 = -1e30f;
    for (int j = 0; j < 32; ++j) {
        if (j == row) continue;
        float v = S[row * 32 + j];
        if      (v > t1) { t3 = t2; t2 = t1; t1 = v; }
        else if (v > t2) { t3 = t2; t2 = v; }
        else if (v > t3) { t3 = v; }
    }
    const float invT = 1.0f / 0.07f;
    float l0 = pos * invT, l1 = t1 * invT, l2 = t2 * invT, l3 = t3 * invT;
    float m  = fmaxf(fmaxf(l0, l1), fmaxf(l2, l3));
    float Z  = expf(l0 - m) + expf(l1 - m) + expf(l2 - m) + expf(l3 - m);
    red[t] = -(l0 - m - logf(Z));
    __syncthreads();
    if (t == 0) {
        float s0 = 0.f, s1 = 0.f;
        for (int r = 0; r < 32; ++r) { s0 += red[r]; s1 += red[32 + r]; }
        out[0] = 0.5f * (s0 / 32.f) + 0.5f * (s1 / 32.f);
    }
}

// ---------------------------------------------------------------------------
// Launch
// ---------------------------------------------------------------------------
extern "C" void kernel_launch(void* const* d_in, const int* in_sizes, int n_in,
                              void* d_out, int out_size)
{
    const float* lang = (const float*)d_in[0];   // [32,64,256]
    const float* vis  = (const float*)d_in[1];   // [32,256,256]
    const float* W    = (const float*)d_in[2];   // [768,256]
    const float* bias = (const float*)d_in[3];   // [768]

    // Resolve device-global addresses (host side, not capturable ops but legal)
    static float *p_lang = nullptr, *p_vis = nullptr, *p_v2t = nullptr,
                 *p_t2v = nullptr, *p_sim = nullptr;
    if (!p_lang) {
        cudaGetSymbolAddress((void**)&p_lang, g_proj_lang);
        cudaGetSymbolAddress((void**)&p_vis,  g_proj_vis);
        cudaGetSymbolAddress((void**)&p_v2t,  g_sc_v2t);
        cudaGetSymbolAddress((void**)&p_t2v,  g_sc_t2v);
        cudaGetSymbolAddress((void**)&p_sim,  g_sim);
        const int gemm_smem = (128 * 68 + 64 * 68) * 4;   // 52224 B
        cudaFuncSetAttribute(score_gemm,
                             cudaFuncAttributeMaxDynamicSharedMemorySize, gemm_smem);
    }
    const int gemm_smem = (128 * 68 + 64 * 68) * 4;

    proj_kernel<<<dim3(8, 32),  256>>>(lang, W, bias, 0);
    proj_kernel<<<dim3(8, 128), 256>>>(vis,  W, bias, 1);

    // v2t: Q = vis (M=8192), K = lang (Ntot=2048)
    score_gemm<<<dim3(2048 / 64, 8192 / 128, 4), 256, gemm_smem>>>(p_vis, p_lang, p_v2t, 2048);
    // t2v: Q = lang (M=2048), K = vis (Ntot=8192)
    score_gemm<<<dim3(8192 / 64, 2048 / 128, 4), 256, gemm_smem>>>(p_lang, p_vis, p_t2v, 8192);

    // v2t: NA=256 anchors per i, NT=64 targets per j
    softmax_kernel<64> <<<dim3(32, 32), 256>>>(p_v2t, 256, 2048, p_sim);
    // t2v: NA=64, NT=256
    softmax_kernel<256><<<dim3(32, 32), 256>>>(p_t2v, 64, 8192, p_sim + 1024);

    loss_kernel<<<1, 64>>>((float*)d_out);
}

// round 5
// speedup vs baseline: 2.6830x; 1.1828x over previous
#include <cuda_runtime.h>
#include <cuda_bf16.h>
#include <math.h>
#include <stdint.h>

// ---------------------------------------------------------------------------
// Scratch (device globals; no allocation allowed)
// ---------------------------------------------------------------------------
__device__ float g_proj_lang[32 * 64 * 512];    // [tok][q(256)|k(256)]
__device__ float g_proj_vis [32 * 256 * 512];
__device__ float g_part     [2 * 32 * 32 * 4];  // [dir][i][j][chunk]

// ---------------------------------------------------------------------------
// Kernel A: projection GEMM  out[m][n] = X[m][:]·W[n][:] + bias[n], n in [0,512)
// ---------------------------------------------------------------------------
__global__ void __launch_bounds__(256) proj_kernel(const float* __restrict__ X,
                                                   const float* __restrict__ W,
                                                   const float* __restrict__ bias,
                                                   int which)
{
    float* out = which ? g_proj_vis : g_proj_lang;
    __shared__ float As[32][68];
    __shared__ float Bs[32][68];

    const int bm = blockIdx.y * 64;
    const int bn = blockIdx.x * 64;
    const int tid  = threadIdx.x;
    const int trow = tid >> 4;
    const int tcol = tid & 15;

    float cc[4][4] = {};

    for (int k0 = 0; k0 < 256; k0 += 32) {
        #pragma unroll
        for (int it = 0; it < 2; ++it) {
            int id = tid + it * 256;
            int r  = id >> 3;
            int qc = id & 7;
            float4 va = *(const float4*)(X + (size_t)(bm + r) * 256 + k0 + qc * 4);
            As[qc*4+0][r] = va.x; As[qc*4+1][r] = va.y;
            As[qc*4+2][r] = va.z; As[qc*4+3][r] = va.w;
            float4 vb = *(const float4*)(W + (size_t)(bn + r) * 256 + k0 + qc * 4);
            Bs[qc*4+0][r] = vb.x; Bs[qc*4+1][r] = vb.y;
            Bs[qc*4+2][r] = vb.z; Bs[qc*4+3][r] = vb.w;
        }
        __syncthreads();
        #pragma unroll
        for (int k = 0; k < 32; ++k) {
            float4 a = *(const float4*)&As[k][trow * 4];
            float4 b = *(const float4*)&Bs[k][tcol * 4];
            cc[0][0] += a.x*b.x; cc[0][1] += a.x*b.y; cc[0][2] += a.x*b.z; cc[0][3] += a.x*b.w;
            cc[1][0] += a.y*b.x; cc[1][1] += a.y*b.y; cc[1][2] += a.y*b.z; cc[1][3] += a.y*b.w;
            cc[2][0] += a.z*b.x; cc[2][1] += a.z*b.y; cc[2][2] += a.z*b.z; cc[2][3] += a.z*b.w;
            cc[3][0] += a.w*b.x; cc[3][1] += a.w*b.y; cc[3][2] += a.w*b.z; cc[3][3] += a.w*b.w;
        }
        __syncthreads();
    }

    #pragma unroll
    for (int x = 0; x < 4; ++x)
        #pragma unroll
        for (int y = 0; y < 4; ++y) {
            int m = bm + trow * 4 + x;
            int n = bn + tcol * 4 + y;
            out[(size_t)m * 512 + n] = cc[x][y] + bias[n];
        }
}

// ---------------------------------------------------------------------------
// bf16 MMA helpers
// ---------------------------------------------------------------------------
__device__ __forceinline__ uint32_t pack_bf2(float a, float b) {
    __nv_bfloat162 t = __floats2bfloat162_rn(a, b);
    return *(uint32_t*)&t;
}

__device__ __forceinline__ void ldsm_x4(uint32_t& r0, uint32_t& r1,
                                        uint32_t& r2, uint32_t& r3, uint32_t addr) {
    asm volatile("ldmatrix.sync.aligned.m8n8.x4.shared.b16 {%0,%1,%2,%3}, [%4];"
                 : "=r"(r0), "=r"(r1), "=r"(r2), "=r"(r3) : "r"(addr));
}

__device__ __forceinline__ void mma_bf16(float c[4],
                                         uint32_t a0, uint32_t a1, uint32_t a2, uint32_t a3,
                                         uint32_t b0, uint32_t b1) {
    asm volatile(
        "mma.sync.aligned.m16n8k16.row.col.f32.bf16.bf16.f32 "
        "{%0,%1,%2,%3}, {%4,%5,%6,%7}, {%8,%9}, {%0,%1,%2,%3};\n"
        : "+f"(c[0]), "+f"(c[1]), "+f"(c[2]), "+f"(c[3])
        : "r"(a0), "r"(a1), "r"(a2), "r"(a3), "r"(b0), "r"(b1));
}

template<int NB>
__device__ __forceinline__ float top3_sum(const float* v, int lane) {
    float am[NB];
    #pragma unroll
    for (int bi = 0; bi < NB; ++bi) am[bi] = v[bi * 32 + lane];
    unsigned msk = 0; float sum3 = 0.f;
    #pragma unroll
    for (int rr = 0; rr < 3; ++rr) {
        float bv = -1e30f; int bg = lane;
        #pragma unroll
        for (int bi = 0; bi < NB; ++bi)
            if (!((msk >> bi) & 1u) && am[bi] > bv) { bv = am[bi]; bg = (bi << 5) | lane; }
        #pragma unroll
        for (int off = 16; off; off >>= 1) {
            float ov = __shfl_xor_sync(0xffffffffu, bv, off);
            int   og = __shfl_xor_sync(0xffffffffu, bg, off);
            if (ov > bv || (ov == bv && og > bg)) { bv = ov; bg = og; }
        }
        if ((bg & 31) == lane) msk |= 1u << (bg >> 5);
        sum3 += bv;
    }
    return sum3;
}

// ---------------------------------------------------------------------------
// Kernel B: fully fused sim.  Block = (j, i, anchor-chunk).
//   M = WR*16 anchors, NT = (8/WR)*32 targets (full softmax axis).
// bf16 HMMA scores -> softmax (per head) -> head-mean -> top3 -> partial sum.
// ---------------------------------------------------------------------------
template<int WR>
__global__ void __launch_bounds__(256) sim_fused(const float* __restrict__ anch,
                                                 const float* __restrict__ targ,
                                                 float* __restrict__ part)
{
    constexpr int WC  = 8 / WR;
    constexpr int M   = WR * 16;          // anchors per block
    constexpr int NT  = WC * 32;          // targets (full axis)
    constexpr int AMS = NT + 4;           // am row stride (floats)

    constexpr int OFF_B   = 0;                       // NT x 256 bf16, swizzled
    constexpr int OFF_A   = OFF_B + NT * 512;        // M x 256 bf16, swizzled
    constexpr int OFF_AM  = OFF_A + M * 512;         // M x AMS f32
    constexpr int OFF_RED = OFF_AM + M * AMS * 4;    // 4 heads x WC x M f32
    constexpr int OFF_WACC= OFF_RED + 4 * WC * M * 4;

    extern __shared__ char smem[];
    const uint32_t sbase = (uint32_t)__cvta_generic_to_shared(smem);

    const int j     = blockIdx.x;
    const int i     = blockIdx.y;
    const int chunk = blockIdx.z;
    const int tid   = threadIdx.x;
    const int w     = tid >> 5;
    const int lane  = tid & 31;

    // ---- load target k-tile (NT x 256) into swizzled bf16 smem ----
    {
        const float* tb = targ + (size_t)j * NT * 512 + 256;
        #pragma unroll
        for (int it = 0; it < NT / 4; ++it) {
            int id = tid + it * 256;
            int r  = id >> 6;
            int q  = id & 63;                    // float4 index within row
            float4 v = *(const float4*)(tb + (size_t)r * 512 + q * 4);
            uint32_t off = OFF_B + r * 512 + ((((q >> 1) ^ (r & 7)) << 4) | ((q & 1) << 3));
            *(uint2*)(smem + off) = make_uint2(pack_bf2(v.x, v.y), pack_bf2(v.z, v.w));
        }
    }
    // ---- load anchor q-tile (M x 256) ----
    {
        const float* ab = anch + (size_t)((i * 4 + chunk) * M) * 512;
        #pragma unroll
        for (int it = 0; it < M / 4; ++it) {
            int id = tid + it * 256;
            int r  = id >> 6;
            int q  = id & 63;
            float4 v = *(const float4*)(ab + (size_t)r * 512 + q * 4);
            uint32_t off = OFF_A + r * 512 + ((((q >> 1) ^ (r & 7)) << 4) | ((q & 1) << 3));
            *(uint2*)(smem + off) = make_uint2(pack_bf2(v.x, v.y), pack_bf2(v.z, v.w));
        }
    }
    __syncthreads();

    // ---- MMA: scores c[h][nt][4] for warp tile m16 x n32 ----
    const int wm = (w / WC) * 16;
    const int wn = (w % WC) * 32;
    const int l8  = lane & 7;
    const int sub = lane >> 3;

    const uint32_t a_base  = sbase + OFF_A + (uint32_t)(wm + l8 + (sub & 1) * 8) * 512;
    const int      a_coff  = sub >> 1;
    const uint32_t b_base  = sbase + OFF_B + (uint32_t)(wn + l8 + ((sub >> 1) & 1) * 8) * 512;
    const int      b_coff  = sub & 1;

    float c[4][4][4];
    #pragma unroll
    for (int h = 0; h < 4; ++h)
        #pragma unroll
        for (int nt = 0; nt < 4; ++nt)
            #pragma unroll
            for (int e = 0; e < 4; ++e) c[h][nt][e] = 0.f;

    #pragma unroll
    for (int h = 0; h < 4; ++h) {
        #pragma unroll
        for (int s = 0; s < 4; ++s) {
            const int cq = h * 8 + s * 2;   // head h spans 8 sixteen-byte chunks
            uint32_t a0, a1, a2, a3, p0, p1, p2, p3, q0, q1, q2, q3;
            ldsm_x4(a0, a1, a2, a3, a_base + (((cq + a_coff) ^ l8) << 4));
            ldsm_x4(p0, p1, p2, p3, b_base + (((cq + b_coff) ^ l8) << 4));
            ldsm_x4(q0, q1, q2, q3, b_base + 16 * 512 + (((cq + b_coff) ^ l8) << 4));
            mma_bf16(c[h][0], a0, a1, a2, a3, p0, p1);
            mma_bf16(c[h][1], a0, a1, a2, a3, p2, p3);
            mma_bf16(c[h][2], a0, a1, a2, a3, q0, q1);
            mma_bf16(c[h][3], a0, a1, a2, a3, q2, q3);
        }
    }

    // scale 1/sqrt(hd)
    #pragma unroll
    for (int h = 0; h < 4; ++h)
        #pragma unroll
        for (int nt = 0; nt < 4; ++nt)
            #pragma unroll
            for (int e = 0; e < 4; ++e) c[h][nt][e] *= 0.125f;

    const int qrow = lane >> 2;
    const int qcol = lane & 3;
    float* redf  = (float*)(smem + OFF_RED);
    float* amf   = (float*)(smem + OFF_AM);
    float* waccf = (float*)(smem + OFF_WACC);
    const int wc = w % WC;

    // ---- row max per head (over full NT) ----
    float mx[4][2];
    #pragma unroll
    for (int h = 0; h < 4; ++h) {
        float m0 = c[h][0][0], m1 = c[h][0][2];
        #pragma unroll
        for (int nt = 0; nt < 4; ++nt) {
            m0 = fmaxf(m0, fmaxf(c[h][nt][0], c[h][nt][1]));
            m1 = fmaxf(m1, fmaxf(c[h][nt][2], c[h][nt][3]));
        }
        m0 = fmaxf(m0, __shfl_xor_sync(0xffffffffu, m0, 1));
        m0 = fmaxf(m0, __shfl_xor_sync(0xffffffffu, m0, 2));
        m1 = fmaxf(m1, __shfl_xor_sync(0xffffffffu, m1, 1));
        m1 = fmaxf(m1, __shfl_xor_sync(0xffffffffu, m1, 2));
        mx[h][0] = m0; mx[h][1] = m1;
    }
    if (qcol == 0) {
        #pragma unroll
        for (int h = 0; h < 4; ++h) {
            redf[h * WC * M + wc * M + wm + qrow]     = mx[h][0];
            redf[h * WC * M + wc * M + wm + qrow + 8] = mx[h][1];
        }
    }
    __syncthreads();
    #pragma unroll
    for (int h = 0; h < 4; ++h)
        #pragma unroll
        for (int rp = 0; rp < 2; ++rp) {
            float m = -1e30f;
            #pragma unroll
            for (int x = 0; x < WC; ++x)
                m = fmaxf(m, redf[h * WC * M + x * M + wm + qrow + rp * 8]);
            mx[h][rp] = m;
        }
    __syncthreads();

    // ---- exp + Z ----
    float rr[4][2];
    #pragma unroll
    for (int h = 0; h < 4; ++h) {
        float z0 = 0.f, z1 = 0.f;
        #pragma unroll
        for (int nt = 0; nt < 4; ++nt) {
            c[h][nt][0] = __expf(c[h][nt][0] - mx[h][0]);
            c[h][nt][1] = __expf(c[h][nt][1] - mx[h][0]);
            c[h][nt][2] = __expf(c[h][nt][2] - mx[h][1]);
            c[h][nt][3] = __expf(c[h][nt][3] - mx[h][1]);
            z0 += c[h][nt][0] + c[h][nt][1];
            z1 += c[h][nt][2] + c[h][nt][3];
        }
        z0 += __shfl_xor_sync(0xffffffffu, z0, 1);
        z0 += __shfl_xor_sync(0xffffffffu, z0, 2);
        z1 += __shfl_xor_sync(0xffffffffu, z1, 1);
        z1 += __shfl_xor_sync(0xffffffffu, z1, 2);
        rr[h][0] = z0; rr[h][1] = z1;
    }
    if (qcol == 0) {
        #pragma unroll
        for (int h = 0; h < 4; ++h) {
            redf[h * WC * M + wc * M + wm + qrow]     = rr[h][0];
            redf[h * WC * M + wc * M + wm + qrow + 8] = rr[h][1];
        }
    }
    __syncthreads();
    #pragma unroll
    for (int h = 0; h < 4; ++h)
        #pragma unroll
        for (int rp = 0; rp < 2; ++rp) {
            float z = 0.f;
            #pragma unroll
            for (int x = 0; x < WC; ++x)
                z += redf[h * WC * M + x * M + wm + qrow + rp * 8];
            rr[h][rp] = 0.25f / z;   // includes head-mean
        }

    // ---- am = head-mean of softmax; stash to smem ----
    #pragma unroll
    for (int nt = 0; nt < 4; ++nt) {
        float a0 = 0.f, a1 = 0.f, a2 = 0.f, a3 = 0.f;
        #pragma unroll
        for (int h = 0; h < 4; ++h) {
            a0 += c[h][nt][0] * rr[h][0];
            a1 += c[h][nt][1] * rr[h][0];
            a2 += c[h][nt][2] * rr[h][1];
            a3 += c[h][nt][3] * rr[h][1];
        }
        const int colb = wn + nt * 8 + qcol * 2;
        *(float2*)&amf[(wm + qrow)     * AMS + colb] = make_float2(a0, a1);
        *(float2*)&amf[(wm + qrow + 8) * AMS + colb] = make_float2(a2, a3);
    }
    __syncthreads();

    // ---- top-3 per anchor row, accumulate ----
    constexpr int RPW = M / 8;
    constexpr int NB  = NT / 32;
    float acc = 0.f;
    #pragma unroll
    for (int r2 = 0; r2 < RPW; ++r2) {
        const int row = w * RPW + r2;
        acc += top3_sum<NB>(&amf[row * AMS], lane);
    }
    if (lane == 0) waccf[w] = acc;
    __syncthreads();
    if (tid == 0) {
        float tot = 0.f;
        #pragma unroll
        for (int x = 0; x < 8; ++x) tot += waccf[x];
        part[((i * 32 + j) << 2) + chunk] = tot;
    }
}

// ---------------------------------------------------------------------------
// Kernel C: contrastive loss (folds the 4 partials per (i,j))
// ---------------------------------------------------------------------------
__global__ void loss_kernel(const float* __restrict__ part, float* __restrict__ out)
{
    __shared__ float red[64];
    const int t   = threadIdx.x;
    const int dir = t >> 5;
    const int row = t & 31;
    const float* P = part + dir * 4096;
    const float scale = dir ? (100.f / (3.f * 64.f)) : (100.f / (3.f * 256.f));

    float pos = 0.f;
    float t1 = -1e30f, t2 = -1e30f, t3 = -1e30f;
    for (int j = 0; j < 32; ++j) {
        float4 p4 = *(const float4*)&P[(row * 32 + j) << 2];
        float v = (p4.x + p4.y + p4.z + p4.w) * scale;
        if (j == row) { pos = v; continue; }
        if      (v > t1) { t3 = t2; t2 = t1; t1 = v; }
        else if (v > t2) { t3 = t2; t2 = v; }
        else if (v > t3) { t3 = v; }
    }
    const float invT = 1.0f / 0.07f;
    float l0 = pos * invT, l1 = t1 * invT, l2 = t2 * invT, l3 = t3 * invT;
    float m  = fmaxf(fmaxf(l0, l1), fmaxf(l2, l3));
    float Z  = expf(l0 - m) + expf(l1 - m) + expf(l2 - m) + expf(l3 - m);
    red[t] = -(l0 - m - logf(Z));
    __syncthreads();
    if (t == 0) {
        float s0 = 0.f, s1 = 0.f;
        for (int r = 0; r < 32; ++r) { s0 += red[r]; s1 += red[32 + r]; }
        out[0] = 0.5f * (s0 / 32.f) + 0.5f * (s1 / 32.f);
    }
}

// ---------------------------------------------------------------------------
// Launch
// ---------------------------------------------------------------------------
extern "C" void kernel_launch(void* const* d_in, const int* in_sizes, int n_in,
                              void* d_out, int out_size)
{
    const float* lang = (const float*)d_in[0];
    const float* vis  = (const float*)d_in[1];
    const float* W    = (const float*)d_in[2];
    const float* bias = (const float*)d_in[3];

    // smem: B + A + am + red + wacc
    const int SM_V2T = 64*512 + 64*512 + 64*(64+4)*4  + 4*2*64*4 + 32;  //  85,024
    const int SM_T2V = 256*512 + 16*512 + 16*(256+4)*4 + 4*8*16*4 + 32; // 157,984

    static float *p_lang = nullptr, *p_vis = nullptr, *p_part = nullptr;
    if (!p_lang) {
        cudaGetSymbolAddress((void**)&p_lang, g_proj_lang);
        cudaGetSymbolAddress((void**)&p_vis,  g_proj_vis);
        cudaGetSymbolAddress((void**)&p_part, g_part);
        cudaFuncSetAttribute(sim_fused<4>,
                             cudaFuncAttributeMaxDynamicSharedMemorySize, SM_V2T);
        cudaFuncSetAttribute(sim_fused<1>,
                             cudaFuncAttributeMaxDynamicSharedMemorySize, SM_T2V);
    }

    proj_kernel<<<dim3(8, 32),  256>>>(lang, W, bias, 0);
    proj_kernel<<<dim3(8, 128), 256>>>(vis,  W, bias, 1);

    // v2t: anchors = vis (M=64/blk, 4 chunks), targets = lang (NT=64)
    sim_fused<4><<<dim3(32, 32, 4), 256, SM_V2T>>>(p_vis, p_lang, p_part);
    // t2v: anchors = lang (M=16/blk, 4 chunks), targets = vis (NT=256)
    sim_fused<1><<<dim3(32, 32, 4), 256, SM_T2V>>>(p_lang, p_vis, p_part + 4096);

    loss_kernel<<<1, 64>>>(p_part, (float*)d_out);
}

// round 6
// speedup vs baseline: 3.0379x; 1.1323x over previous
#include <cuda_runtime.h>
#include <cuda_bf16.h>
#include <math.h>
#include <stdint.h>

// ---------------------------------------------------------------------------
// Scratch (device globals; no allocation allowed)
// q/k stored as bf16 in ldsm-swizzled layout: row stride 512B,
// byte_off(row, col) = row*512 + (((col>>3) ^ (row&7))<<4) + (col&7)*2
// ---------------------------------------------------------------------------
__device__ __align__(16) char g_q_lang[2048 * 512];
__device__ __align__(16) char g_k_lang[2048 * 512];
__device__ __align__(16) char g_q_vis [8192 * 512];
__device__ __align__(16) char g_k_vis [8192 * 512];
__device__ float g_part[2 * 32 * 32 * 4];   // [dir][i][j][chunk]

// ---------------------------------------------------------------------------
// bf16 / async helpers
// ---------------------------------------------------------------------------
__device__ __forceinline__ uint32_t pack_bf2(float a, float b) {
    __nv_bfloat162 t = __floats2bfloat162_rn(a, b);
    return *(uint32_t*)&t;
}
__device__ __forceinline__ void cpasync16(uint32_t s, const void* g) {
    asm volatile("cp.async.cg.shared.global [%0], [%1], 16;\n" :: "r"(s), "l"(g));
}
__device__ __forceinline__ void cpasync_commit() {
    asm volatile("cp.async.commit_group;\n");
}
__device__ __forceinline__ void cpasync_wait_all() {
    asm volatile("cp.async.wait_group 0;\n");
}
__device__ __forceinline__ void ldsm_x4(uint32_t& r0, uint32_t& r1,
                                        uint32_t& r2, uint32_t& r3, uint32_t addr) {
    asm volatile("ldmatrix.sync.aligned.m8n8.x4.shared.b16 {%0,%1,%2,%3}, [%4];"
                 : "=r"(r0), "=r"(r1), "=r"(r2), "=r"(r3) : "r"(addr));
}
__device__ __forceinline__ void mma_bf16(float c[4],
                                         uint32_t a0, uint32_t a1, uint32_t a2, uint32_t a3,
                                         uint32_t b0, uint32_t b1) {
    asm volatile(
        "mma.sync.aligned.m16n8k16.row.col.f32.bf16.bf16.f32 "
        "{%0,%1,%2,%3}, {%4,%5,%6,%7}, {%8,%9}, {%0,%1,%2,%3};\n"
        : "+f"(c[0]), "+f"(c[1]), "+f"(c[2]), "+f"(c[3])
        : "r"(a0), "r"(a1), "r"(a2), "r"(a3), "r"(b0), "r"(b1));
}

// ---------------------------------------------------------------------------
// Kernel A: projection GEMM -> bf16 swizzled q/k arrays
// ---------------------------------------------------------------------------
__global__ void __launch_bounds__(256) proj_kernel(const float* __restrict__ X,
                                                   const float* __restrict__ W,
                                                   const float* __restrict__ bias,
                                                   int which)
{
    __shared__ float As[32][68];
    __shared__ float Bs[32][68];

    const int bm = blockIdx.y * 64;
    const int bn = blockIdx.x * 64;
    const int tid  = threadIdx.x;
    const int trow = tid >> 4;
    const int tcol = tid & 15;

    float cc[4][4] = {};

    for (int k0 = 0; k0 < 256; k0 += 32) {
        #pragma unroll
        for (int it = 0; it < 2; ++it) {
            int id = tid + it * 256;
            int r  = id >> 3;
            int qc = id & 7;
            float4 va = *(const float4*)(X + (size_t)(bm + r) * 256 + k0 + qc * 4);
            As[qc*4+0][r] = va.x; As[qc*4+1][r] = va.y;
            As[qc*4+2][r] = va.z; As[qc*4+3][r] = va.w;
            float4 vb = *(const float4*)(W + (size_t)(bn + r) * 256 + k0 + qc * 4);
            Bs[qc*4+0][r] = vb.x; Bs[qc*4+1][r] = vb.y;
            Bs[qc*4+2][r] = vb.z; Bs[qc*4+3][r] = vb.w;
        }
        __syncthreads();
        #pragma unroll
        for (int k = 0; k < 32; ++k) {
            float4 a = *(const float4*)&As[k][trow * 4];
            float4 b = *(const float4*)&Bs[k][tcol * 4];
            cc[0][0] += a.x*b.x; cc[0][1] += a.x*b.y; cc[0][2] += a.x*b.z; cc[0][3] += a.x*b.w;
            cc[1][0] += a.y*b.x; cc[1][1] += a.y*b.y; cc[1][2] += a.y*b.z; cc[1][3] += a.y*b.w;
            cc[2][0] += a.z*b.x; cc[2][1] += a.z*b.y; cc[2][2] += a.z*b.z; cc[2][3] += a.z*b.w;
            cc[3][0] += a.w*b.x; cc[3][1] += a.w*b.y; cc[3][2] += a.w*b.z; cc[3][3] += a.w*b.w;
        }
        __syncthreads();
    }

    const int n0   = bn + tcol * 4;
    const bool isq = (n0 < 256);
    const int cl   = n0 & 255;
    char* arr = which ? (isq ? g_q_vis : g_k_vis) : (isq ? g_q_lang : g_k_lang);
    const float b0 = bias[n0], b1 = bias[n0+1], b2 = bias[n0+2], b3 = bias[n0+3];

    #pragma unroll
    for (int x = 0; x < 4; ++x) {
        int m = bm + trow * 4 + x;
        uint32_t lo = pack_bf2(cc[x][0] + b0, cc[x][1] + b1);
        uint32_t hi = pack_bf2(cc[x][2] + b2, cc[x][3] + b3);
        uint32_t off = (uint32_t)m * 512 + ((((cl >> 3) ^ (m & 7)) << 4) | ((cl & 7) << 1));
        *(uint2*)(arr + off) = make_uint2(lo, hi);
    }
}

// ---------------------------------------------------------------------------
// top3 helper
// ---------------------------------------------------------------------------
template<int NB>
__device__ __forceinline__ float top3_sum(const float* v, int lane) {
    float am[NB];
    #pragma unroll
    for (int bi = 0; bi < NB; ++bi) am[bi] = v[bi * 32 + lane];
    unsigned msk = 0; float sum3 = 0.f;
    #pragma unroll
    for (int rr = 0; rr < 3; ++rr) {
        float bv = -1e30f; int bg = lane;
        #pragma unroll
        for (int bi = 0; bi < NB; ++bi)
            if (!((msk >> bi) & 1u) && am[bi] > bv) { bv = am[bi]; bg = (bi << 5) | lane; }
        #pragma unroll
        for (int off = 16; off; off >>= 1) {
            float ov = __shfl_xor_sync(0xffffffffu, bv, off);
            int   og = __shfl_xor_sync(0xffffffffu, bg, off);
            if (ov > bv || (ov == bv && og > bg)) { bv = ov; bg = og; }
        }
        if ((bg & 31) == lane) msk |= 1u << (bg >> 5);
        sum3 += bv;
    }
    return sum3;
}

// ---------------------------------------------------------------------------
// Kernel B: fused sim, persistent over anchor chunks.
//   Block (j, z): load B tile (target k, NT rows of batch j) ONCE,
//   loop NITER anchor chunks cidx = z*NITER+it (M rows each).
// ---------------------------------------------------------------------------
template<int WR, int NITER>
__global__ void __launch_bounds__(256) sim_fused(const char* __restrict__ anch_q,
                                                 const char* __restrict__ targ_k,
                                                 float* __restrict__ part)
{
    constexpr int WC  = 8 / WR;
    constexpr int M   = WR * 16;          // anchors per chunk
    constexpr int NT  = WC * 32;          // targets (full softmax axis)
    constexpr int AMS = NT + 4;

    constexpr int OFF_B    = 0;                      // NT x 512B (swizzled bf16)
    constexpr int OFF_A    = OFF_B + NT * 512;       // M x 512B
    constexpr int OFF_AM   = OFF_A + M * 512;        // M x AMS f32
    constexpr int OFF_RED  = OFF_AM + M * AMS * 4;   // 4 x WC x M f32
    constexpr int OFF_WACC = OFF_RED + 4 * WC * M * 4;

    extern __shared__ char smem[];
    const uint32_t sbase = (uint32_t)__cvta_generic_to_shared(smem);

    const int j    = blockIdx.x;
    const int z    = blockIdx.y;
    const int tid  = threadIdx.x;
    const int w    = tid >> 5;
    const int lane = tid & 31;

    // ---- B tile: straight byte copy (already bf16 + swizzled) ----
    {
        const char* src = targ_k + (size_t)j * NT * 512;
        #pragma unroll
        for (int id = tid; id < NT * 32; id += 256)
            cpasync16(sbase + OFF_B + id * 16, src + id * 16);
        cpasync_commit();
    }

    const int wm = (w / WC) * 16;
    const int wn = (w % WC) * 32;
    const int wc = w % WC;
    const int l8  = lane & 7;
    const int sub = lane >> 3;
    const int qrow = lane >> 2;
    const int qcol = lane & 3;

    const uint32_t a_base = sbase + OFF_A + (uint32_t)(wm + l8 + (sub & 1) * 8) * 512;
    const int      a_coff = sub >> 1;
    const uint32_t b_base = sbase + OFF_B + (uint32_t)(wn + l8 + ((sub >> 1) & 1) * 8) * 512;
    const int      b_coff = sub & 1;

    float* redf  = (float*)(smem + OFF_RED);
    float* amf   = (float*)(smem + OFF_AM);
    float* waccf = (float*)(smem + OFF_WACC);

    for (int it = 0; it < NITER; ++it) {
        const int cidx = z * NITER + it;

        __syncthreads();   // previous iter fully done before A overwrite
        {
            const char* src = anch_q + (size_t)cidx * M * 512;
            #pragma unroll
            for (int id = tid; id < M * 32; id += 256)
                cpasync16(sbase + OFF_A + id * 16, src + id * 16);
            cpasync_commit();
            cpasync_wait_all();   // waits B too on first iter
        }
        __syncthreads();

        // ---- MMA: scores c[h][nt][4], warp tile m16 x n32 ----
        float c[4][4][4];
        #pragma unroll
        for (int h = 0; h < 4; ++h)
            #pragma unroll
            for (int nt = 0; nt < 4; ++nt)
                #pragma unroll
                for (int e = 0; e < 4; ++e) c[h][nt][e] = 0.f;

        #pragma unroll
        for (int h = 0; h < 4; ++h) {
            #pragma unroll
            for (int s = 0; s < 4; ++s) {
                const int cq = h * 8 + s * 2;
                uint32_t a0, a1, a2, a3, p0, p1, p2, p3, q0, q1, q2, q3;
                ldsm_x4(a0, a1, a2, a3, a_base + (((cq + a_coff) ^ l8) << 4));
                ldsm_x4(p0, p1, p2, p3, b_base + (((cq + b_coff) ^ l8) << 4));
                ldsm_x4(q0, q1, q2, q3, b_base + 16 * 512 + (((cq + b_coff) ^ l8) << 4));
                mma_bf16(c[h][0], a0, a1, a2, a3, p0, p1);
                mma_bf16(c[h][1], a0, a1, a2, a3, p2, p3);
                mma_bf16(c[h][2], a0, a1, a2, a3, q0, q1);
                mma_bf16(c[h][3], a0, a1, a2, a3, q2, q3);
            }
        }

        #pragma unroll
        for (int h = 0; h < 4; ++h)
            #pragma unroll
            for (int nt = 0; nt < 4; ++nt)
                #pragma unroll
                for (int e = 0; e < 4; ++e) c[h][nt][e] *= 0.125f;

        // ---- row max per head ----
        float mx[4][2];
        #pragma unroll
        for (int h = 0; h < 4; ++h) {
            float m0 = c[h][0][0], m1 = c[h][0][2];
            #pragma unroll
            for (int nt = 0; nt < 4; ++nt) {
                m0 = fmaxf(m0, fmaxf(c[h][nt][0], c[h][nt][1]));
                m1 = fmaxf(m1, fmaxf(c[h][nt][2], c[h][nt][3]));
            }
            m0 = fmaxf(m0, __shfl_xor_sync(0xffffffffu, m0, 1));
            m0 = fmaxf(m0, __shfl_xor_sync(0xffffffffu, m0, 2));
            m1 = fmaxf(m1, __shfl_xor_sync(0xffffffffu, m1, 1));
            m1 = fmaxf(m1, __shfl_xor_sync(0xffffffffu, m1, 2));
            mx[h][0] = m0; mx[h][1] = m1;
        }
        if (qcol == 0) {
            #pragma unroll
            for (int h = 0; h < 4; ++h) {
                redf[h * WC * M + wc * M + wm + qrow]     = mx[h][0];
                redf[h * WC * M + wc * M + wm + qrow + 8] = mx[h][1];
            }
        }
        __syncthreads();
        #pragma unroll
        for (int h = 0; h < 4; ++h)
            #pragma unroll
            for (int rp = 0; rp < 2; ++rp) {
                float m = -1e30f;
                #pragma unroll
                for (int x = 0; x < WC; ++x)
                    m = fmaxf(m, redf[h * WC * M + x * M + wm + qrow + rp * 8]);
                mx[h][rp] = m;
            }
        __syncthreads();

        // ---- exp + Z ----
        float rr[4][2];
        #pragma unroll
        for (int h = 0; h < 4; ++h) {
            float z0 = 0.f, z1 = 0.f;
            #pragma unroll
            for (int nt = 0; nt < 4; ++nt) {
                c[h][nt][0] = __expf(c[h][nt][0] - mx[h][0]);
                c[h][nt][1] = __expf(c[h][nt][1] - mx[h][0]);
                c[h][nt][2] = __expf(c[h][nt][2] - mx[h][1]);
                c[h][nt][3] = __expf(c[h][nt][3] - mx[h][1]);
                z0 += c[h][nt][0] + c[h][nt][1];
                z1 += c[h][nt][2] + c[h][nt][3];
            }
            z0 += __shfl_xor_sync(0xffffffffu, z0, 1);
            z0 += __shfl_xor_sync(0xffffffffu, z0, 2);
            z1 += __shfl_xor_sync(0xffffffffu, z1, 1);
            z1 += __shfl_xor_sync(0xffffffffu, z1, 2);
            rr[h][0] = z0; rr[h][1] = z1;
        }
        if (qcol == 0) {
            #pragma unroll
            for (int h = 0; h < 4; ++h) {
                redf[h * WC * M + wc * M + wm + qrow]     = rr[h][0];
                redf[h * WC * M + wc * M + wm + qrow + 8] = rr[h][1];
            }
        }
        __syncthreads();
        #pragma unroll
        for (int h = 0; h < 4; ++h)
            #pragma unroll
            for (int rp = 0; rp < 2; ++rp) {
                float zz = 0.f;
                #pragma unroll
                for (int x = 0; x < WC; ++x)
                    zz += redf[h * WC * M + x * M + wm + qrow + rp * 8];
                rr[h][rp] = 0.25f / zz;   // includes head-mean
            }

        // ---- am = head-mean of softmax ----
        #pragma unroll
        for (int nt = 0; nt < 4; ++nt) {
            float a0 = 0.f, a1 = 0.f, a2 = 0.f, a3 = 0.f;
            #pragma unroll
            for (int h = 0; h < 4; ++h) {
                a0 += c[h][nt][0] * rr[h][0];
                a1 += c[h][nt][1] * rr[h][0];
                a2 += c[h][nt][2] * rr[h][1];
                a3 += c[h][nt][3] * rr[h][1];
            }
            const int colb = wn + nt * 8 + qcol * 2;
            *(float2*)&amf[(wm + qrow)     * AMS + colb] = make_float2(a0, a1);
            *(float2*)&amf[(wm + qrow + 8) * AMS + colb] = make_float2(a2, a3);
        }
        __syncthreads();

        // ---- top-3 per anchor row ----
        constexpr int RPW = M / 8;
        constexpr int NB  = NT / 32;
        float acc = 0.f;
        #pragma unroll
        for (int r2 = 0; r2 < RPW; ++r2)
            acc += top3_sum<NB>(&amf[(w * RPW + r2) * AMS], lane);
        if (lane == 0) waccf[w] = acc;
        __syncthreads();
        if (tid == 0) {
            float tot = 0.f;
            #pragma unroll
            for (int x = 0; x < 8; ++x) tot += waccf[x];
            const int i = cidx >> 2, chunk = cidx & 3;
            part[((i * 32 + j) << 2) + chunk] = tot;
        }
    }
}

// ---------------------------------------------------------------------------
// Kernel C: contrastive loss
// ---------------------------------------------------------------------------
__global__ void loss_kernel(const float* __restrict__ part, float* __restrict__ out)
{
    __shared__ float red[64];
    const int t   = threadIdx.x;
    const int dir = t >> 5;
    const int row = t & 31;
    const float* P = part + dir * 4096;
    const float scale = dir ? (100.f / (3.f * 64.f)) : (100.f / (3.f * 256.f));

    float pos = 0.f;
    float t1 = -1e30f, t2 = -1e30f, t3 = -1e30f;
    for (int j = 0; j < 32; ++j) {
        float4 p4 = *(const float4*)&P[(row * 32 + j) << 2];
        float v = (p4.x + p4.y + p4.z + p4.w) * scale;
        if (j == row) { pos = v; continue; }
        if      (v > t1) { t3 = t2; t2 = t1; t1 = v; }
        else if (v > t2) { t3 = t2; t2 = v; }
        else if (v > t3) { t3 = v; }
    }
    const float invT = 1.0f / 0.07f;
    float l0 = pos * invT, l1 = t1 * invT, l2 = t2 * invT, l3 = t3 * invT;
    float m  = fmaxf(fmaxf(l0, l1), fmaxf(l2, l3));
    float Z  = expf(l0 - m) + expf(l1 - m) + expf(l2 - m) + expf(l3 - m);
    red[t] = -(l0 - m - logf(Z));
    __syncthreads();
    if (t == 0) {
        float s0 = 0.f, s1 = 0.f;
        for (int r = 0; r < 32; ++r) { s0 += red[r]; s1 += red[32 + r]; }
        out[0] = 0.5f * (s0 / 32.f) + 0.5f * (s1 / 32.f);
    }
}

// ---------------------------------------------------------------------------
// Launch
// ---------------------------------------------------------------------------
extern "C" void kernel_launch(void* const* d_in, const int* in_sizes, int n_in,
                              void* d_out, int out_size)
{
    const float* lang = (const float*)d_in[0];
    const float* vis  = (const float*)d_in[1];
    const float* W    = (const float*)d_in[2];
    const float* bias = (const float*)d_in[3];

    const int SM_V2T = 64*512 + 64*512 + 64*(64+4)*4  + 4*2*64*4 + 32;  //  85,024
    const int SM_T2V = 256*512 + 16*512 + 16*(256+4)*4 + 4*8*16*4 + 32; // 157,984

    static char *p_ql = nullptr, *p_kl = nullptr, *p_qv = nullptr, *p_kv = nullptr;
    static float *p_part = nullptr;
    if (!p_ql) {
        cudaGetSymbolAddress((void**)&p_ql, g_q_lang);
        cudaGetSymbolAddress((void**)&p_kl, g_k_lang);
        cudaGetSymbolAddress((void**)&p_qv, g_q_vis);
        cudaGetSymbolAddress((void**)&p_kv, g_k_vis);
        cudaGetSymbolAddress((void**)&p_part, g_part);
        cudaFuncSetAttribute(sim_fused<4, 8>,
                             cudaFuncAttributeMaxDynamicSharedMemorySize, SM_V2T);
        cudaFuncSetAttribute(sim_fused<1, 16>,
                             cudaFuncAttributeMaxDynamicSharedMemorySize, SM_T2V);
    }

    proj_kernel<<<dim3(8, 32),  256>>>(lang, W, bias, 0);
    proj_kernel<<<dim3(8, 128), 256>>>(vis,  W, bias, 1);

    // v2t: anchors = vis q (128 chunks of 64), targets = lang k (NT=64)
    sim_fused<4, 8><<<dim3(32, 16), 256, SM_V2T>>>(p_qv, p_kl, p_part);
    // t2v: anchors = lang q (128 chunks of 16), targets = vis k (NT=256)
    sim_fused<1, 16><<<dim3(32, 8), 256, SM_T2V>>>(p_ql, p_kv, p_part + 4096);

    loss_kernel<<<1, 64>>>(p_part, (float*)d_out);
}

// round 7
// speedup vs baseline: 3.4696x; 1.1421x over previous
#include <cuda_runtime.h>
#include <cuda_bf16.h>
#include <math.h>
#include <stdint.h>

// ---------------------------------------------------------------------------
// Scratch (device globals; no allocation allowed)
// q/k stored as bf16 in ldsm-swizzled layout: row stride 512B,
// byte_off(row, col) = row*512 + (((col>>3) ^ (row&7))<<4) + (col&7)*2
// ---------------------------------------------------------------------------
__device__ __align__(16) char g_q_lang[2048 * 512];
__device__ __align__(16) char g_k_lang[2048 * 512];
__device__ __align__(16) char g_q_vis [8192 * 512];
__device__ __align__(16) char g_k_vis [8192 * 512];
__device__ float g_part[2 * 32 * 32 * 4];   // [dir][i][j][chunk]

// ---------------------------------------------------------------------------
// bf16 / async helpers
// ---------------------------------------------------------------------------
__device__ __forceinline__ uint32_t pack_bf2(float a, float b) {
    __nv_bfloat162 t = __floats2bfloat162_rn(a, b);
    return *(uint32_t*)&t;
}
__device__ __forceinline__ void cpasync16(uint32_t s, const void* g) {
    asm volatile("cp.async.cg.shared.global [%0], [%1], 16;\n" :: "r"(s), "l"(g));
}
__device__ __forceinline__ void cpasync_commit() {
    asm volatile("cp.async.commit_group;\n");
}
__device__ __forceinline__ void cpasync_wait_all() {
    asm volatile("cp.async.wait_group 0;\n");
}
__device__ __forceinline__ void ldsm_x4(uint32_t& r0, uint32_t& r1,
                                        uint32_t& r2, uint32_t& r3, uint32_t addr) {
    asm volatile("ldmatrix.sync.aligned.m8n8.x4.shared.b16 {%0,%1,%2,%3}, [%4];"
                 : "=r"(r0), "=r"(r1), "=r"(r2), "=r"(r3) : "r"(addr));
}
__device__ __forceinline__ void mma_bf16(float c[4],
                                         uint32_t a0, uint32_t a1, uint32_t a2, uint32_t a3,
                                         uint32_t b0, uint32_t b1) {
    asm volatile(
        "mma.sync.aligned.m16n8k16.row.col.f32.bf16.bf16.f32 "
        "{%0,%1,%2,%3}, {%4,%5,%6,%7}, {%8,%9}, {%0,%1,%2,%3};\n"
        : "+f"(c[0]), "+f"(c[1]), "+f"(c[2]), "+f"(c[3])
        : "r"(a0), "r"(a1), "r"(a2), "r"(a3), "r"(b0), "r"(b1));
}

// ---------------------------------------------------------------------------
// Kernel A: projection GEMM -> bf16 swizzled q/k arrays
// ---------------------------------------------------------------------------
__global__ void __launch_bounds__(256) proj_kernel(const float* __restrict__ X,
                                                   const float* __restrict__ W,
                                                   const float* __restrict__ bias,
                                                   int which)
{
    __shared__ float As[32][68];
    __shared__ float Bs[32][68];

    const int bm = blockIdx.y * 64;
    const int bn = blockIdx.x * 64;
    const int tid  = threadIdx.x;
    const int trow = tid >> 4;
    const int tcol = tid & 15;

    float cc[4][4] = {};

    for (int k0 = 0; k0 < 256; k0 += 32) {
        #pragma unroll
        for (int it = 0; it < 2; ++it) {
            int id = tid + it * 256;
            int r  = id >> 3;
            int qc = id & 7;
            float4 va = *(const float4*)(X + (size_t)(bm + r) * 256 + k0 + qc * 4);
            As[qc*4+0][r] = va.x; As[qc*4+1][r] = va.y;
            As[qc*4+2][r] = va.z; As[qc*4+3][r] = va.w;
            float4 vb = *(const float4*)(W + (size_t)(bn + r) * 256 + k0 + qc * 4);
            Bs[qc*4+0][r] = vb.x; Bs[qc*4+1][r] = vb.y;
            Bs[qc*4+2][r] = vb.z; Bs[qc*4+3][r] = vb.w;
        }
        __syncthreads();
        #pragma unroll
        for (int k = 0; k < 32; ++k) {
            float4 a = *(const float4*)&As[k][trow * 4];
            float4 b = *(const float4*)&Bs[k][tcol * 4];
            cc[0][0] += a.x*b.x; cc[0][1] += a.x*b.y; cc[0][2] += a.x*b.z; cc[0][3] += a.x*b.w;
            cc[1][0] += a.y*b.x; cc[1][1] += a.y*b.y; cc[1][2] += a.y*b.z; cc[1][3] += a.y*b.w;
            cc[2][0] += a.z*b.x; cc[2][1] += a.z*b.y; cc[2][2] += a.z*b.z; cc[2][3] += a.z*b.w;
            cc[3][0] += a.w*b.x; cc[3][1] += a.w*b.y; cc[3][2] += a.w*b.z; cc[3][3] += a.w*b.w;
        }
        __syncthreads();
    }

    const int n0   = bn + tcol * 4;
    const bool isq = (n0 < 256);
    const int cl   = n0 & 255;
    char* arr = which ? (isq ? g_q_vis : g_k_vis) : (isq ? g_q_lang : g_k_lang);
    const float b0 = bias[n0], b1 = bias[n0+1], b2 = bias[n0+2], b3 = bias[n0+3];

    #pragma unroll
    for (int x = 0; x < 4; ++x) {
        int m = bm + trow * 4 + x;
        uint32_t lo = pack_bf2(cc[x][0] + b0, cc[x][1] + b1);
        uint32_t hi = pack_bf2(cc[x][2] + b2, cc[x][3] + b3);
        uint32_t off = (uint32_t)m * 512 + ((((cl >> 3) ^ (m & 7)) << 4) | ((cl & 7) << 1));
        *(uint2*)(arr + off) = make_uint2(lo, hi);
    }
}

// ---------------------------------------------------------------------------
// top3 helper
// ---------------------------------------------------------------------------
template<int NB>
__device__ __forceinline__ float top3_sum(const float* v, int lane) {
    float am[NB];
    #pragma unroll
    for (int bi = 0; bi < NB; ++bi) am[bi] = v[bi * 32 + lane];
    unsigned msk = 0; float sum3 = 0.f;
    #pragma unroll
    for (int rr = 0; rr < 3; ++rr) {
        float bv = -1e30f; int bg = lane;
        #pragma unroll
        for (int bi = 0; bi < NB; ++bi)
            if (!((msk >> bi) & 1u) && am[bi] > bv) { bv = am[bi]; bg = (bi << 5) | lane; }
        #pragma unroll
        for (int off = 16; off; off >>= 1) {
            float ov = __shfl_xor_sync(0xffffffffu, bv, off);
            int   og = __shfl_xor_sync(0xffffffffu, bg, off);
            if (ov > bv || (ov == bv && og > bg)) { bv = ov; bg = og; }
        }
        if ((bg & 31) == lane) msk |= 1u << (bg >> 5);
        sum3 += bv;
    }
    return sum3;
}

// ---------------------------------------------------------------------------
// Kernel B: fused sim, persistent over anchor chunks.
// No-max softmax (scores bounded for this workload): e = exp(0.125*s).
// ---------------------------------------------------------------------------
template<int WR, int NITER, int MINB>
__global__ void __launch_bounds__(256, MINB) sim_fused(const char* __restrict__ anch_q,
                                                       const char* __restrict__ targ_k,
                                                       float* __restrict__ part)
{
    constexpr int WC  = 8 / WR;
    constexpr int M   = WR * 16;          // anchors per chunk
    constexpr int NT  = WC * 32;          // targets (full softmax axis)
    constexpr int AMS = NT + 4;

    constexpr int OFF_B    = 0;                      // NT x 512B (swizzled bf16)
    constexpr int OFF_A    = OFF_B + NT * 512;       // M x 512B
    constexpr int OFF_AM   = OFF_A + M * 512;        // M x AMS f32
    constexpr int OFF_RED  = OFF_AM + M * AMS * 4;   // 4 x WC x M f32
    constexpr int OFF_WACC = OFF_RED + 4 * WC * M * 4;

    extern __shared__ char smem[];
    const uint32_t sbase = (uint32_t)__cvta_generic_to_shared(smem);

    const int j    = blockIdx.x;
    const int z    = blockIdx.y;
    const int tid  = threadIdx.x;
    const int w    = tid >> 5;
    const int lane = tid & 31;

    // ---- B tile: straight byte copy (already bf16 + swizzled) ----
    {
        const char* src = targ_k + (size_t)j * NT * 512;
        #pragma unroll
        for (int id = tid; id < NT * 32; id += 256)
            cpasync16(sbase + OFF_B + id * 16, src + id * 16);
        cpasync_commit();
    }

    const int wm = (w / WC) * 16;
    const int wn = (w % WC) * 32;
    const int wc = w % WC;
    const int l8  = lane & 7;
    const int sub = lane >> 3;
    const int qrow = lane >> 2;
    const int qcol = lane & 3;

    const uint32_t a_base = sbase + OFF_A + (uint32_t)(wm + l8 + (sub & 1) * 8) * 512;
    const int      a_coff = sub >> 1;
    const uint32_t b_base = sbase + OFF_B + (uint32_t)(wn + l8 + ((sub >> 1) & 1) * 8) * 512;
    const int      b_coff = sub & 1;

    float* redf  = (float*)(smem + OFF_RED);
    float* amf   = (float*)(smem + OFF_AM);
    float* waccf = (float*)(smem + OFF_WACC);

    for (int it = 0; it < NITER; ++it) {
        const int cidx = z * NITER + it;

        __syncthreads();   // previous iter fully done before A overwrite
        {
            const char* src = anch_q + (size_t)cidx * M * 512;
            #pragma unroll
            for (int id = tid; id < M * 32; id += 256)
                cpasync16(sbase + OFF_A + id * 16, src + id * 16);
            cpasync_commit();
            cpasync_wait_all();   // waits B too on first iter
        }
        __syncthreads();

        // ---- MMA: scores c[h][nt][4], warp tile m16 x n32 ----
        float c[4][4][4];
        #pragma unroll
        for (int h = 0; h < 4; ++h)
            #pragma unroll
            for (int nt = 0; nt < 4; ++nt)
                #pragma unroll
                for (int e = 0; e < 4; ++e) c[h][nt][e] = 0.f;

        #pragma unroll
        for (int h = 0; h < 4; ++h) {
            #pragma unroll
            for (int s = 0; s < 4; ++s) {
                const int cq = h * 8 + s * 2;
                uint32_t a0, a1, a2, a3, p0, p1, p2, p3, q0, q1, q2, q3;
                ldsm_x4(a0, a1, a2, a3, a_base + (((cq + a_coff) ^ l8) << 4));
                ldsm_x4(p0, p1, p2, p3, b_base + (((cq + b_coff) ^ l8) << 4));
                ldsm_x4(q0, q1, q2, q3, b_base + 16 * 512 + (((cq + b_coff) ^ l8) << 4));
                mma_bf16(c[h][0], a0, a1, a2, a3, p0, p1);
                mma_bf16(c[h][1], a0, a1, a2, a3, p2, p3);
                mma_bf16(c[h][2], a0, a1, a2, a3, q0, q1);
                mma_bf16(c[h][3], a0, a1, a2, a3, q2, q3);
            }
        }

        // ---- exp (scale folded) + Z; no max subtraction ----
        float rr[4][2];
        #pragma unroll
        for (int h = 0; h < 4; ++h) {
            float z0 = 0.f, z1 = 0.f;
            #pragma unroll
            for (int nt = 0; nt < 4; ++nt) {
                c[h][nt][0] = __expf(c[h][nt][0] * 0.125f);
                c[h][nt][1] = __expf(c[h][nt][1] * 0.125f);
                c[h][nt][2] = __expf(c[h][nt][2] * 0.125f);
                c[h][nt][3] = __expf(c[h][nt][3] * 0.125f);
                z0 += c[h][nt][0] + c[h][nt][1];
                z1 += c[h][nt][2] + c[h][nt][3];
            }
            z0 += __shfl_xor_sync(0xffffffffu, z0, 1);
            z0 += __shfl_xor_sync(0xffffffffu, z0, 2);
            z1 += __shfl_xor_sync(0xffffffffu, z1, 1);
            z1 += __shfl_xor_sync(0xffffffffu, z1, 2);
            rr[h][0] = z0; rr[h][1] = z1;
        }
        if (qcol == 0) {
            #pragma unroll
            for (int h = 0; h < 4; ++h) {
                redf[h * WC * M + wc * M + wm + qrow]     = rr[h][0];
                redf[h * WC * M + wc * M + wm + qrow + 8] = rr[h][1];
            }
        }
        __syncthreads();
        #pragma unroll
        for (int h = 0; h < 4; ++h)
            #pragma unroll
            for (int rp = 0; rp < 2; ++rp) {
                float zz = 0.f;
                #pragma unroll
                for (int x = 0; x < WC; ++x)
                    zz += redf[h * WC * M + x * M + wm + qrow + rp * 8];
                rr[h][rp] = 0.25f / zz;   // includes head-mean
            }

        // ---- am = head-mean of softmax ----
        #pragma unroll
        for (int nt = 0; nt < 4; ++nt) {
            float a0 = 0.f, a1 = 0.f, a2 = 0.f, a3 = 0.f;
            #pragma unroll
            for (int h = 0; h < 4; ++h) {
                a0 += c[h][nt][0] * rr[h][0];
                a1 += c[h][nt][1] * rr[h][0];
                a2 += c[h][nt][2] * rr[h][1];
                a3 += c[h][nt][3] * rr[h][1];
            }
            const int colb = wn + nt * 8 + qcol * 2;
            *(float2*)&amf[(wm + qrow)     * AMS + colb] = make_float2(a0, a1);
            *(float2*)&amf[(wm + qrow + 8) * AMS + colb] = make_float2(a2, a3);
        }
        __syncthreads();

        // ---- top-3 per anchor row ----
        constexpr int RPW = M / 8;
        constexpr int NB  = NT / 32;
        float acc = 0.f;
        #pragma unroll
        for (int r2 = 0; r2 < RPW; ++r2)
            acc += top3_sum<NB>(&amf[(w * RPW + r2) * AMS], lane);
        if (lane == 0) waccf[w] = acc;
        __syncthreads();
        if (tid == 0) {
            float tot = 0.f;
            #pragma unroll
            for (int x = 0; x < 8; ++x) tot += waccf[x];
            const int i = cidx >> 2, chunk = cidx & 3;
            part[((i * 32 + j) << 2) + chunk] = tot;
        }
    }
}

// ---------------------------------------------------------------------------
// Kernel C: contrastive loss
// ---------------------------------------------------------------------------
__global__ void loss_kernel(const float* __restrict__ part, float* __restrict__ out)
{
    __shared__ float red[64];
    const int t   = threadIdx.x;
    const int dir = t >> 5;
    const int row = t & 31;
    const float* P = part + dir * 4096;
    const float scale = dir ? (100.f / (3.f * 64.f)) : (100.f / (3.f * 256.f));

    float pos = 0.f;
    float t1 = -1e30f, t2 = -1e30f, t3 = -1e30f;
    for (int j = 0; j < 32; ++j) {
        float4 p4 = *(const float4*)&P[(row * 32 + j) << 2];
        float v = (p4.x + p4.y + p4.z + p4.w) * scale;
        if (j == row) { pos = v; continue; }
        if      (v > t1) { t3 = t2; t2 = t1; t1 = v; }
        else if (v > t2) { t3 = t2; t2 = v; }
        else if (v > t3) { t3 = v; }
    }
    const float invT = 1.0f / 0.07f;
    float l0 = pos * invT, l1 = t1 * invT, l2 = t2 * invT, l3 = t3 * invT;
    float m  = fmaxf(fmaxf(l0, l1), fmaxf(l2, l3));
    float Z  = expf(l0 - m) + expf(l1 - m) + expf(l2 - m) + expf(l3 - m);
    red[t] = -(l0 - m - logf(Z));
    __syncthreads();
    if (t == 0) {
        float s0 = 0.f, s1 = 0.f;
        for (int r = 0; r < 32; ++r) { s0 += red[r]; s1 += red[32 + r]; }
        out[0] = 0.5f * (s0 / 32.f) + 0.5f * (s1 / 32.f);
    }
}

// ---------------------------------------------------------------------------
// Launch (fork-join across two streams; capture-safe event pattern)
// ---------------------------------------------------------------------------
extern "C" void kernel_launch(void* const* d_in, const int* in_sizes, int n_in,
                              void* d_out, int out_size)
{
    const float* lang = (const float*)d_in[0];
    const float* vis  = (const float*)d_in[1];
    const float* W    = (const float*)d_in[2];
    const float* bias = (const float*)d_in[3];

    const int SM_V2T = 64*512 + 64*512 + 64*(64+4)*4  + 4*2*64*4 + 32;  //  85,024
    const int SM_T2V = 256*512 + 16*512 + 16*(256+4)*4 + 4*8*16*4 + 32; // 157,984

    static char *p_ql = nullptr, *p_kl = nullptr, *p_qv = nullptr, *p_kv = nullptr;
    static float *p_part = nullptr;
    static cudaStream_t s2;
    static cudaEvent_t evF, evV, evL, evT;
    if (!p_ql) {
        cudaGetSymbolAddress((void**)&p_ql, g_q_lang);
        cudaGetSymbolAddress((void**)&p_kl, g_k_lang);
        cudaGetSymbolAddress((void**)&p_qv, g_q_vis);
        cudaGetSymbolAddress((void**)&p_kv, g_k_vis);
        cudaGetSymbolAddress((void**)&p_part, g_part);
        cudaFuncSetAttribute((const void*)sim_fused<4, 8, 2>,
                             cudaFuncAttributeMaxDynamicSharedMemorySize, SM_V2T);
        cudaFuncSetAttribute((const void*)sim_fused<1, 16, 1>,
                             cudaFuncAttributeMaxDynamicSharedMemorySize, SM_T2V);
        cudaStreamCreateWithFlags(&s2, cudaStreamNonBlocking);
        cudaEventCreateWithFlags(&evF, cudaEventDisableTiming);
        cudaEventCreateWithFlags(&evV, cudaEventDisableTiming);
        cudaEventCreateWithFlags(&evL, cudaEventDisableTiming);
        cudaEventCreateWithFlags(&evT, cudaEventDisableTiming);
    }

    // fork: bring s2 into the captured graph
    cudaEventRecord(evF, 0);
    cudaStreamWaitEvent(s2, evF, 0);

    proj_kernel<<<dim3(8, 32),  256, 0, 0 >>>(lang, W, bias, 0);
    proj_kernel<<<dim3(8, 128), 256, 0, s2>>>(vis,  W, bias, 1);

    // join: both sims need both projections
    cudaEventRecord(evV, s2);
    cudaStreamWaitEvent(0, evV, 0);
    cudaEventRecord(evL, 0);
    cudaStreamWaitEvent(s2, evL, 0);

    // v2t: anchors = vis q (128 chunks of 64), targets = lang k (NT=64)
    sim_fused<4, 8, 2><<<dim3(32, 16), 256, SM_V2T, 0 >>>(p_qv, p_kl, p_part);
    // t2v: anchors = lang q (128 chunks of 16), targets = vis k (NT=256)
    sim_fused<1, 16, 1><<<dim3(32, 8), 256, SM_T2V, s2>>>(p_ql, p_kv, p_part + 4096);

    // join before loss
    cudaEventRecord(evT, s2);
    cudaStreamWaitEvent(0, evT, 0);

    loss_kernel<<<1, 64, 0, 0>>>(p_part, (float*)d_out);
}

// round 8
// speedup vs baseline: 3.5407x; 1.0205x over previous
#include <cuda_runtime.h>
#include <cuda_bf16.h>
#include <math.h>
#include <stdint.h>

// ---------------------------------------------------------------------------
// Scratch (device globals; no allocation allowed)
// q/k stored as bf16 in ldsm-swizzled layout: row stride 512B,
// byte_off(row, col) = row*512 + (((col>>3) ^ (row&7))<<4) + (col&7)*2
// ---------------------------------------------------------------------------
__device__ __align__(16) char g_q_lang[2048 * 512];
__device__ __align__(16) char g_k_lang[2048 * 512];
__device__ __align__(16) char g_q_vis [8192 * 512];
__device__ __align__(16) char g_k_vis [8192 * 512];
__device__ float g_part[2 * 32 * 32 * 4];   // [dir][i][j][chunk] (zero-init)

// ---------------------------------------------------------------------------
// bf16 / async helpers
// ---------------------------------------------------------------------------
__device__ __forceinline__ uint32_t pack_bf2(float a, float b) {
    __nv_bfloat162 t = __floats2bfloat162_rn(a, b);
    return *(uint32_t*)&t;
}
__device__ __forceinline__ void cpasync16(uint32_t s, const void* g) {
    asm volatile("cp.async.cg.shared.global [%0], [%1], 16;\n" :: "r"(s), "l"(g));
}
__device__ __forceinline__ void cpasync_commit() {
    asm volatile("cp.async.commit_group;\n");
}
__device__ __forceinline__ void cpasync_wait_all() {
    asm volatile("cp.async.wait_group 0;\n");
}
__device__ __forceinline__ void ldsm_x4(uint32_t& r0, uint32_t& r1,
                                        uint32_t& r2, uint32_t& r3, uint32_t addr) {
    asm volatile("ldmatrix.sync.aligned.m8n8.x4.shared.b16 {%0,%1,%2,%3}, [%4];"
                 : "=r"(r0), "=r"(r1), "=r"(r2), "=r"(r3) : "r"(addr));
}
__device__ __forceinline__ void mma_bf16(float c[4],
                                         uint32_t a0, uint32_t a1, uint32_t a2, uint32_t a3,
                                         uint32_t b0, uint32_t b1) {
    asm volatile(
        "mma.sync.aligned.m16n8k16.row.col.f32.bf16.bf16.f32 "
        "{%0,%1,%2,%3}, {%4,%5,%6,%7}, {%8,%9}, {%0,%1,%2,%3};\n"
        : "+f"(c[0]), "+f"(c[1]), "+f"(c[2]), "+f"(c[3])
        : "r"(a0), "r"(a1), "r"(a2), "r"(a3), "r"(b0), "r"(b1));
}

// ---------------------------------------------------------------------------
// Kernel A: projection GEMM -> bf16 swizzled q/k arrays
// ---------------------------------------------------------------------------
__global__ void __launch_bounds__(256) proj_kernel(const float* __restrict__ X,
                                                   const float* __restrict__ W,
                                                   const float* __restrict__ bias,
                                                   int which)
{
    __shared__ float As[32][68];
    __shared__ float Bs[32][68];

    const int bm = blockIdx.y * 64;
    const int bn = blockIdx.x * 64;
    const int tid  = threadIdx.x;
    const int trow = tid >> 4;
    const int tcol = tid & 15;

    float cc[4][4] = {};

    for (int k0 = 0; k0 < 256; k0 += 32) {
        #pragma unroll
        for (int it = 0; it < 2; ++it) {
            int id = tid + it * 256;
            int r  = id >> 3;
            int qc = id & 7;
            float4 va = *(const float4*)(X + (size_t)(bm + r) * 256 + k0 + qc * 4);
            As[qc*4+0][r] = va.x; As[qc*4+1][r] = va.y;
            As[qc*4+2][r] = va.z; As[qc*4+3][r] = va.w;
            float4 vb = *(const float4*)(W + (size_t)(bn + r) * 256 + k0 + qc * 4);
            Bs[qc*4+0][r] = vb.x; Bs[qc*4+1][r] = vb.y;
            Bs[qc*4+2][r] = vb.z; Bs[qc*4+3][r] = vb.w;
        }
        __syncthreads();
        #pragma unroll
        for (int k = 0; k < 32; ++k) {
            float4 a = *(const float4*)&As[k][trow * 4];
            float4 b = *(const float4*)&Bs[k][tcol * 4];
            cc[0][0] += a.x*b.x; cc[0][1] += a.x*b.y; cc[0][2] += a.x*b.z; cc[0][3] += a.x*b.w;
            cc[1][0] += a.y*b.x; cc[1][1] += a.y*b.y; cc[1][2] += a.y*b.z; cc[1][3] += a.y*b.w;
            cc[2][0] += a.z*b.x; cc[2][1] += a.z*b.y; cc[2][2] += a.z*b.z; cc[2][3] += a.z*b.w;
            cc[3][0] += a.w*b.x; cc[3][1] += a.w*b.y; cc[3][2] += a.w*b.z; cc[3][3] += a.w*b.w;
        }
        __syncthreads();
    }

    const int n0   = bn + tcol * 4;
    const bool isq = (n0 < 256);
    const int cl   = n0 & 255;
    char* arr = which ? (isq ? g_q_vis : g_k_vis) : (isq ? g_q_lang : g_k_lang);
    const float b0 = bias[n0], b1 = bias[n0+1], b2 = bias[n0+2], b3 = bias[n0+3];

    #pragma unroll
    for (int x = 0; x < 4; ++x) {
        int m = bm + trow * 4 + x;
        uint32_t lo = pack_bf2(cc[x][0] + b0, cc[x][1] + b1);
        uint32_t hi = pack_bf2(cc[x][2] + b2, cc[x][3] + b3);
        uint32_t off = (uint32_t)m * 512 + ((((cl >> 3) ^ (m & 7)) << 4) | ((cl & 7) << 1));
        *(uint2*)(arr + off) = make_uint2(lo, hi);
    }
}

// ---------------------------------------------------------------------------
// top3 helper
// ---------------------------------------------------------------------------
template<int NB>
__device__ __forceinline__ float top3_sum(const float* v, int lane) {
    float am[NB];
    #pragma unroll
    for (int bi = 0; bi < NB; ++bi) am[bi] = v[bi * 32 + lane];
    unsigned msk = 0; float sum3 = 0.f;
    #pragma unroll
    for (int rr = 0; rr < 3; ++rr) {
        float bv = -1e30f; int bg = lane;
        #pragma unroll
        for (int bi = 0; bi < NB; ++bi)
            if (!((msk >> bi) & 1u) && am[bi] > bv) { bv = am[bi]; bg = (bi << 5) | lane; }
        #pragma unroll
        for (int off = 16; off; off >>= 1) {
            float ov = __shfl_xor_sync(0xffffffffu, bv, off);
            int   og = __shfl_xor_sync(0xffffffffu, bg, off);
            if (ov > bv || (ov == bv && og > bg)) { bv = ov; bg = og; }
        }
        if ((bg & 31) == lane) msk |= 1u << (bg >> 5);
        sum3 += bv;
    }
    return sum3;
}

// ---------------------------------------------------------------------------
// Kernel B: fused sim, persistent over anchor chunks, head-pair blocked.
//   Warp grid WR x WC (NWARP = WR*WC warps). M = WR*16 anchors/iter,
//   NT = WC*32 targets (full softmax axis). No-max softmax.
//   CPB = anchor chunks per batch for part-slot addressing.
// ---------------------------------------------------------------------------
template<int WR, int WC, int NITER, int CPB, int MINB>
__global__ void __launch_bounds__(WR * WC * 32, MINB)
sim_fused(const char* __restrict__ anch_q,
          const char* __restrict__ targ_k,
          float* __restrict__ part)
{
    constexpr int NWARP   = WR * WC;
    constexpr int THREADS = NWARP * 32;
    constexpr int M   = WR * 16;
    constexpr int NT  = WC * 32;
    constexpr int AMS = NT + 4;

    constexpr int OFF_B    = 0;                      // NT x 512B (swizzled bf16)
    constexpr int OFF_A    = OFF_B + NT * 512;       // M x 512B
    constexpr int OFF_AM   = OFF_A + M * 512;        // M x AMS f32
    constexpr int OFF_RED  = OFF_AM + M * AMS * 4;   // 4 x WC x M f32
    constexpr int OFF_WACC = OFF_RED + 4 * WC * M * 4;

    extern __shared__ char smem[];
    const uint32_t sbase = (uint32_t)__cvta_generic_to_shared(smem);

    const int j    = blockIdx.x;
    const int z    = blockIdx.y;
    const int tid  = threadIdx.x;
    const int w    = tid >> 5;
    const int lane = tid & 31;

    // ---- B tile: straight byte copy (already bf16 + swizzled) ----
    {
        const char* src = targ_k + (size_t)j * NT * 512;
        #pragma unroll
        for (int id = tid; id < NT * 32; id += THREADS)
            cpasync16(sbase + OFF_B + id * 16, src + id * 16);
        cpasync_commit();
    }

    const int wm = (w / WC) * 16;
    const int wn = (w % WC) * 32;
    const int wc = w % WC;
    const int l8  = lane & 7;
    const int sub = lane >> 3;
    const int qrow = lane >> 2;
    const int qcol = lane & 3;

    const uint32_t a_base = sbase + OFF_A + (uint32_t)(wm + l8 + (sub & 1) * 8) * 512;
    const int      a_coff = sub >> 1;
    const uint32_t b_base = sbase + OFF_B + (uint32_t)(wn + l8 + ((sub >> 1) & 1) * 8) * 512;
    const int      b_coff = sub & 1;

    float* redf  = (float*)(smem + OFF_RED);
    float* amf   = (float*)(smem + OFF_AM);
    float* waccf = (float*)(smem + OFF_WACC);

    for (int it = 0; it < NITER; ++it) {
        const int cidx = z * NITER + it;

        __syncthreads();   // previous iter fully done before A overwrite
        {
            const char* src = anch_q + (size_t)cidx * M * 512;
            #pragma unroll
            for (int id = tid; id < M * 32; id += THREADS)
                cpasync16(sbase + OFF_A + id * 16, src + id * 16);
            cpasync_commit();
            cpasync_wait_all();   // waits B too on first iter
        }
        __syncthreads();

        float am[4][4];
        #pragma unroll
        for (int nt = 0; nt < 4; ++nt)
            #pragma unroll
            for (int e = 0; e < 4; ++e) am[nt][e] = 0.f;

        // ---- head pairs: MMA -> exp -> Z reduce -> am accumulate ----
        #pragma unroll
        for (int hp = 0; hp < 2; ++hp) {
            float c[2][4][4];
            #pragma unroll
            for (int hh = 0; hh < 2; ++hh)
                #pragma unroll
                for (int nt = 0; nt < 4; ++nt)
                    #pragma unroll
                    for (int e = 0; e < 4; ++e) c[hh][nt][e] = 0.f;

            #pragma unroll
            for (int hh = 0; hh < 2; ++hh) {
                const int h = hp * 2 + hh;
                #pragma unroll
                for (int s = 0; s < 4; ++s) {
                    const int cq = h * 8 + s * 2;
                    uint32_t a0, a1, a2, a3, p0, p1, p2, p3, q0, q1, q2, q3;
                    ldsm_x4(a0, a1, a2, a3, a_base + (((cq + a_coff) ^ l8) << 4));
                    ldsm_x4(p0, p1, p2, p3, b_base + (((cq + b_coff) ^ l8) << 4));
                    ldsm_x4(q0, q1, q2, q3, b_base + 16 * 512 + (((cq + b_coff) ^ l8) << 4));
                    mma_bf16(c[hh][0], a0, a1, a2, a3, p0, p1);
                    mma_bf16(c[hh][1], a0, a1, a2, a3, p2, p3);
                    mma_bf16(c[hh][2], a0, a1, a2, a3, q0, q1);
                    mma_bf16(c[hh][3], a0, a1, a2, a3, q2, q3);
                }
            }

            // exp (scale folded) + warp-partial Z
            #pragma unroll
            for (int hh = 0; hh < 2; ++hh) {
                const int h = hp * 2 + hh;
                float z0 = 0.f, z1 = 0.f;
                #pragma unroll
                for (int nt = 0; nt < 4; ++nt) {
                    c[hh][nt][0] = __expf(c[hh][nt][0] * 0.125f);
                    c[hh][nt][1] = __expf(c[hh][nt][1] * 0.125f);
                    c[hh][nt][2] = __expf(c[hh][nt][2] * 0.125f);
                    c[hh][nt][3] = __expf(c[hh][nt][3] * 0.125f);
                    z0 += c[hh][nt][0] + c[hh][nt][1];
                    z1 += c[hh][nt][2] + c[hh][nt][3];
                }
                z0 += __shfl_xor_sync(0xffffffffu, z0, 1);
                z0 += __shfl_xor_sync(0xffffffffu, z0, 2);
                z1 += __shfl_xor_sync(0xffffffffu, z1, 1);
                z1 += __shfl_xor_sync(0xffffffffu, z1, 2);
                if (qcol == 0) {
                    redf[h * WC * M + wc * M + wm + qrow]     = z0;
                    redf[h * WC * M + wc * M + wm + qrow + 8] = z1;
                }
            }
            __syncthreads();

            float rr[2][2];
            #pragma unroll
            for (int hh = 0; hh < 2; ++hh) {
                const int h = hp * 2 + hh;
                #pragma unroll
                for (int rp = 0; rp < 2; ++rp) {
                    float zz = 0.f;
                    #pragma unroll
                    for (int x = 0; x < WC; ++x)
                        zz += redf[h * WC * M + x * M + wm + qrow + rp * 8];
                    rr[hh][rp] = 0.25f / zz;   // includes head-mean
                }
            }

            #pragma unroll
            for (int nt = 0; nt < 4; ++nt) {
                am[nt][0] += c[0][nt][0] * rr[0][0] + c[1][nt][0] * rr[1][0];
                am[nt][1] += c[0][nt][1] * rr[0][0] + c[1][nt][1] * rr[1][0];
                am[nt][2] += c[0][nt][2] * rr[0][1] + c[1][nt][2] * rr[1][1];
                am[nt][3] += c[0][nt][3] * rr[0][1] + c[1][nt][3] * rr[1][1];
            }
        }

        // ---- stash am tile to smem ----
        #pragma unroll
        for (int nt = 0; nt < 4; ++nt) {
            const int colb = wn + nt * 8 + qcol * 2;
            *(float2*)&amf[(wm + qrow)     * AMS + colb] = make_float2(am[nt][0], am[nt][1]);
            *(float2*)&amf[(wm + qrow + 8) * AMS + colb] = make_float2(am[nt][2], am[nt][3]);
        }
        __syncthreads();

        // ---- top-3 per anchor row ----
        constexpr int RPW = M / NWARP;
        constexpr int NB  = NT / 32;
        float acc = 0.f;
        #pragma unroll
        for (int r2 = 0; r2 < RPW; ++r2)
            acc += top3_sum<NB>(&amf[(w * RPW + r2) * AMS], lane);
        if (lane == 0) waccf[w] = acc;
        __syncthreads();
        if (tid == 0) {
            float tot = 0.f;
            #pragma unroll
            for (int x = 0; x < NWARP; ++x) tot += waccf[x];
            const int i = cidx / CPB, slot = cidx % CPB;
            part[((i * 32 + j) << 2) + slot] = tot;
        }
    }
}

// ---------------------------------------------------------------------------
// Kernel C: contrastive loss (slots beyond CPB stay zero from static init)
// ---------------------------------------------------------------------------
__global__ void loss_kernel(const float* __restrict__ part, float* __restrict__ out)
{
    __shared__ float red[64];
    const int t   = threadIdx.x;
    const int dir = t >> 5;
    const int row = t & 31;
    const float* P = part + dir * 4096;
    const float scale = dir ? (100.f / (3.f * 64.f)) : (100.f / (3.f * 256.f));

    float pos = 0.f;
    float t1 = -1e30f, t2 = -1e30f, t3 = -1e30f;
    for (int j = 0; j < 32; ++j) {
        float4 p4 = *(const float4*)&P[(row * 32 + j) << 2];
        float v = (p4.x + p4.y + p4.z + p4.w) * scale;
        if (j == row) { pos = v; continue; }
        if      (v > t1) { t3 = t2; t2 = t1; t1 = v; }
        else if (v > t2) { t3 = t2; t2 = v; }
        else if (v > t3) { t3 = v; }
    }
    const float invT = 1.0f / 0.07f;
    float l0 = pos * invT, l1 = t1 * invT, l2 = t2 * invT, l3 = t3 * invT;
    float m  = fmaxf(fmaxf(l0, l1), fmaxf(l2, l3));
    float Z  = expf(l0 - m) + expf(l1 - m) + expf(l2 - m) + expf(l3 - m);
    red[t] = -(l0 - m - logf(Z));
    __syncthreads();
    if (t == 0) {
        float s0 = 0.f, s1 = 0.f;
        for (int r = 0; r < 32; ++r) { s0 += red[r]; s1 += red[32 + r]; }
        out[0] = 0.5f * (s0 / 32.f) + 0.5f * (s1 / 32.f);
    }
}

// ---------------------------------------------------------------------------
// Launch (fork-join across two streams; capture-safe event pattern)
// ---------------------------------------------------------------------------
extern "C" void kernel_launch(void* const* d_in, const int* in_sizes, int n_in,
                              void* d_out, int out_size)
{
    const float* lang = (const float*)d_in[0];
    const float* vis  = (const float*)d_in[1];
    const float* W    = (const float*)d_in[2];
    const float* bias = (const float*)d_in[3];

    // v2t: WR=4, WC=2 -> M=64, NT=64, 256 thr
    const int SM_V2T = 64*512 + 64*512 + 64*(64+4)*4 + 4*2*64*4 + 8*4;      //  85,024
    // t2v: WR=2, WC=8 -> M=32, NT=256, 512 thr
    const int SM_T2V = 256*512 + 32*512 + 32*(256+4)*4 + 4*8*32*4 + 16*4;   // 184,896

    static char *p_ql = nullptr, *p_kl = nullptr, *p_qv = nullptr, *p_kv = nullptr;
    static float *p_part = nullptr;
    static cudaStream_t s2;
    static cudaEvent_t evF, evV, evL, evT;
    if (!p_ql) {
        cudaGetSymbolAddress((void**)&p_ql, g_q_lang);
        cudaGetSymbolAddress((void**)&p_kl, g_k_lang);
        cudaGetSymbolAddress((void**)&p_qv, g_q_vis);
        cudaGetSymbolAddress((void**)&p_kv, g_k_vis);
        cudaGetSymbolAddress((void**)&p_part, g_part);
        cudaFuncSetAttribute((const void*)sim_fused<4, 2, 8, 4, 2>,
                             cudaFuncAttributeMaxDynamicSharedMemorySize, SM_V2T);
        cudaFuncSetAttribute((const void*)sim_fused<2, 8, 8, 2, 1>,
                             cudaFuncAttributeMaxDynamicSharedMemorySize, SM_T2V);
        cudaStreamCreateWithFlags(&s2, cudaStreamNonBlocking);
        cudaEventCreateWithFlags(&evF, cudaEventDisableTiming);
        cudaEventCreateWithFlags(&evV, cudaEventDisableTiming);
        cudaEventCreateWithFlags(&evL, cudaEventDisableTiming);
        cudaEventCreateWithFlags(&evT, cudaEventDisableTiming);
    }

    // fork: bring s2 into the captured graph
    cudaEventRecord(evF, 0);
    cudaStreamWaitEvent(s2, evF, 0);

    proj_kernel<<<dim3(8, 32),  256, 0, 0 >>>(lang, W, bias, 0);
    proj_kernel<<<dim3(8, 128), 256, 0, s2>>>(vis,  W, bias, 1);

    // join: both sims need both projections
    cudaEventRecord(evV, s2);
    cudaStreamWaitEvent(0, evV, 0);
    cudaEventRecord(evL, 0);
    cudaStreamWaitEvent(s2, evL, 0);

    // v2t: anchors = vis q (128 chunks of 64), targets = lang k (NT=64)
    sim_fused<4, 2, 8, 4, 2><<<dim3(32, 16), 256, SM_V2T, 0 >>>(p_qv, p_kl, p_part);
    // t2v: anchors = lang q (64 chunks of 32), targets = vis k (NT=256)
    sim_fused<2, 8, 8, 2, 1><<<dim3(32, 8), 512, SM_T2V, s2>>>(p_ql, p_kv, p_part + 4096);

    // join before loss
    cudaEventRecord(evT, s2);
    cudaStreamWaitEvent(0, evT, 0);

    loss_kernel<<<1, 64, 0, 0>>>(p_part, (float*)d_out);
}

// round 9
// speedup vs baseline: 4.2380x; 1.1969x over previous
#include <cuda_runtime.h>
#include <cuda_bf16.h>
#include <math.h>
#include <stdint.h>

// ---------------------------------------------------------------------------
// Scratch (device globals; no allocation allowed)
// q/k stored as bf16 in ldsm-swizzled layout: row stride 512B,
// byte_off(row, col) = row*512 + (((col>>3) ^ (row&7))<<4) + (col&7)*2
// ---------------------------------------------------------------------------
__device__ __align__(16) char g_q_lang[2048 * 512];
__device__ __align__(16) char g_k_lang[2048 * 512];
__device__ __align__(16) char g_q_vis [8192 * 512];
__device__ __align__(16) char g_k_vis [8192 * 512];
__device__ float g_part[2 * 32 * 32 * 4];   // [dir][i][j][slot] (zero-init)

// ---------------------------------------------------------------------------
// helpers
// ---------------------------------------------------------------------------
__device__ __forceinline__ uint32_t pack_bf2(float a, float b) {
    __nv_bfloat162 t = __floats2bfloat162_rn(a, b);
    return *(uint32_t*)&t;
}
__device__ __forceinline__ uint32_t f2tf32(float v) {
    uint32_t r;
    asm("cvt.rna.tf32.f32 %0, %1;" : "=r"(r) : "f"(v));
    return r;
}
__device__ __forceinline__ void mma_tf32(float c[4],
                                         uint32_t a0, uint32_t a1, uint32_t a2, uint32_t a3,
                                         uint32_t b0, uint32_t b1)
{
    asm volatile(
        "mma.sync.aligned.m16n8k8.row.col.f32.tf32.tf32.f32 "
        "{%0,%1,%2,%3}, {%4,%5,%6,%7}, {%8,%9}, {%0,%1,%2,%3};\n"
        : "+f"(c[0]), "+f"(c[1]), "+f"(c[2]), "+f"(c[3])
        : "r"(a0), "r"(a1), "r"(a2), "r"(a3), "r"(b0), "r"(b1));
}
__device__ __forceinline__ void cpasync16(uint32_t s, const void* g) {
    asm volatile("cp.async.cg.shared.global [%0], [%1], 16;\n" :: "r"(s), "l"(g));
}
__device__ __forceinline__ void cpasync_commit() {
    asm volatile("cp.async.commit_group;\n");
}
__device__ __forceinline__ void cpasync_wait_all() {
    asm volatile("cp.async.wait_group 0;\n");
}
__device__ __forceinline__ void ldsm_x4(uint32_t& r0, uint32_t& r1,
                                        uint32_t& r2, uint32_t& r3, uint32_t addr) {
    asm volatile("ldmatrix.sync.aligned.m8n8.x4.shared.b16 {%0,%1,%2,%3}, [%4];"
                 : "=r"(r0), "=r"(r1), "=r"(r2), "=r"(r3) : "r"(addr));
}
__device__ __forceinline__ void mma_bf16(float c[4],
                                         uint32_t a0, uint32_t a1, uint32_t a2, uint32_t a3,
                                         uint32_t b0, uint32_t b1) {
    asm volatile(
        "mma.sync.aligned.m16n8k16.row.col.f32.bf16.bf16.f32 "
        "{%0,%1,%2,%3}, {%4,%5,%6,%7}, {%8,%9}, {%0,%1,%2,%3};\n"
        : "+f"(c[0]), "+f"(c[1]), "+f"(c[2]), "+f"(c[3])
        : "r"(a0), "r"(a1), "r"(a2), "r"(a3), "r"(b0), "r"(b1));
}

// ---------------------------------------------------------------------------
// Kernel A: projection GEMM (tf32 tensor cores) -> bf16 swizzled q/k arrays
//   out[m][n] = X[m,:]·W[n,:] + bias[n], n in [0,512)
//   Block tile 128(m) x 64(n); K=256 in 4 chunks of 64. Grid (8, M/128).
// ---------------------------------------------------------------------------
__global__ void __launch_bounds__(256) proj_tc(const float* __restrict__ X,
                                               const float* __restrict__ W,
                                               const float* __restrict__ bias,
                                               int which)
{
    extern __shared__ uint32_t smemU[];
    uint32_t* As = smemU;               // [128][68]
    uint32_t* Bs = smemU + 128 * 68;    // [64][68]

    const int n0  = blockIdx.x * 64;
    const int m0  = blockIdx.y * 128;
    const int tid = threadIdx.x;
    const int w    = tid >> 5;
    const int lane = tid & 31;

    const int wm = (w & 3) * 32;
    const int wn = (w >> 2) * 32;
    const int qrow = lane >> 2;
    const int qcol = lane & 3;

    float c[2][4][4] = {};

    for (int k0 = 0; k0 < 256; k0 += 64) {
        __syncthreads();
        #pragma unroll
        for (int it = 0; it < 8; ++it) {
            int id = tid + it * 256;
            int r  = id >> 4;
            int q  = id & 15;
            float4 v = *(const float4*)(X + (size_t)(m0 + r) * 256 + k0 + q * 4);
            uint32_t* d = As + r * 68 + q * 4;
            d[0] = f2tf32(v.x); d[1] = f2tf32(v.y); d[2] = f2tf32(v.z); d[3] = f2tf32(v.w);
        }
        #pragma unroll
        for (int it = 0; it < 4; ++it) {
            int id = tid + it * 256;
            int r  = id >> 4;
            int q  = id & 15;
            float4 v = *(const float4*)(W + (size_t)(n0 + r) * 256 + k0 + q * 4);
            uint32_t* d = Bs + r * 68 + q * 4;
            d[0] = f2tf32(v.x); d[1] = f2tf32(v.y); d[2] = f2tf32(v.z); d[3] = f2tf32(v.w);
        }
        __syncthreads();

        const uint32_t* Aw = As + wm * 68;
        const uint32_t* Bw = Bs + wn * 68;
        #pragma unroll
        for (int kk = 0; kk < 8; ++kk) {
            uint32_t a[2][4];
            #pragma unroll
            for (int mt = 0; mt < 2; ++mt) {
                const uint32_t* p = Aw + (mt * 16 + qrow) * 68 + kk * 8 + qcol;
                a[mt][0] = p[0];
                a[mt][1] = p[8 * 68];
                a[mt][2] = p[4];
                a[mt][3] = p[8 * 68 + 4];
            }
            uint32_t b[4][2];
            #pragma unroll
            for (int nt = 0; nt < 4; ++nt) {
                const uint32_t* p = Bw + (nt * 8 + qrow) * 68 + kk * 8 + qcol;
                b[nt][0] = p[0];
                b[nt][1] = p[4];
            }
            #pragma unroll
            for (int mt = 0; mt < 2; ++mt)
                #pragma unroll
                for (int nt = 0; nt < 4; ++nt)
                    mma_tf32(c[mt][nt], a[mt][0], a[mt][1], a[mt][2], a[mt][3],
                             b[nt][0], b[nt][1]);
        }
    }

    // Epilogue: + bias, pack bf16 pairs, store to swizzled layout
    const bool isq = (n0 < 256);
    char* arr = which ? (isq ? g_q_vis : g_k_vis) : (isq ? g_q_lang : g_k_lang);

    #pragma unroll
    for (int mt = 0; mt < 2; ++mt) {
        #pragma unroll
        for (int nt = 0; nt < 4; ++nt) {
            const int n  = n0 + wn + nt * 8 + qcol * 2;
            const int cl = n & 255;
            const float b0 = __ldg(bias + n), b1 = __ldg(bias + n + 1);
            const int r0 = m0 + wm + mt * 16 + qrow;
            const int r1 = r0 + 8;
            uint32_t v0 = pack_bf2(c[mt][nt][0] + b0, c[mt][nt][1] + b1);
            uint32_t v1 = pack_bf2(c[mt][nt][2] + b0, c[mt][nt][3] + b1);
            uint32_t o0 = (uint32_t)r0 * 512 + ((((cl >> 3) ^ (r0 & 7)) << 4) | ((cl & 7) << 1));
            uint32_t o1 = (uint32_t)r1 * 512 + ((((cl >> 3) ^ (r1 & 7)) << 4) | ((cl & 7) << 1));
            *(uint32_t*)(arr + o0) = v0;
            *(uint32_t*)(arr + o1) = v1;
        }
    }
}

// ---------------------------------------------------------------------------
// top3 helper
// ---------------------------------------------------------------------------
template<int NB>
__device__ __forceinline__ float top3_sum(const float* v, int lane) {
    float am[NB];
    #pragma unroll
    for (int bi = 0; bi < NB; ++bi) am[bi] = v[bi * 32 + lane];
    unsigned msk = 0; float sum3 = 0.f;
    #pragma unroll
    for (int rr = 0; rr < 3; ++rr) {
        float bv = -1e30f; int bg = lane;
        #pragma unroll
        for (int bi = 0; bi < NB; ++bi)
            if (!((msk >> bi) & 1u) && am[bi] > bv) { bv = am[bi]; bg = (bi << 5) | lane; }
        #pragma unroll
        for (int off = 16; off; off >>= 1) {
            float ov = __shfl_xor_sync(0xffffffffu, bv, off);
            int   og = __shfl_xor_sync(0xffffffffu, bg, off);
            if (ov > bv || (ov == bv && og > bg)) { bv = ov; bg = og; }
        }
        if ((bg & 31) == lane) msk |= 1u << (bg >> 5);
        sum3 += bv;
    }
    return sum3;
}

// ---------------------------------------------------------------------------
// Kernel B: fused sim, persistent over anchor chunks, HPB heads per step.
//   Warp grid WR x WC. M = WR*16 anchors/iter, NT = WC*32 targets.
//   No-max softmax. CPB = anchor chunks per batch for part-slot addressing.
// ---------------------------------------------------------------------------
template<int WR, int WC, int NITER, int CPB, int MINB, int HPB>
__global__ void __launch_bounds__(WR * WC * 32, MINB)
sim_fused(const char* __restrict__ anch_q,
          const char* __restrict__ targ_k,
          float* __restrict__ part)
{
    constexpr int NWARP   = WR * WC;
    constexpr int THREADS = NWARP * 32;
    constexpr int M   = WR * 16;
    constexpr int NT  = WC * 32;
    constexpr int AMS = NT + 4;

    constexpr int OFF_B    = 0;                      // NT x 512B (swizzled bf16)
    constexpr int OFF_A    = OFF_B + NT * 512;       // M x 512B
    constexpr int OFF_AM   = OFF_A + M * 512;        // M x AMS f32
    constexpr int OFF_RED  = OFF_AM + M * AMS * 4;   // 4 x WC x M f32
    constexpr int OFF_WACC = OFF_RED + 4 * WC * M * 4;

    extern __shared__ char smem[];
    const uint32_t sbase = (uint32_t)__cvta_generic_to_shared(smem);

    const int j    = blockIdx.x;
    const int z    = blockIdx.y;
    const int tid  = threadIdx.x;
    const int w    = tid >> 5;
    const int lane = tid & 31;

    // ---- B tile: straight byte copy (already bf16 + swizzled) ----
    {
        const char* src = targ_k + (size_t)j * NT * 512;
        #pragma unroll
        for (int id = tid; id < NT * 32; id += THREADS)
            cpasync16(sbase + OFF_B + id * 16, src + id * 16);
        cpasync_commit();
    }

    const int wm = (w / WC) * 16;
    const int wn = (w % WC) * 32;
    const int wc = w % WC;
    const int l8  = lane & 7;
    const int sub = lane >> 3;
    const int qrow = lane >> 2;
    const int qcol = lane & 3;

    const uint32_t a_base = sbase + OFF_A + (uint32_t)(wm + l8 + (sub & 1) * 8) * 512;
    const int      a_coff = sub >> 1;
    const uint32_t b_base = sbase + OFF_B + (uint32_t)(wn + l8 + ((sub >> 1) & 1) * 8) * 512;
    const int      b_coff = sub & 1;

    float* redf  = (float*)(smem + OFF_RED);
    float* amf   = (float*)(smem + OFF_AM);
    float* waccf = (float*)(smem + OFF_WACC);

    for (int it = 0; it < NITER; ++it) {
        const int cidx = z * NITER + it;

        __syncthreads();   // previous iter fully done before A overwrite
        {
            const char* src = anch_q + (size_t)cidx * M * 512;
            #pragma unroll
            for (int id = tid; id < M * 32; id += THREADS)
                cpasync16(sbase + OFF_A + id * 16, src + id * 16);
            cpasync_commit();
            cpasync_wait_all();   // waits B too on first iter
        }
        __syncthreads();

        float am[4][4];
        #pragma unroll
        for (int nt = 0; nt < 4; ++nt)
            #pragma unroll
            for (int e = 0; e < 4; ++e) am[nt][e] = 0.f;

        // ---- head groups of HPB: MMA -> exp -> Z reduce -> am accumulate ----
        #pragma unroll
        for (int hp = 0; hp < 4; hp += HPB) {
            float c[HPB][4][4];
            #pragma unroll
            for (int hh = 0; hh < HPB; ++hh)
                #pragma unroll
                for (int nt = 0; nt < 4; ++nt)
                    #pragma unroll
                    for (int e = 0; e < 4; ++e) c[hh][nt][e] = 0.f;

            #pragma unroll
            for (int hh = 0; hh < HPB; ++hh) {
                const int h = hp + hh;
                #pragma unroll
                for (int s = 0; s < 4; ++s) {
                    const int cq = h * 8 + s * 2;
                    uint32_t a0, a1, a2, a3, p0, p1, p2, p3, q0, q1, q2, q3;
                    ldsm_x4(a0, a1, a2, a3, a_base + (((cq + a_coff) ^ l8) << 4));
                    ldsm_x4(p0, p1, p2, p3, b_base + (((cq + b_coff) ^ l8) << 4));
                    ldsm_x4(q0, q1, q2, q3, b_base + 16 * 512 + (((cq + b_coff) ^ l8) << 4));
                    mma_bf16(c[hh][0], a0, a1, a2, a3, p0, p1);
                    mma_bf16(c[hh][1], a0, a1, a2, a3, p2, p3);
                    mma_bf16(c[hh][2], a0, a1, a2, a3, q0, q1);
                    mma_bf16(c[hh][3], a0, a1, a2, a3, q2, q3);
                }
            }

            // exp (scale folded) + warp-partial Z
            #pragma unroll
            for (int hh = 0; hh < HPB; ++hh) {
                const int h = hp + hh;
                float z0 = 0.f, z1 = 0.f;
                #pragma unroll
                for (int nt = 0; nt < 4; ++nt) {
                    c[hh][nt][0] = __expf(c[hh][nt][0] * 0.125f);
                    c[hh][nt][1] = __expf(c[hh][nt][1] * 0.125f);
                    c[hh][nt][2] = __expf(c[hh][nt][2] * 0.125f);
                    c[hh][nt][3] = __expf(c[hh][nt][3] * 0.125f);
                    z0 += c[hh][nt][0] + c[hh][nt][1];
                    z1 += c[hh][nt][2] + c[hh][nt][3];
                }
                z0 += __shfl_xor_sync(0xffffffffu, z0, 1);
                z0 += __shfl_xor_sync(0xffffffffu, z0, 2);
                z1 += __shfl_xor_sync(0xffffffffu, z1, 1);
                z1 += __shfl_xor_sync(0xffffffffu, z1, 2);
                if (qcol == 0) {
                    redf[h * WC * M + wc * M + wm + qrow]     = z0;
                    redf[h * WC * M + wc * M + wm + qrow + 8] = z1;
                }
            }
            __syncthreads();

            float rr[HPB][2];
            #pragma unroll
            for (int hh = 0; hh < HPB; ++hh) {
                const int h = hp + hh;
                #pragma unroll
                for (int rp = 0; rp < 2; ++rp) {
                    float zz = 0.f;
                    #pragma unroll
                    for (int x = 0; x < WC; ++x)
                        zz += redf[h * WC * M + x * M + wm + qrow + rp * 8];
                    rr[hh][rp] = 0.25f / zz;   // includes head-mean
                }
            }

            #pragma unroll
            for (int nt = 0; nt < 4; ++nt)
                #pragma unroll
                for (int hh = 0; hh < HPB; ++hh) {
                    am[nt][0] += c[hh][nt][0] * rr[hh][0];
                    am[nt][1] += c[hh][nt][1] * rr[hh][0];
                    am[nt][2] += c[hh][nt][2] * rr[hh][1];
                    am[nt][3] += c[hh][nt][3] * rr[hh][1];
                }
        }

        // ---- stash am tile to smem ----
        #pragma unroll
        for (int nt = 0; nt < 4; ++nt) {
            const int colb = wn + nt * 8 + qcol * 2;
            *(float2*)&amf[(wm + qrow)     * AMS + colb] = make_float2(am[nt][0], am[nt][1]);
            *(float2*)&amf[(wm + qrow + 8) * AMS + colb] = make_float2(am[nt][2], am[nt][3]);
        }
        __syncthreads();

        // ---- top-3 per anchor row ----
        constexpr int RPW = M / NWARP;
        constexpr int NB  = NT / 32;
        float acc = 0.f;
        #pragma unroll
        for (int r2 = 0; r2 < RPW; ++r2)
            acc += top3_sum<NB>(&amf[(w * RPW + r2) * AMS], lane);
        if (lane == 0) waccf[w] = acc;
        __syncthreads();
        if (tid == 0) {
            float tot = 0.f;
            #pragma unroll
            for (int x = 0; x < NWARP; ++x) tot += waccf[x];
            const int i = cidx / CPB, slot = cidx % CPB;
            part[((i * 32 + j) << 2) + slot] = tot;
        }
    }
}

// ---------------------------------------------------------------------------
// Kernel C: contrastive loss (slots beyond CPB stay zero from static init)
// ---------------------------------------------------------------------------
__global__ void loss_kernel(const float* __restrict__ part, float* __restrict__ out)
{
    __shared__ float red[64];
    const int t   = threadIdx.x;
    const int dir = t >> 5;
    const int row = t & 31;
    const float* P = part + dir * 4096;
    const float scale = dir ? (100.f / (3.f * 64.f)) : (100.f / (3.f * 256.f));

    float pos = 0.f;
    float t1 = -1e30f, t2 = -1e30f, t3 = -1e30f;
    for (int j = 0; j < 32; ++j) {
        float4 p4 = *(const float4*)&P[(row * 32 + j) << 2];
        float v = (p4.x + p4.y + p4.z + p4.w) * scale;
        if (j == row) { pos = v; continue; }
        if      (v > t1) { t3 = t2; t2 = t1; t1 = v; }
        else if (v > t2) { t3 = t2; t2 = v; }
        else if (v > t3) { t3 = v; }
    }
    const float invT = 1.0f / 0.07f;
    float l0 = pos * invT, l1 = t1 * invT, l2 = t2 * invT, l3 = t3 * invT;
    float m  = fmaxf(fmaxf(l0, l1), fmaxf(l2, l3));
    float Z  = expf(l0 - m) + expf(l1 - m) + expf(l2 - m) + expf(l3 - m);
    red[t] = -(l0 - m - logf(Z));
    __syncthreads();
    if (t == 0) {
        float s0 = 0.f, s1 = 0.f;
        for (int r = 0; r < 32; ++r) { s0 += red[r]; s1 += red[32 + r]; }
        out[0] = 0.5f * (s0 / 32.f) + 0.5f * (s1 / 32.f);
    }
}

// ---------------------------------------------------------------------------
// Launch (fork-join across two streams; capture-safe event pattern)
// ---------------------------------------------------------------------------
extern "C" void kernel_launch(void* const* d_in, const int* in_sizes, int n_in,
                              void* d_out, int out_size)
{
    const float* lang = (const float*)d_in[0];
    const float* vis  = (const float*)d_in[1];
    const float* W    = (const float*)d_in[2];
    const float* bias = (const float*)d_in[3];

    const int SM_PROJ = (128 * 68 + 64 * 68) * 4;   // 52,224
    // v2t: WR=4, WC=2 -> M=64, NT=64, 256 thr, HPB=2
    const int SM_V2T = 64*512 + 64*512 + 64*(64+4)*4 + 4*2*64*4 + 8*4;      //  85,024
    // t2v: WR=2, WC=8 -> M=32, NT=256, 512 thr, HPB=1
    const int SM_T2V = 256*512 + 32*512 + 32*(256+4)*4 + 4*8*32*4 + 16*4;   // 184,896

    static char *p_ql = nullptr, *p_kl = nullptr, *p_qv = nullptr, *p_kv = nullptr;
    static float *p_part = nullptr;
    static cudaStream_t s2;
    static cudaEvent_t evF, evV, evL, evT;
    if (!p_ql) {
        cudaGetSymbolAddress((void**)&p_ql, g_q_lang);
        cudaGetSymbolAddress((void**)&p_kl, g_k_lang);
        cudaGetSymbolAddress((void**)&p_qv, g_q_vis);
        cudaGetSymbolAddress((void**)&p_kv, g_k_vis);
        cudaGetSymbolAddress((void**)&p_part, g_part);
        cudaFuncSetAttribute((const void*)proj_tc,
                             cudaFuncAttributeMaxDynamicSharedMemorySize, SM_PROJ);
        cudaFuncSetAttribute((const void*)sim_fused<4, 2, 8, 4, 2, 2>,
                             cudaFuncAttributeMaxDynamicSharedMemorySize, SM_V2T);
        cudaFuncSetAttribute((const void*)sim_fused<2, 8, 8, 2, 1, 1>,
                             cudaFuncAttributeMaxDynamicSharedMemorySize, SM_T2V);
        cudaStreamCreateWithFlags(&s2, cudaStreamNonBlocking);
        cudaEventCreateWithFlags(&evF, cudaEventDisableTiming);
        cudaEventCreateWithFlags(&evV, cudaEventDisableTiming);
        cudaEventCreateWithFlags(&evL, cudaEventDisableTiming);
        cudaEventCreateWithFlags(&evT, cudaEventDisableTiming);
    }

    // fork: bring s2 into the captured graph
    cudaEventRecord(evF, 0);
    cudaStreamWaitEvent(s2, evF, 0);

    proj_tc<<<dim3(8, 16), 256, SM_PROJ, 0 >>>(lang, W, bias, 0);
    proj_tc<<<dim3(8, 64), 256, SM_PROJ, s2>>>(vis,  W, bias, 1);

    // join: both sims need both projections
    cudaEventRecord(evV, s2);
    cudaStreamWaitEvent(0, evV, 0);
    cudaEventRecord(evL, 0);
    cudaStreamWaitEvent(s2, evL, 0);

    // v2t: anchors = vis q (128 chunks of 64), targets = lang k (NT=64)
    sim_fused<4, 2, 8, 4, 2, 2><<<dim3(32, 16), 256, SM_V2T, 0 >>>(p_qv, p_kl, p_part);
    // t2v: anchors = lang q (64 chunks of 32), targets = vis k (NT=256)
    sim_fused<2, 8, 8, 2, 1, 1><<<dim3(32, 8), 512, SM_T2V, s2>>>(p_ql, p_kv, p_part + 4096);

    // join before loss
    cudaEventRecord(evT, s2);
    cudaStreamWaitEvent(0, evT, 0);

    loss_kernel<<<1, 64, 0, 0>>>(p_part, (float*)d_out);
}

// round 10
// speedup vs baseline: 4.2878x; 1.0118x over previous
#include <cuda_runtime.h>
#include <cuda_bf16.h>
#include <math.h>
#include <stdint.h>

// ---------------------------------------------------------------------------
// Scratch (device globals; no allocation allowed)
// q/k stored as bf16 in ldsm-swizzled layout: row stride 512B,
// byte_off(row, col) = row*512 + (((col>>3) ^ (row&7))<<4) + (col&7)*2
// ---------------------------------------------------------------------------
__device__ __align__(16) char g_q_lang[2048 * 512];
__device__ __align__(16) char g_k_lang[2048 * 512];
__device__ __align__(16) char g_q_vis [8192 * 512];
__device__ __align__(16) char g_k_vis [8192 * 512];
__device__ float g_part[2 * 32 * 32 * 4];   // [dir][i][j][slot]

// ---------------------------------------------------------------------------
// helpers
// ---------------------------------------------------------------------------
__device__ __forceinline__ uint32_t pack_bf2(float a, float b) {
    __nv_bfloat162 t = __floats2bfloat162_rn(a, b);
    return *(uint32_t*)&t;
}
__device__ __forceinline__ uint32_t f2tf32(float v) {
    uint32_t r;
    asm("cvt.rna.tf32.f32 %0, %1;" : "=r"(r) : "f"(v));
    return r;
}
__device__ __forceinline__ void mma_tf32(float c[4],
                                         uint32_t a0, uint32_t a1, uint32_t a2, uint32_t a3,
                                         uint32_t b0, uint32_t b1)
{
    asm volatile(
        "mma.sync.aligned.m16n8k8.row.col.f32.tf32.tf32.f32 "
        "{%0,%1,%2,%3}, {%4,%5,%6,%7}, {%8,%9}, {%0,%1,%2,%3};\n"
        : "+f"(c[0]), "+f"(c[1]), "+f"(c[2]), "+f"(c[3])
        : "r"(a0), "r"(a1), "r"(a2), "r"(a3), "r"(b0), "r"(b1));
}
__device__ __forceinline__ void cpasync16(uint32_t s, const void* g) {
    asm volatile("cp.async.cg.shared.global [%0], [%1], 16;\n" :: "r"(s), "l"(g));
}
__device__ __forceinline__ void cpasync_commit() {
    asm volatile("cp.async.commit_group;\n");
}
__device__ __forceinline__ void cpasync_wait_all() {
    asm volatile("cp.async.wait_group 0;\n");
}
__device__ __forceinline__ void bar_sync(int id, int cnt) {
    asm volatile("bar.sync %0, %1;" :: "r"(id), "r"(cnt) : "memory");
}
__device__ __forceinline__ void ldsm_x4(uint32_t& r0, uint32_t& r1,
                                        uint32_t& r2, uint32_t& r3, uint32_t addr) {
    asm volatile("ldmatrix.sync.aligned.m8n8.x4.shared.b16 {%0,%1,%2,%3}, [%4];"
                 : "=r"(r0), "=r"(r1), "=r"(r2), "=r"(r3) : "r"(addr));
}
__device__ __forceinline__ void mma_bf16(float c[4],
                                         uint32_t a0, uint32_t a1, uint32_t a2, uint32_t a3,
                                         uint32_t b0, uint32_t b1) {
    asm volatile(
        "mma.sync.aligned.m16n8k16.row.col.f32.bf16.bf16.f32 "
        "{%0,%1,%2,%3}, {%4,%5,%6,%7}, {%8,%9}, {%0,%1,%2,%3};\n"
        : "+f"(c[0]), "+f"(c[1]), "+f"(c[2]), "+f"(c[3])
        : "r"(a0), "r"(a1), "r"(a2), "r"(a3), "r"(b0), "r"(b1));
}

// ---------------------------------------------------------------------------
// Kernel A: projection GEMM (tf32 tensor cores) -> bf16 swizzled q/k arrays
// ---------------------------------------------------------------------------
__global__ void __launch_bounds__(256) proj_tc(const float* __restrict__ X,
                                               const float* __restrict__ W,
                                               const float* __restrict__ bias,
                                               int which)
{
    extern __shared__ uint32_t smemU[];
    uint32_t* As = smemU;               // [128][68]
    uint32_t* Bs = smemU + 128 * 68;    // [64][68]

    const int n0  = blockIdx.x * 64;
    const int m0  = blockIdx.y * 128;
    const int tid = threadIdx.x;
    const int w    = tid >> 5;
    const int lane = tid & 31;

    const int wm = (w & 3) * 32;
    const int wn = (w >> 2) * 32;
    const int qrow = lane >> 2;
    const int qcol = lane & 3;

    float c[2][4][4] = {};

    for (int k0 = 0; k0 < 256; k0 += 64) {
        __syncthreads();
        #pragma unroll
        for (int it = 0; it < 8; ++it) {
            int id = tid + it * 256;
            int r  = id >> 4;
            int q  = id & 15;
            float4 v = *(const float4*)(X + (size_t)(m0 + r) * 256 + k0 + q * 4);
            uint32_t* d = As + r * 68 + q * 4;
            d[0] = f2tf32(v.x); d[1] = f2tf32(v.y); d[2] = f2tf32(v.z); d[3] = f2tf32(v.w);
        }
        #pragma unroll
        for (int it = 0; it < 4; ++it) {
            int id = tid + it * 256;
            int r  = id >> 4;
            int q  = id & 15;
            float4 v = *(const float4*)(W + (size_t)(n0 + r) * 256 + k0 + q * 4);
            uint32_t* d = Bs + r * 68 + q * 4;
            d[0] = f2tf32(v.x); d[1] = f2tf32(v.y); d[2] = f2tf32(v.z); d[3] = f2tf32(v.w);
        }
        __syncthreads();

        const uint32_t* Aw = As + wm * 68;
        const uint32_t* Bw = Bs + wn * 68;
        #pragma unroll
        for (int kk = 0; kk < 8; ++kk) {
            uint32_t a[2][4];
            #pragma unroll
            for (int mt = 0; mt < 2; ++mt) {
                const uint32_t* p = Aw + (mt * 16 + qrow) * 68 + kk * 8 + qcol;
                a[mt][0] = p[0];
                a[mt][1] = p[8 * 68];
                a[mt][2] = p[4];
                a[mt][3] = p[8 * 68 + 4];
            }
            uint32_t b[4][2];
            #pragma unroll
            for (int nt = 0; nt < 4; ++nt) {
                const uint32_t* p = Bw + (nt * 8 + qrow) * 68 + kk * 8 + qcol;
                b[nt][0] = p[0];
                b[nt][1] = p[4];
            }
            #pragma unroll
            for (int mt = 0; mt < 2; ++mt)
                #pragma unroll
                for (int nt = 0; nt < 4; ++nt)
                    mma_tf32(c[mt][nt], a[mt][0], a[mt][1], a[mt][2], a[mt][3],
                             b[nt][0], b[nt][1]);
        }
    }

    const bool isq = (n0 < 256);
    char* arr = which ? (isq ? g_q_vis : g_k_vis) : (isq ? g_q_lang : g_k_lang);

    #pragma unroll
    for (int mt = 0; mt < 2; ++mt) {
        #pragma unroll
        for (int nt = 0; nt < 4; ++nt) {
            const int n  = n0 + wn + nt * 8 + qcol * 2;
            const int cl = n & 255;
            const float b0 = __ldg(bias + n), b1 = __ldg(bias + n + 1);
            const int r0 = m0 + wm + mt * 16 + qrow;
            const int r1 = r0 + 8;
            uint32_t v0 = pack_bf2(c[mt][nt][0] + b0, c[mt][nt][1] + b1);
            uint32_t v1 = pack_bf2(c[mt][nt][2] + b0, c[mt][nt][3] + b1);
            uint32_t o0 = (uint32_t)r0 * 512 + ((((cl >> 3) ^ (r0 & 7)) << 4) | ((cl & 7) << 1));
            uint32_t o1 = (uint32_t)r1 * 512 + ((((cl >> 3) ^ (r1 & 7)) << 4) | ((cl & 7) << 1));
            *(uint32_t*)(arr + o0) = v0;
            *(uint32_t*)(arr + o1) = v1;
        }
    }
}

// ---------------------------------------------------------------------------
// top3 helper
// ---------------------------------------------------------------------------
template<int NB>
__device__ __forceinline__ float top3_sum(const float* v, int lane) {
    float am[NB];
    #pragma unroll
    for (int bi = 0; bi < NB; ++bi) am[bi] = v[bi * 32 + lane];
    unsigned msk = 0; float sum3 = 0.f;
    #pragma unroll
    for (int rr = 0; rr < 3; ++rr) {
        float bv = -1e30f; int bg = lane;
        #pragma unroll
        for (int bi = 0; bi < NB; ++bi)
            if (!((msk >> bi) & 1u) && am[bi] > bv) { bv = am[bi]; bg = (bi << 5) | lane; }
        #pragma unroll
        for (int off = 16; off; off >>= 1) {
            float ov = __shfl_xor_sync(0xffffffffu, bv, off);
            int   og = __shfl_xor_sync(0xffffffffu, bg, off);
            if (ov > bv || (ov == bv && og > bg)) { bv = ov; bg = og; }
        }
        if ((bg & 31) == lane) msk |= 1u << (bg >> 5);
        sum3 += bv;
    }
    return sum3;
}

// ---------------------------------------------------------------------------
// Kernel B1: v2t fused sim (unchanged structure; WR=4, WC=2, HPB=2)
// ---------------------------------------------------------------------------
__global__ void __launch_bounds__(256, 2)
sim_v2t(const char* __restrict__ anch_q,
        const char* __restrict__ targ_k,
        float* __restrict__ part)
{
    constexpr int WC = 2, M = 64, NT = 64, NITER = 8, CPB = 4;
    constexpr int AMS = NT + 4;
    constexpr int OFF_B    = 0;
    constexpr int OFF_A    = OFF_B + NT * 512;
    constexpr int OFF_AM   = OFF_A + M * 512;
    constexpr int OFF_RED  = OFF_AM + M * AMS * 4;
    constexpr int OFF_WACC = OFF_RED + 4 * WC * M * 4;

    extern __shared__ char smem[];
    const uint32_t sbase = (uint32_t)__cvta_generic_to_shared(smem);

    const int j    = blockIdx.x;
    const int z    = blockIdx.y;
    const int tid  = threadIdx.x;
    const int w    = tid >> 5;
    const int lane = tid & 31;

    {
        const char* src = targ_k + (size_t)j * NT * 512;
        #pragma unroll
        for (int id = tid; id < NT * 32; id += 256)
            cpasync16(sbase + OFF_B + id * 16, src + id * 16);
        cpasync_commit();
    }

    const int wm = (w / WC) * 16;
    const int wn = (w % WC) * 32;
    const int wc = w % WC;
    const int l8  = lane & 7;
    const int sub = lane >> 3;
    const int qrow = lane >> 2;
    const int qcol = lane & 3;

    const uint32_t a_base = sbase + OFF_A + (uint32_t)(wm + l8 + (sub & 1) * 8) * 512;
    const int      a_coff = sub >> 1;
    const uint32_t b_base = sbase + OFF_B + (uint32_t)(wn + l8 + ((sub >> 1) & 1) * 8) * 512;
    const int      b_coff = sub & 1;

    float* redf  = (float*)(smem + OFF_RED);
    float* amf   = (float*)(smem + OFF_AM);
    float* waccf = (float*)(smem + OFF_WACC);

    for (int it = 0; it < NITER; ++it) {
        const int cidx = z * NITER + it;

        __syncthreads();
        {
            const char* src = anch_q + (size_t)cidx * M * 512;
            #pragma unroll
            for (int id = tid; id < M * 32; id += 256)
                cpasync16(sbase + OFF_A + id * 16, src + id * 16);
            cpasync_commit();
            cpasync_wait_all();
        }
        __syncthreads();

        float am[4][4];
        #pragma unroll
        for (int nt = 0; nt < 4; ++nt)
            #pragma unroll
            for (int e = 0; e < 4; ++e) am[nt][e] = 0.f;

        #pragma unroll
        for (int hp = 0; hp < 4; hp += 2) {
            float c[2][4][4];
            #pragma unroll
            for (int hh = 0; hh < 2; ++hh)
                #pragma unroll
                for (int nt = 0; nt < 4; ++nt)
                    #pragma unroll
                    for (int e = 0; e < 4; ++e) c[hh][nt][e] = 0.f;

            #pragma unroll
            for (int hh = 0; hh < 2; ++hh) {
                const int h = hp + hh;
                #pragma unroll
                for (int s = 0; s < 4; ++s) {
                    const int cq = h * 8 + s * 2;
                    uint32_t a0, a1, a2, a3, p0, p1, p2, p3, q0, q1, q2, q3;
                    ldsm_x4(a0, a1, a2, a3, a_base + (((cq + a_coff) ^ l8) << 4));
                    ldsm_x4(p0, p1, p2, p3, b_base + (((cq + b_coff) ^ l8) << 4));
                    ldsm_x4(q0, q1, q2, q3, b_base + 16 * 512 + (((cq + b_coff) ^ l8) << 4));
                    mma_bf16(c[hh][0], a0, a1, a2, a3, p0, p1);
                    mma_bf16(c[hh][1], a0, a1, a2, a3, p2, p3);
                    mma_bf16(c[hh][2], a0, a1, a2, a3, q0, q1);
                    mma_bf16(c[hh][3], a0, a1, a2, a3, q2, q3);
                }
            }

            #pragma unroll
            for (int hh = 0; hh < 2; ++hh) {
                const int h = hp + hh;
                float z0 = 0.f, z1 = 0.f;
                #pragma unroll
                for (int nt = 0; nt < 4; ++nt) {
                    c[hh][nt][0] = __expf(c[hh][nt][0] * 0.125f);
                    c[hh][nt][1] = __expf(c[hh][nt][1] * 0.125f);
                    c[hh][nt][2] = __expf(c[hh][nt][2] * 0.125f);
                    c[hh][nt][3] = __expf(c[hh][nt][3] * 0.125f);
                    z0 += c[hh][nt][0] + c[hh][nt][1];
                    z1 += c[hh][nt][2] + c[hh][nt][3];
                }
                z0 += __shfl_xor_sync(0xffffffffu, z0, 1);
                z0 += __shfl_xor_sync(0xffffffffu, z0, 2);
                z1 += __shfl_xor_sync(0xffffffffu, z1, 1);
                z1 += __shfl_xor_sync(0xffffffffu, z1, 2);
                if (qcol == 0) {
                    redf[h * WC * M + wc * M + wm + qrow]     = z0;
                    redf[h * WC * M + wc * M + wm + qrow + 8] = z1;
                }
            }
            __syncthreads();

            float rr[2][2];
            #pragma unroll
            for (int hh = 0; hh < 2; ++hh) {
                const int h = hp + hh;
                #pragma unroll
                for (int rp = 0; rp < 2; ++rp) {
                    float zz = 0.f;
                    #pragma unroll
                    for (int x = 0; x < WC; ++x)
                        zz += redf[h * WC * M + x * M + wm + qrow + rp * 8];
                    rr[hh][rp] = 0.25f / zz;
                }
            }

            #pragma unroll
            for (int nt = 0; nt < 4; ++nt) {
                am[nt][0] += c[0][nt][0] * rr[0][0] + c[1][nt][0] * rr[1][0];
                am[nt][1] += c[0][nt][1] * rr[0][0] + c[1][nt][1] * rr[1][0];
                am[nt][2] += c[0][nt][2] * rr[0][1] + c[1][nt][2] * rr[1][1];
                am[nt][3] += c[0][nt][3] * rr[0][1] + c[1][nt][3] * rr[1][1];
            }
        }

        #pragma unroll
        for (int nt = 0; nt < 4; ++nt) {
            const int colb = wn + nt * 8 + qcol * 2;
            *(float2*)&amf[(wm + qrow)     * AMS + colb] = make_float2(am[nt][0], am[nt][1]);
            *(float2*)&amf[(wm + qrow + 8) * AMS + colb] = make_float2(am[nt][2], am[nt][3]);
        }
        __syncthreads();

        float acc = 0.f;
        #pragma unroll
        for (int r2 = 0; r2 < 8; ++r2)
            acc += top3_sum<2>(&amf[(w * 8 + r2) * AMS], lane);
        if (lane == 0) waccf[w] = acc;
        __syncthreads();
        if (tid == 0) {
            float tot = 0.f;
            #pragma unroll
            for (int x = 0; x < 8; ++x) tot += waccf[x];
            const int i = cidx / CPB, slot = cidx % CPB;
            part[((i * 32 + j) << 2) + slot] = tot;
        }
    }
}

// ---------------------------------------------------------------------------
// Kernel B2: t2v fused sim — 512 thr, TWO independent 256-thread groups
// sharing one B tile. Group g: 8 warps, M=16 anchors, NT=256, HPB=2,
// chunk cidx = (z*NITER+it)*2 + g. All in-loop barriers are group-scoped.
// ---------------------------------------------------------------------------
__global__ void __launch_bounds__(512, 1)
sim_t2v(const char* __restrict__ anch_q,
        const char* __restrict__ targ_k,
        float* __restrict__ part)
{
    constexpr int NT = 256, M = 16, NITER = 8, AMS = NT + 4;
    constexpr int OFF_B    = 0;                    // 256*512 = 131072
    constexpr int OFF_A    = OFF_B + NT * 512;     // 2 x 8192
    constexpr int OFF_AM   = OFF_A + 2 * M * 512;  // 2 x 16640
    constexpr int OFF_RED  = OFF_AM + 2 * M * AMS * 4;  // 2 x 2048
    constexpr int OFF_WACC = OFF_RED + 2 * 4 * 8 * M * 4;

    extern __shared__ char smem[];
    const uint32_t sbase = (uint32_t)__cvta_generic_to_shared(smem);

    const int j    = blockIdx.x;
    const int z    = blockIdx.y;
    const int tid  = threadIdx.x;
    const int w    = tid >> 5;
    const int lane = tid & 31;
    const int g    = w >> 3;        // group 0/1
    const int wg   = w & 7;         // warp-in-group
    const int gt   = tid & 255;     // thread-in-group
    const int barid = 1 + g;

    // ---- B tile: cooperative global load, ONE block-wide sync ----
    {
        const char* src = targ_k + (size_t)j * NT * 512;
        #pragma unroll
        for (int id = tid; id < NT * 32; id += 512)
            cpasync16(sbase + OFF_B + id * 16, src + id * 16);
        cpasync_commit();
        cpasync_wait_all();
    }
    __syncthreads();

    const uint32_t offA = OFF_A + (uint32_t)g * (M * 512);
    const int wn = wg * 32;
    const int l8  = lane & 7;
    const int sub = lane >> 3;
    const int qrow = lane >> 2;
    const int qcol = lane & 3;

    const uint32_t a_base = sbase + offA + (uint32_t)(l8 + (sub & 1) * 8) * 512;
    const int      a_coff = sub >> 1;
    const uint32_t b_base = sbase + OFF_B + (uint32_t)(wn + l8 + ((sub >> 1) & 1) * 8) * 512;
    const int      b_coff = sub & 1;

    float* redf  = (float*)(smem + OFF_RED  + g * (4 * 8 * M * 4));
    float* amf   = (float*)(smem + OFF_AM   + g * (M * AMS * 4));
    float* waccf = (float*)(smem + OFF_WACC + g * 32);

    for (int it = 0; it < NITER; ++it) {
        const int cidx = (z * NITER + it) * 2 + g;

        // ---- A tile (group-local: 16 rows = 512 x 16B) ----
        {
            const char* src = anch_q + (size_t)cidx * M * 512;
            #pragma unroll
            for (int id = gt; id < M * 32; id += 256)
                cpasync16(sbase + offA + id * 16, src + id * 16);
            cpasync_commit();
            cpasync_wait_all();
        }
        bar_sync(barid, 256);

        float am[4][4];
        #pragma unroll
        for (int nt = 0; nt < 4; ++nt)
            #pragma unroll
            for (int e = 0; e < 4; ++e) am[nt][e] = 0.f;

        #pragma unroll
        for (int hp = 0; hp < 4; hp += 2) {
            float c[2][4][4];
            #pragma unroll
            for (int hh = 0; hh < 2; ++hh)
                #pragma unroll
                for (int nt = 0; nt < 4; ++nt)
                    #pragma unroll
                    for (int e = 0; e < 4; ++e) c[hh][nt][e] = 0.f;

            #pragma unroll
            for (int hh = 0; hh < 2; ++hh) {
                const int h = hp + hh;
                #pragma unroll
                for (int s = 0; s < 4; ++s) {
                    const int cq = h * 8 + s * 2;
                    uint32_t a0, a1, a2, a3, p0, p1, p2, p3, q0, q1, q2, q3;
                    ldsm_x4(a0, a1, a2, a3, a_base + (((cq + a_coff) ^ l8) << 4));
                    ldsm_x4(p0, p1, p2, p3, b_base + (((cq + b_coff) ^ l8) << 4));
                    ldsm_x4(q0, q1, q2, q3, b_base + 16 * 512 + (((cq + b_coff) ^ l8) << 4));
                    mma_bf16(c[hh][0], a0, a1, a2, a3, p0, p1);
                    mma_bf16(c[hh][1], a0, a1, a2, a3, p2, p3);
                    mma_bf16(c[hh][2], a0, a1, a2, a3, q0, q1);
                    mma_bf16(c[hh][3], a0, a1, a2, a3, q2, q3);
                }
            }

            #pragma unroll
            for (int hh = 0; hh < 2; ++hh) {
                const int h = hp + hh;
                float z0 = 0.f, z1 = 0.f;
                #pragma unroll
                for (int nt = 0; nt < 4; ++nt) {
                    c[hh][nt][0] = __expf(c[hh][nt][0] * 0.125f);
                    c[hh][nt][1] = __expf(c[hh][nt][1] * 0.125f);
                    c[hh][nt][2] = __expf(c[hh][nt][2] * 0.125f);
                    c[hh][nt][3] = __expf(c[hh][nt][3] * 0.125f);
                    z0 += c[hh][nt][0] + c[hh][nt][1];
                    z1 += c[hh][nt][2] + c[hh][nt][3];
                }
                z0 += __shfl_xor_sync(0xffffffffu, z0, 1);
                z0 += __shfl_xor_sync(0xffffffffu, z0, 2);
                z1 += __shfl_xor_sync(0xffffffffu, z1, 1);
                z1 += __shfl_xor_sync(0xffffffffu, z1, 2);
                if (qcol == 0) {
                    redf[h * 8 * M + wg * M + qrow]     = z0;
                    redf[h * 8 * M + wg * M + qrow + 8] = z1;
                }
            }
            bar_sync(barid, 256);

            float rr[2][2];
            #pragma unroll
            for (int hh = 0; hh < 2; ++hh) {
                const int h = hp + hh;
                #pragma unroll
                for (int rp = 0; rp < 2; ++rp) {
                    float zz = 0.f;
                    #pragma unroll
                    for (int x = 0; x < 8; ++x)
                        zz += redf[h * 8 * M + x * M + qrow + rp * 8];
                    rr[hh][rp] = 0.25f / zz;
                }
            }

            #pragma unroll
            for (int nt = 0; nt < 4; ++nt) {
                am[nt][0] += c[0][nt][0] * rr[0][0] + c[1][nt][0] * rr[1][0];
                am[nt][1] += c[0][nt][1] * rr[0][0] + c[1][nt][1] * rr[1][0];
                am[nt][2] += c[0][nt][2] * rr[0][1] + c[1][nt][2] * rr[1][1];
                am[nt][3] += c[0][nt][3] * rr[0][1] + c[1][nt][3] * rr[1][1];
            }
        }

        // ---- stash am tile (rows 0..15 of this group) ----
        #pragma unroll
        for (int nt = 0; nt < 4; ++nt) {
            const int colb = wn + nt * 8 + qcol * 2;
            *(float2*)&amf[qrow       * AMS + colb] = make_float2(am[nt][0], am[nt][1]);
            *(float2*)&amf[(qrow + 8) * AMS + colb] = make_float2(am[nt][2], am[nt][3]);
        }
        bar_sync(barid, 256);

        // ---- top-3: warp wg handles rows wg*2, wg*2+1 ----
        float acc = 0.f;
        acc += top3_sum<8>(&amf[(wg * 2 + 0) * AMS], lane);
        acc += top3_sum<8>(&amf[(wg * 2 + 1) * AMS], lane);
        if (lane == 0) waccf[wg] = acc;
        bar_sync(barid, 256);
        if (wg == 0 && lane == 0) {
            float tot = 0.f;
            #pragma unroll
            for (int x = 0; x < 8; ++x) tot += waccf[x];
            const int i = cidx >> 2, slot = cidx & 3;
            part[((i * 32 + j) << 2) + slot] = tot;
        }
        bar_sync(barid, 256);   // guard A/am overwrite next iter
    }
}

// ---------------------------------------------------------------------------
// Kernel C: contrastive loss
// ---------------------------------------------------------------------------
__global__ void loss_kernel(const float* __restrict__ part, float* __restrict__ out)
{
    __shared__ float red[64];
    const int t   = threadIdx.x;
    const int dir = t >> 5;
    const int row = t & 31;
    const float* P = part + dir * 4096;
    const float scale = dir ? (100.f / (3.f * 64.f)) : (100.f / (3.f * 256.f));

    float pos = 0.f;
    float t1 = -1e30f, t2 = -1e30f, t3 = -1e30f;
    for (int j = 0; j < 32; ++j) {
        float4 p4 = *(const float4*)&P[(row * 32 + j) << 2];
        float v = (p4.x + p4.y + p4.z + p4.w) * scale;
        if (j == row) { pos = v; continue; }
        if      (v > t1) { t3 = t2; t2 = t1; t1 = v; }
        else if (v > t2) { t3 = t2; t2 = v; }
        else if (v > t3) { t3 = v; }
    }
    const float invT = 1.0f / 0.07f;
    float l0 = pos * invT, l1 = t1 * invT, l2 = t2 * invT, l3 = t3 * invT;
    float m  = fmaxf(fmaxf(l0, l1), fmaxf(l2, l3));
    float Z  = expf(l0 - m) + expf(l1 - m) + expf(l2 - m) + expf(l3 - m);
    red[t] = -(l0 - m - logf(Z));
    __syncthreads();
    if (t == 0) {
        float s0 = 0.f, s1 = 0.f;
        for (int r = 0; r < 32; ++r) { s0 += red[r]; s1 += red[32 + r]; }
        out[0] = 0.5f * (s0 / 32.f) + 0.5f * (s1 / 32.f);
    }
}

// ---------------------------------------------------------------------------
// Launch (fork-join across two streams)
// ---------------------------------------------------------------------------
extern "C" void kernel_launch(void* const* d_in, const int* in_sizes, int n_in,
                              void* d_out, int out_size)
{
    const float* lang = (const float*)d_in[0];
    const float* vis  = (const float*)d_in[1];
    const float* W    = (const float*)d_in[2];
    const float* bias = (const float*)d_in[3];

    const int SM_PROJ = (128 * 68 + 64 * 68) * 4;   // 52,224
    const int SM_V2T = 64*512 + 64*512 + 64*(64+4)*4 + 4*2*64*4 + 8*4;   //  85,024
    const int SM_T2V = 256*512 + 2*16*512 + 2*16*260*4 + 2*4*8*16*4 + 2*32; // 184,960

    static char *p_ql = nullptr, *p_kl = nullptr, *p_qv = nullptr, *p_kv = nullptr;
    static float *p_part = nullptr;
    static cudaStream_t s2;
    static cudaEvent_t evF, evV, evL, evT;
    if (!p_ql) {
        cudaGetSymbolAddress((void**)&p_ql, g_q_lang);
        cudaGetSymbolAddress((void**)&p_kl, g_k_lang);
        cudaGetSymbolAddress((void**)&p_qv, g_q_vis);
        cudaGetSymbolAddress((void**)&p_kv, g_k_vis);
        cudaGetSymbolAddress((void**)&p_part, g_part);
        cudaFuncSetAttribute((const void*)proj_tc,
                             cudaFuncAttributeMaxDynamicSharedMemorySize, SM_PROJ);
        cudaFuncSetAttribute((const void*)sim_v2t,
                             cudaFuncAttributeMaxDynamicSharedMemorySize, SM_V2T);
        cudaFuncSetAttribute((const void*)sim_t2v,
                             cudaFuncAttributeMaxDynamicSharedMemorySize, SM_T2V);
        cudaStreamCreateWithFlags(&s2, cudaStreamNonBlocking);
        cudaEventCreateWithFlags(&evF, cudaEventDisableTiming);
        cudaEventCreateWithFlags(&evV, cudaEventDisableTiming);
        cudaEventCreateWithFlags(&evL, cudaEventDisableTiming);
        cudaEventCreateWithFlags(&evT, cudaEventDisableTiming);
    }

    cudaEventRecord(evF, 0);
    cudaStreamWaitEvent(s2, evF, 0);

    proj_tc<<<dim3(8, 16), 256, SM_PROJ, 0 >>>(lang, W, bias, 0);
    proj_tc<<<dim3(8, 64), 256, SM_PROJ, s2>>>(vis,  W, bias, 1);

    cudaEventRecord(evV, s2);
    cudaStreamWaitEvent(0, evV, 0);
    cudaEventRecord(evL, 0);
    cudaStreamWaitEvent(s2, evL, 0);

    // v2t: anchors = vis q (128 chunks of 64), targets = lang k (NT=64)
    sim_v2t<<<dim3(32, 16), 256, SM_V2T, 0 >>>(p_qv, p_kl, p_part);
    // t2v: anchors = lang q (128 chunks of 16, 2 groups/block), targets = vis k
    sim_t2v<<<dim3(32, 8), 512, SM_T2V, s2>>>(p_ql, p_kv, p_part + 4096);

    cudaEventRecord(evT, s2);
    cudaStreamWaitEvent(0, evT, 0);

    loss_kernel<<<1, 64, 0, 0>>>(p_part, (float*)d_out);
}

// round 11
// speedup vs baseline: 4.4351x; 1.0344x over previous
#include <cuda_runtime.h>
#include <cuda_bf16.h>
#include <math.h>
#include <stdint.h>

// ---------------------------------------------------------------------------
// Scratch (device globals; no allocation allowed)
// q/k stored as bf16 in ldsm-swizzled layout: row stride 512B,
// byte_off(row, col) = row*512 + (((col>>3) ^ (row&7))<<4) + (col&7)*2
// ---------------------------------------------------------------------------
__device__ __align__(16) char g_q_lang[2048 * 512];
__device__ __align__(16) char g_k_lang[2048 * 512];
__device__ __align__(16) char g_q_vis [8192 * 512];
__device__ __align__(16) char g_k_vis [8192 * 512];
__device__ float g_part[2 * 32 * 32 * 8];   // [dir][i][j][slot], zero-init

// ---------------------------------------------------------------------------
// helpers
// ---------------------------------------------------------------------------
__device__ __forceinline__ uint32_t pack_bf2(float a, float b) {
    __nv_bfloat162 t = __floats2bfloat162_rn(a, b);
    return *(uint32_t*)&t;
}
__device__ __forceinline__ uint32_t f2tf32(float v) {
    uint32_t r;
    asm("cvt.rna.tf32.f32 %0, %1;" : "=r"(r) : "f"(v));
    return r;
}
__device__ __forceinline__ void mma_tf32(float c[4],
                                         uint32_t a0, uint32_t a1, uint32_t a2, uint32_t a3,
                                         uint32_t b0, uint32_t b1)
{
    asm volatile(
        "mma.sync.aligned.m16n8k8.row.col.f32.tf32.tf32.f32 "
        "{%0,%1,%2,%3}, {%4,%5,%6,%7}, {%8,%9}, {%0,%1,%2,%3};\n"
        : "+f"(c[0]), "+f"(c[1]), "+f"(c[2]), "+f"(c[3])
        : "r"(a0), "r"(a1), "r"(a2), "r"(a3), "r"(b0), "r"(b1));
}
__device__ __forceinline__ void cpasync16(uint32_t s, const void* g) {
    asm volatile("cp.async.cg.shared.global [%0], [%1], 16;\n" :: "r"(s), "l"(g));
}
__device__ __forceinline__ void cpasync_commit() {
    asm volatile("cp.async.commit_group;\n");
}
__device__ __forceinline__ void cpasync_wait_all() {
    asm volatile("cp.async.wait_group 0;\n");
}
__device__ __forceinline__ void bar_sync(int id, int cnt) {
    asm volatile("bar.sync %0, %1;" :: "r"(id), "r"(cnt) : "memory");
}
__device__ __forceinline__ void ldsm_x4(uint32_t& r0, uint32_t& r1,
                                        uint32_t& r2, uint32_t& r3, uint32_t addr) {
    asm volatile("ldmatrix.sync.aligned.m8n8.x4.shared.b16 {%0,%1,%2,%3}, [%4];"
                 : "=r"(r0), "=r"(r1), "=r"(r2), "=r"(r3) : "r"(addr));
}
__device__ __forceinline__ void mma_bf16(float c[4],
                                         uint32_t a0, uint32_t a1, uint32_t a2, uint32_t a3,
                                         uint32_t b0, uint32_t b1) {
    asm volatile(
        "mma.sync.aligned.m16n8k16.row.col.f32.bf16.bf16.f32 "
        "{%0,%1,%2,%3}, {%4,%5,%6,%7}, {%8,%9}, {%0,%1,%2,%3};\n"
        : "+f"(c[0]), "+f"(c[1]), "+f"(c[2]), "+f"(c[3])
        : "r"(a0), "r"(a1), "r"(a2), "r"(a3), "r"(b0), "r"(b1));
}

// ---------------------------------------------------------------------------
// Kernel A: projection GEMM (tf32) -> bf16 swizzled q/k arrays
// bx0: blockIdx.x offset (allows launching q-half / k-half separately)
// ---------------------------------------------------------------------------
__global__ void __launch_bounds__(256) proj_tc(const float* __restrict__ X,
                                               const float* __restrict__ W,
                                               const float* __restrict__ bias,
                                               int which, int bx0)
{
    extern __shared__ uint32_t smemU[];
    uint32_t* As = smemU;               // [128][68]
    uint32_t* Bs = smemU + 128 * 68;    // [64][68]

    const int n0  = (blockIdx.x + bx0) * 64;
    const int m0  = blockIdx.y * 128;
    const int tid = threadIdx.x;
    const int w    = tid >> 5;
    const int lane = tid & 31;

    const int wm = (w & 3) * 32;
    const int wn = (w >> 2) * 32;
    const int qrow = lane >> 2;
    const int qcol = lane & 3;

    float c[2][4][4] = {};

    for (int k0 = 0; k0 < 256; k0 += 64) {
        __syncthreads();
        #pragma unroll
        for (int it = 0; it < 8; ++it) {
            int id = tid + it * 256;
            int r  = id >> 4;
            int q  = id & 15;
            float4 v = *(const float4*)(X + (size_t)(m0 + r) * 256 + k0 + q * 4);
            uint32_t* d = As + r * 68 + q * 4;
            d[0] = f2tf32(v.x); d[1] = f2tf32(v.y); d[2] = f2tf32(v.z); d[3] = f2tf32(v.w);
        }
        #pragma unroll
        for (int it = 0; it < 4; ++it) {
            int id = tid + it * 256;
            int r  = id >> 4;
            int q  = id & 15;
            float4 v = *(const float4*)(W + (size_t)(n0 + r) * 256 + k0 + q * 4);
            uint32_t* d = Bs + r * 68 + q * 4;
            d[0] = f2tf32(v.x); d[1] = f2tf32(v.y); d[2] = f2tf32(v.z); d[3] = f2tf32(v.w);
        }
        __syncthreads();

        const uint32_t* Aw = As + wm * 68;
        const uint32_t* Bw = Bs + wn * 68;
        #pragma unroll
        for (int kk = 0; kk < 8; ++kk) {
            uint32_t a[2][4];
            #pragma unroll
            for (int mt = 0; mt < 2; ++mt) {
                const uint32_t* p = Aw + (mt * 16 + qrow) * 68 + kk * 8 + qcol;
                a[mt][0] = p[0];
                a[mt][1] = p[8 * 68];
                a[mt][2] = p[4];
                a[mt][3] = p[8 * 68 + 4];
            }
            uint32_t b[4][2];
            #pragma unroll
            for (int nt = 0; nt < 4; ++nt) {
                const uint32_t* p = Bw + (nt * 8 + qrow) * 68 + kk * 8 + qcol;
                b[nt][0] = p[0];
                b[nt][1] = p[4];
            }
            #pragma unroll
            for (int mt = 0; mt < 2; ++mt)
                #pragma unroll
                for (int nt = 0; nt < 4; ++nt)
                    mma_tf32(c[mt][nt], a[mt][0], a[mt][1], a[mt][2], a[mt][3],
                             b[nt][0], b[nt][1]);
        }
    }

    const bool isq = (n0 < 256);
    char* arr = which ? (isq ? g_q_vis : g_k_vis) : (isq ? g_q_lang : g_k_lang);

    #pragma unroll
    for (int mt = 0; mt < 2; ++mt) {
        #pragma unroll
        for (int nt = 0; nt < 4; ++nt) {
            const int n  = n0 + wn + nt * 8 + qcol * 2;
            const int cl = n & 255;
            const float b0 = __ldg(bias + n), b1 = __ldg(bias + n + 1);
            const int r0 = m0 + wm + mt * 16 + qrow;
            const int r1 = r0 + 8;
            uint32_t v0 = pack_bf2(c[mt][nt][0] + b0, c[mt][nt][1] + b1);
            uint32_t v1 = pack_bf2(c[mt][nt][2] + b0, c[mt][nt][3] + b1);
            uint32_t o0 = (uint32_t)r0 * 512 + ((((cl >> 3) ^ (r0 & 7)) << 4) | ((cl & 7) << 1));
            uint32_t o1 = (uint32_t)r1 * 512 + ((((cl >> 3) ^ (r1 & 7)) << 4) | ((cl & 7) << 1));
            *(uint32_t*)(arr + o0) = v0;
            *(uint32_t*)(arr + o1) = v1;
        }
    }
}

// ---------------------------------------------------------------------------
// top3 helper
// ---------------------------------------------------------------------------
template<int NB>
__device__ __forceinline__ float top3_sum(const float* v, int lane) {
    float am[NB];
    #pragma unroll
    for (int bi = 0; bi < NB; ++bi) am[bi] = v[bi * 32 + lane];
    unsigned msk = 0; float sum3 = 0.f;
    #pragma unroll
    for (int rr = 0; rr < 3; ++rr) {
        float bv = -1e30f; int bg = lane;
        #pragma unroll
        for (int bi = 0; bi < NB; ++bi)
            if (!((msk >> bi) & 1u) && am[bi] > bv) { bv = am[bi]; bg = (bi << 5) | lane; }
        #pragma unroll
        for (int off = 16; off; off >>= 1) {
            float ov = __shfl_xor_sync(0xffffffffu, bv, off);
            int   og = __shfl_xor_sync(0xffffffffu, bg, off);
            if (ov > bv || (ov == bv && og > bg)) { bv = ov; bg = og; }
        }
        if ((bg & 31) == lane) msk |= 1u << (bg >> 5);
        sum3 += bv;
    }
    return sum3;
}

// ---------------------------------------------------------------------------
// Kernel B1: v2t fused sim — re-tiled for occupancy.
// WR=2, WC=4: M=32 anchors/iter, NT=64 targets, warp n-tile 16 (2 mma-n8).
// 256 thr, target 3 CTAs/SM. NITER=16, chunks of 32 -> 8 slots/batch-pair.
// ---------------------------------------------------------------------------
__global__ void __launch_bounds__(256, 3)
sim_v2t(const char* __restrict__ anch_q,
        const char* __restrict__ targ_k,
        float* __restrict__ part)
{
    constexpr int WC = 4, M = 32, NT = 64, NITER = 16;
    constexpr int AMS = NT + 4;
    constexpr int OFF_B    = 0;                      // 64*512  = 32768
    constexpr int OFF_A    = OFF_B + NT * 512;       // 32*512  = 16384
    constexpr int OFF_AM   = OFF_A + M * 512;        // 32*68*4 = 8704
    constexpr int OFF_RED  = OFF_AM + M * AMS * 4;   // 4*4*32*4= 2048
    constexpr int OFF_WACC = OFF_RED + 4 * WC * M * 4;

    extern __shared__ char smem[];
    const uint32_t sbase = (uint32_t)__cvta_generic_to_shared(smem);

    const int j    = blockIdx.x;
    const int z    = blockIdx.y;
    const int tid  = threadIdx.x;
    const int w    = tid >> 5;
    const int lane = tid & 31;

    {
        const char* src = targ_k + (size_t)j * NT * 512;
        #pragma unroll
        for (int id = tid; id < NT * 32; id += 256)
            cpasync16(sbase + OFF_B + id * 16, src + id * 16);
        cpasync_commit();
    }

    const int wm = (w >> 2) * 16;     // 0 or 16
    const int wn = (w & 3) * 16;      // 0,16,32,48
    const int wc = w & 3;
    const int l8  = lane & 7;
    const int sub = lane >> 3;
    const int qrow = lane >> 2;
    const int qcol = lane & 3;

    const uint32_t a_base = sbase + OFF_A + (uint32_t)(wm + l8 + (sub & 1) * 8) * 512;
    const int      a_coff = sub >> 1;
    const uint32_t b_base = sbase + OFF_B + (uint32_t)(wn + l8 + ((sub >> 1) & 1) * 8) * 512;
    const int      b_coff = sub & 1;

    float* redf  = (float*)(smem + OFF_RED);
    float* amf   = (float*)(smem + OFF_AM);
    float* waccf = (float*)(smem + OFF_WACC);

    for (int it = 0; it < NITER; ++it) {
        const int cidx = z * NITER + it;

        __syncthreads();
        {
            const char* src = anch_q + (size_t)cidx * M * 512;
            #pragma unroll
            for (int id = tid; id < M * 32; id += 256)
                cpasync16(sbase + OFF_A + id * 16, src + id * 16);
            cpasync_commit();
            cpasync_wait_all();
        }
        __syncthreads();

        float am[2][4];
        #pragma unroll
        for (int nt = 0; nt < 2; ++nt)
            #pragma unroll
            for (int e = 0; e < 4; ++e) am[nt][e] = 0.f;

        #pragma unroll
        for (int hp = 0; hp < 4; hp += 2) {
            float c[2][2][4];
            #pragma unroll
            for (int hh = 0; hh < 2; ++hh)
                #pragma unroll
                for (int nt = 0; nt < 2; ++nt)
                    #pragma unroll
                    for (int e = 0; e < 4; ++e) c[hh][nt][e] = 0.f;

            #pragma unroll
            for (int hh = 0; hh < 2; ++hh) {
                const int h = hp + hh;
                #pragma unroll
                for (int s = 0; s < 4; ++s) {
                    const int cq = h * 8 + s * 2;
                    uint32_t a0, a1, a2, a3, p0, p1, p2, p3;
                    ldsm_x4(a0, a1, a2, a3, a_base + (((cq + a_coff) ^ l8) << 4));
                    ldsm_x4(p0, p1, p2, p3, b_base + (((cq + b_coff) ^ l8) << 4));
                    mma_bf16(c[hh][0], a0, a1, a2, a3, p0, p1);
                    mma_bf16(c[hh][1], a0, a1, a2, a3, p2, p3);
                }
            }

            #pragma unroll
            for (int hh = 0; hh < 2; ++hh) {
                const int h = hp + hh;
                float z0 = 0.f, z1 = 0.f;
                #pragma unroll
                for (int nt = 0; nt < 2; ++nt) {
                    c[hh][nt][0] = __expf(c[hh][nt][0] * 0.125f);
                    c[hh][nt][1] = __expf(c[hh][nt][1] * 0.125f);
                    c[hh][nt][2] = __expf(c[hh][nt][2] * 0.125f);
                    c[hh][nt][3] = __expf(c[hh][nt][3] * 0.125f);
                    z0 += c[hh][nt][0] + c[hh][nt][1];
                    z1 += c[hh][nt][2] + c[hh][nt][3];
                }
                z0 += __shfl_xor_sync(0xffffffffu, z0, 1);
                z0 += __shfl_xor_sync(0xffffffffu, z0, 2);
                z1 += __shfl_xor_sync(0xffffffffu, z1, 1);
                z1 += __shfl_xor_sync(0xffffffffu, z1, 2);
                if (qcol == 0) {
                    redf[h * WC * M + wc * M + wm + qrow]     = z0;
                    redf[h * WC * M + wc * M + wm + qrow + 8] = z1;
                }
            }
            __syncthreads();

            float rr[2][2];
            #pragma unroll
            for (int hh = 0; hh < 2; ++hh) {
                const int h = hp + hh;
                #pragma unroll
                for (int rp = 0; rp < 2; ++rp) {
                    float zz = 0.f;
                    #pragma unroll
                    for (int x = 0; x < WC; ++x)
                        zz += redf[h * WC * M + x * M + wm + qrow + rp * 8];
                    rr[hh][rp] = 0.25f / zz;
                }
            }

            #pragma unroll
            for (int nt = 0; nt < 2; ++nt) {
                am[nt][0] += c[0][nt][0] * rr[0][0] + c[1][nt][0] * rr[1][0];
                am[nt][1] += c[0][nt][1] * rr[0][0] + c[1][nt][1] * rr[1][0];
                am[nt][2] += c[0][nt][2] * rr[0][1] + c[1][nt][2] * rr[1][1];
                am[nt][3] += c[0][nt][3] * rr[0][1] + c[1][nt][3] * rr[1][1];
            }
        }

        #pragma unroll
        for (int nt = 0; nt < 2; ++nt) {
            const int colb = wn + nt * 8 + qcol * 2;
            *(float2*)&amf[(wm + qrow)     * AMS + colb] = make_float2(am[nt][0], am[nt][1]);
            *(float2*)&amf[(wm + qrow + 8) * AMS + colb] = make_float2(am[nt][2], am[nt][3]);
        }
        __syncthreads();

        // top-3: warp w handles rows w*4 .. w*4+3
        float acc = 0.f;
        #pragma unroll
        for (int r2 = 0; r2 < 4; ++r2)
            acc += top3_sum<2>(&amf[(w * 4 + r2) * AMS], lane);
        if (lane == 0) waccf[w] = acc;
        __syncthreads();
        if (tid == 0) {
            float tot = 0.f;
            #pragma unroll
            for (int x = 0; x < 8; ++x) tot += waccf[x];
            const int i = cidx >> 3, slot = cidx & 7;
            part[((i * 32 + j) << 3) + slot] = tot;
        }
    }
}

// ---------------------------------------------------------------------------
// Kernel B2: t2v fused sim — 512 thr, two 256-thread groups (unchanged)
// ---------------------------------------------------------------------------
__global__ void __launch_bounds__(512, 1)
sim_t2v(const char* __restrict__ anch_q,
        const char* __restrict__ targ_k,
        float* __restrict__ part)
{
    constexpr int NT = 256, M = 16, NITER = 8, AMS = NT + 4;
    constexpr int OFF_B    = 0;
    constexpr int OFF_A    = OFF_B + NT * 512;
    constexpr int OFF_AM   = OFF_A + 2 * M * 512;
    constexpr int OFF_RED  = OFF_AM + 2 * M * AMS * 4;
    constexpr int OFF_WACC = OFF_RED + 2 * 4 * 8 * M * 4;

    extern __shared__ char smem[];
    const uint32_t sbase = (uint32_t)__cvta_generic_to_shared(smem);

    const int j    = blockIdx.x;
    const int z    = blockIdx.y;
    const int tid  = threadIdx.x;
    const int w    = tid >> 5;
    const int lane = tid & 31;
    const int g    = w >> 3;
    const int wg   = w & 7;
    const int gt   = tid & 255;
    const int barid = 1 + g;

    {
        const char* src = targ_k + (size_t)j * NT * 512;
        #pragma unroll
        for (int id = tid; id < NT * 32; id += 512)
            cpasync16(sbase + OFF_B + id * 16, src + id * 16);
        cpasync_commit();
        cpasync_wait_all();
    }
    __syncthreads();

    const uint32_t offA = OFF_A + (uint32_t)g * (M * 512);
    const int wn = wg * 32;
    const int l8  = lane & 7;
    const int sub = lane >> 3;
    const int qrow = lane >> 2;
    const int qcol = lane & 3;

    const uint32_t a_base = sbase + offA + (uint32_t)(l8 + (sub & 1) * 8) * 512;
    const int      a_coff = sub >> 1;
    const uint32_t b_base = sbase + OFF_B + (uint32_t)(wn + l8 + ((sub >> 1) & 1) * 8) * 512;
    const int      b_coff = sub & 1;

    float* redf  = (float*)(smem + OFF_RED  + g * (4 * 8 * M * 4));
    float* amf   = (float*)(smem + OFF_AM   + g * (M * AMS * 4));
    float* waccf = (float*)(smem + OFF_WACC + g * 32);

    for (int it = 0; it < NITER; ++it) {
        const int cidx = (z * NITER + it) * 2 + g;

        {
            const char* src = anch_q + (size_t)cidx * M * 512;
            #pragma unroll
            for (int id = gt; id < M * 32; id += 256)
                cpasync16(sbase + offA + id * 16, src + id * 16);
            cpasync_commit();
            cpasync_wait_all();
        }
        bar_sync(barid, 256);

        float am[4][4];
        #pragma unroll
        for (int nt = 0; nt < 4; ++nt)
            #pragma unroll
            for (int e = 0; e < 4; ++e) am[nt][e] = 0.f;

        #pragma unroll
        for (int hp = 0; hp < 4; hp += 2) {
            float c[2][4][4];
            #pragma unroll
            for (int hh = 0; hh < 2; ++hh)
                #pragma unroll
                for (int nt = 0; nt < 4; ++nt)
                    #pragma unroll
                    for (int e = 0; e < 4; ++e) c[hh][nt][e] = 0.f;

            #pragma unroll
            for (int hh = 0; hh < 2; ++hh) {
                const int h = hp + hh;
                #pragma unroll
                for (int s = 0; s < 4; ++s) {
                    const int cq = h * 8 + s * 2;
                    uint32_t a0, a1, a2, a3, p0, p1, p2, p3, q0, q1, q2, q3;
                    ldsm_x4(a0, a1, a2, a3, a_base + (((cq + a_coff) ^ l8) << 4));
                    ldsm_x4(p0, p1, p2, p3, b_base + (((cq + b_coff) ^ l8) << 4));
                    ldsm_x4(q0, q1, q2, q3, b_base + 16 * 512 + (((cq + b_coff) ^ l8) << 4));
                    mma_bf16(c[hh][0], a0, a1, a2, a3, p0, p1);
                    mma_bf16(c[hh][1], a0, a1, a2, a3, p2, p3);
                    mma_bf16(c[hh][2], a0, a1, a2, a3, q0, q1);
                    mma_bf16(c[hh][3], a0, a1, a2, a3, q2, q3);
                }
            }

            #pragma unroll
            for (int hh = 0; hh < 2; ++hh) {
                const int h = hp + hh;
                float z0 = 0.f, z1 = 0.f;
                #pragma unroll
                for (int nt = 0; nt < 4; ++nt) {
                    c[hh][nt][0] = __expf(c[hh][nt][0] * 0.125f);
                    c[hh][nt][1] = __expf(c[hh][nt][1] * 0.125f);
                    c[hh][nt][2] = __expf(c[hh][nt][2] * 0.125f);
                    c[hh][nt][3] = __expf(c[hh][nt][3] * 0.125f);
                    z0 += c[hh][nt][0] + c[hh][nt][1];
                    z1 += c[hh][nt][2] + c[hh][nt][3];
                }
                z0 += __shfl_xor_sync(0xffffffffu, z0, 1);
                z0 += __shfl_xor_sync(0xffffffffu, z0, 2);
                z1 += __shfl_xor_sync(0xffffffffu, z1, 1);
                z1 += __shfl_xor_sync(0xffffffffu, z1, 2);
                if (qcol == 0) {
                    redf[h * 8 * M + wg * M + qrow]     = z0;
                    redf[h * 8 * M + wg * M + qrow + 8] = z1;
                }
            }
            bar_sync(barid, 256);

            float rr[2][2];
            #pragma unroll
            for (int hh = 0; hh < 2; ++hh) {
                const int h = hp + hh;
                #pragma unroll
                for (int rp = 0; rp < 2; ++rp) {
                    float zz = 0.f;
                    #pragma unroll
                    for (int x = 0; x < 8; ++x)
                        zz += redf[h * 8 * M + x * M + qrow + rp * 8];
                    rr[hh][rp] = 0.25f / zz;
                }
            }

            #pragma unroll
            for (int nt = 0; nt < 4; ++nt) {
                am[nt][0] += c[0][nt][0] * rr[0][0] + c[1][nt][0] * rr[1][0];
                am[nt][1] += c[0][nt][1] * rr[0][0] + c[1][nt][1] * rr[1][0];
                am[nt][2] += c[0][nt][2] * rr[0][1] + c[1][nt][2] * rr[1][1];
                am[nt][3] += c[0][nt][3] * rr[0][1] + c[1][nt][3] * rr[1][1];
            }
        }

        #pragma unroll
        for (int nt = 0; nt < 4; ++nt) {
            const int colb = wn + nt * 8 + qcol * 2;
            *(float2*)&amf[qrow       * AMS + colb] = make_float2(am[nt][0], am[nt][1]);
            *(float2*)&amf[(qrow + 8) * AMS + colb] = make_float2(am[nt][2], am[nt][3]);
        }
        bar_sync(barid, 256);

        float acc = 0.f;
        acc += top3_sum<8>(&amf[(wg * 2 + 0) * AMS], lane);
        acc += top3_sum<8>(&amf[(wg * 2 + 1) * AMS], lane);
        if (lane == 0) waccf[wg] = acc;
        bar_sync(barid, 256);
        if (wg == 0 && lane == 0) {
            float tot = 0.f;
            #pragma unroll
            for (int x = 0; x < 8; ++x) tot += waccf[x];
            const int i = cidx >> 2, slot = cidx & 3;
            part[((i * 32 + j) << 3) + slot] = tot;
        }
        bar_sync(barid, 256);
    }
}

// ---------------------------------------------------------------------------
// Kernel C: contrastive loss (8 slots per pair; unused slots stay zero)
// ---------------------------------------------------------------------------
__global__ void loss_kernel(const float* __restrict__ part, float* __restrict__ out)
{
    __shared__ float red[64];
    const int t   = threadIdx.x;
    const int dir = t >> 5;
    const int row = t & 31;
    const float* P = part + dir * 8192;
    const float scale = dir ? (100.f / (3.f * 64.f)) : (100.f / (3.f * 256.f));

    float pos = 0.f;
    float t1 = -1e30f, t2 = -1e30f, t3 = -1e30f;
    for (int j = 0; j < 32; ++j) {
        const float* q = &P[(row * 32 + j) << 3];
        float4 a = *(const float4*)q;
        float4 b = *(const float4*)(q + 4);
        float v = (a.x + a.y + a.z + a.w + b.x + b.y + b.z + b.w) * scale;
        if (j == row) { pos = v; continue; }
        if      (v > t1) { t3 = t2; t2 = t1; t1 = v; }
        else if (v > t2) { t3 = t2; t2 = v; }
        else if (v > t3) { t3 = v; }
    }
    const float invT = 1.0f / 0.07f;
    float l0 = pos * invT, l1 = t1 * invT, l2 = t2 * invT, l3 = t3 * invT;
    float m  = fmaxf(fmaxf(l0, l1), fmaxf(l2, l3));
    float Z  = expf(l0 - m) + expf(l1 - m) + expf(l2 - m) + expf(l3 - m);
    red[t] = -(l0 - m - logf(Z));
    __syncthreads();
    if (t == 0) {
        float s0 = 0.f, s1 = 0.f;
        for (int r = 0; r < 32; ++r) { s0 += red[r]; s1 += red[32 + r]; }
        out[0] = 0.5f * (s0 / 32.f) + 0.5f * (s1 / 32.f);
    }
}

// ---------------------------------------------------------------------------
// Launch: critical-path shaping. t2v needs {q_lang, k_vis}; v2t needs
// {k_lang, q_vis}. Split proj_vis into k-half (feeds t2v early) and q-half.
// ---------------------------------------------------------------------------
extern "C" void kernel_launch(void* const* d_in, const int* in_sizes, int n_in,
                              void* d_out, int out_size)
{
    const float* lang = (const float*)d_in[0];
    const float* vis  = (const float*)d_in[1];
    const float* W    = (const float*)d_in[2];
    const float* bias = (const float*)d_in[3];

    const int SM_PROJ = (128 * 68 + 64 * 68) * 4;   // 52,224
    const int SM_V2T  = 64*512 + 32*512 + 32*68*4 + 4*4*32*4 + 32;          //  59,968
    const int SM_T2V  = 256*512 + 2*16*512 + 2*16*260*4 + 2*4*8*16*4 + 64;  // 184,960

    static char *p_ql = nullptr, *p_kl = nullptr, *p_qv = nullptr, *p_kv = nullptr;
    static float *p_part = nullptr;
    static cudaStream_t s2;
    static cudaEvent_t evF, evLang, evT;
    if (!p_ql) {
        cudaGetSymbolAddress((void**)&p_ql, g_q_lang);
        cudaGetSymbolAddress((void**)&p_kl, g_k_lang);
        cudaGetSymbolAddress((void**)&p_qv, g_q_vis);
        cudaGetSymbolAddress((void**)&p_kv, g_k_vis);
        cudaGetSymbolAddress((void**)&p_part, g_part);
        cudaFuncSetAttribute((const void*)proj_tc,
                             cudaFuncAttributeMaxDynamicSharedMemorySize, SM_PROJ);
        cudaFuncSetAttribute((const void*)sim_v2t,
                             cudaFuncAttributeMaxDynamicSharedMemorySize, SM_V2T);
        cudaFuncSetAttribute((const void*)sim_t2v,
                             cudaFuncAttributeMaxDynamicSharedMemorySize, SM_T2V);
        cudaStreamCreateWithFlags(&s2, cudaStreamNonBlocking);
        cudaEventCreateWithFlags(&evF,    cudaEventDisableTiming);
        cudaEventCreateWithFlags(&evLang, cudaEventDisableTiming);
        cudaEventCreateWithFlags(&evT,    cudaEventDisableTiming);
    }

    // fork s2 into the captured graph
    cudaEventRecord(evF, 0);
    cudaStreamWaitEvent(s2, evF, 0);

    // s2: k-half of vis projection, then t2v (the long pole) ASAP
    proj_tc<<<dim3(4, 64), 256, SM_PROJ, s2>>>(vis, W, bias, 1, 4);   // k_vis

    // s0: lang projection (q_lang + k_lang), then q-half of vis
    proj_tc<<<dim3(8, 16), 256, SM_PROJ, 0>>>(lang, W, bias, 0, 0);   // q/k_lang
    cudaEventRecord(evLang, 0);
    proj_tc<<<dim3(4, 64), 256, SM_PROJ, 0>>>(vis, W, bias, 1, 0);    // q_vis

    // t2v: waits k_vis (s2 order) + q_lang (evLang)
    cudaStreamWaitEvent(s2, evLang, 0);
    sim_t2v<<<dim3(32, 8), 512, SM_T2V, s2>>>(p_ql, p_kv, p_part + 8192);

    // v2t: deps (k_lang, q_vis) are both earlier in s0
    sim_v2t<<<dim3(32, 16), 256, SM_V2T, 0>>>(p_qv, p_kl, p_part);

    // join before loss
    cudaEventRecord(evT, s2);
    cudaStreamWaitEvent(0, evT, 0);

    loss_kernel<<<1, 64, 0, 0>>>(p_part, (float*)d_out);
}

// round 12
// speedup vs baseline: 4.5709x; 1.0306x over previous
#include <cuda_runtime.h>
#include <cuda_bf16.h>
#include <math.h>
#include <stdint.h>

// ---------------------------------------------------------------------------
// Scratch (device globals; no allocation allowed)
// q/k stored as fp8 e4m3 in ldsm-swizzled layout: row stride 256B,
// byte_off(row, col) = row*256 + (((col>>4) ^ (row&7))<<4) + (col&15)
// ---------------------------------------------------------------------------
__device__ __align__(16) char g_q_lang[2048 * 256];
__device__ __align__(16) char g_k_lang[2048 * 256];
__device__ __align__(16) char g_q_vis [8192 * 256];
__device__ __align__(16) char g_k_vis [8192 * 256];
__device__ float g_part[2 * 32 * 32 * 8];   // [dir][i][j][slot], zero-init

// ---------------------------------------------------------------------------
// helpers
// ---------------------------------------------------------------------------
__device__ __forceinline__ uint16_t pack_fp8x2(float lo, float hi) {
    uint16_t r;
    asm("cvt.rn.satfinite.e4m3x2.f32 %0, %1, %2;" : "=h"(r) : "f"(hi), "f"(lo));
    return r;
}
__device__ __forceinline__ uint32_t f2tf32(float v) {
    uint32_t r;
    asm("cvt.rna.tf32.f32 %0, %1;" : "=r"(r) : "f"(v));
    return r;
}
__device__ __forceinline__ void mma_tf32(float c[4],
                                         uint32_t a0, uint32_t a1, uint32_t a2, uint32_t a3,
                                         uint32_t b0, uint32_t b1)
{
    asm volatile(
        "mma.sync.aligned.m16n8k8.row.col.f32.tf32.tf32.f32 "
        "{%0,%1,%2,%3}, {%4,%5,%6,%7}, {%8,%9}, {%0,%1,%2,%3};\n"
        : "+f"(c[0]), "+f"(c[1]), "+f"(c[2]), "+f"(c[3])
        : "r"(a0), "r"(a1), "r"(a2), "r"(a3), "r"(b0), "r"(b1));
}
__device__ __forceinline__ void cpasync16(uint32_t s, const void* g) {
    asm volatile("cp.async.cg.shared.global [%0], [%1], 16;\n" :: "r"(s), "l"(g));
}
__device__ __forceinline__ void cpasync_commit() {
    asm volatile("cp.async.commit_group;\n");
}
__device__ __forceinline__ void cpasync_wait_all() {
    asm volatile("cp.async.wait_group 0;\n");
}
__device__ __forceinline__ void ldsm_x4(uint32_t& r0, uint32_t& r1,
                                        uint32_t& r2, uint32_t& r3, uint32_t addr) {
    asm volatile("ldmatrix.sync.aligned.m8n8.x4.shared.b16 {%0,%1,%2,%3}, [%4];"
                 : "=r"(r0), "=r"(r1), "=r"(r2), "=r"(r3) : "r"(addr));
}
__device__ __forceinline__ void mma_fp8(float c[4],
                                        uint32_t a0, uint32_t a1, uint32_t a2, uint32_t a3,
                                        uint32_t b0, uint32_t b1) {
    asm volatile(
        "mma.sync.aligned.m16n8k32.row.col.f32.e4m3.e4m3.f32 "
        "{%0,%1,%2,%3}, {%4,%5,%6,%7}, {%8,%9}, {%0,%1,%2,%3};\n"
        : "+f"(c[0]), "+f"(c[1]), "+f"(c[2]), "+f"(c[3])
        : "r"(a0), "r"(a1), "r"(a2), "r"(a3), "r"(b0), "r"(b1));
}

// ---------------------------------------------------------------------------
// Kernel A: projection GEMM (tf32) -> fp8 swizzled q/k arrays
// bx0: blockIdx.x offset (q-half / k-half split launches)
// ---------------------------------------------------------------------------
__global__ void __launch_bounds__(256) proj_tc(const float* __restrict__ X,
                                               const float* __restrict__ W,
                                               const float* __restrict__ bias,
                                               int which, int bx0)
{
    extern __shared__ uint32_t smemU[];
    uint32_t* As = smemU;               // [128][68]
    uint32_t* Bs = smemU + 128 * 68;    // [64][68]

    const int n0  = (blockIdx.x + bx0) * 64;
    const int m0  = blockIdx.y * 128;
    const int tid = threadIdx.x;
    const int w    = tid >> 5;
    const int lane = tid & 31;

    const int wm = (w & 3) * 32;
    const int wn = (w >> 2) * 32;
    const int qrow = lane >> 2;
    const int qcol = lane & 3;

    float c[2][4][4] = {};

    for (int k0 = 0; k0 < 256; k0 += 64) {
        __syncthreads();
        #pragma unroll
        for (int it = 0; it < 8; ++it) {
            int id = tid + it * 256;
            int r  = id >> 4;
            int q  = id & 15;
            float4 v = *(const float4*)(X + (size_t)(m0 + r) * 256 + k0 + q * 4);
            uint32_t* d = As + r * 68 + q * 4;
            d[0] = f2tf32(v.x); d[1] = f2tf32(v.y); d[2] = f2tf32(v.z); d[3] = f2tf32(v.w);
        }
        #pragma unroll
        for (int it = 0; it < 4; ++it) {
            int id = tid + it * 256;
            int r  = id >> 4;
            int q  = id & 15;
            float4 v = *(const float4*)(W + (size_t)(n0 + r) * 256 + k0 + q * 4);
            uint32_t* d = Bs + r * 68 + q * 4;
            d[0] = f2tf32(v.x); d[1] = f2tf32(v.y); d[2] = f2tf32(v.z); d[3] = f2tf32(v.w);
        }
        __syncthreads();

        const uint32_t* Aw = As + wm * 68;
        const uint32_t* Bw = Bs + wn * 68;
        #pragma unroll
        for (int kk = 0; kk < 8; ++kk) {
            uint32_t a[2][4];
            #pragma unroll
            for (int mt = 0; mt < 2; ++mt) {
                const uint32_t* p = Aw + (mt * 16 + qrow) * 68 + kk * 8 + qcol;
                a[mt][0] = p[0];
                a[mt][1] = p[8 * 68];
                a[mt][2] = p[4];
                a[mt][3] = p[8 * 68 + 4];
            }
            uint32_t b[4][2];
            #pragma unroll
            for (int nt = 0; nt < 4; ++nt) {
                const uint32_t* p = Bw + (nt * 8 + qrow) * 68 + kk * 8 + qcol;
                b[nt][0] = p[0];
                b[nt][1] = p[4];
            }
            #pragma unroll
            for (int mt = 0; mt < 2; ++mt)
                #pragma unroll
                for (int nt = 0; nt < 4; ++nt)
                    mma_tf32(c[mt][nt], a[mt][0], a[mt][1], a[mt][2], a[mt][3],
                             b[nt][0], b[nt][1]);
        }
    }

    const bool isq = (n0 < 256);
    char* arr = which ? (isq ? g_q_vis : g_k_vis) : (isq ? g_q_lang : g_k_lang);

    #pragma unroll
    for (int mt = 0; mt < 2; ++mt) {
        #pragma unroll
        for (int nt = 0; nt < 4; ++nt) {
            const int n  = n0 + wn + nt * 8 + qcol * 2;
            const int cl = n & 255;
            const float b0 = __ldg(bias + n), b1 = __ldg(bias + n + 1);
            const int r0 = m0 + wm + mt * 16 + qrow;
            const int r1 = r0 + 8;
            uint16_t v0 = pack_fp8x2(c[mt][nt][0] + b0, c[mt][nt][1] + b1);
            uint16_t v1 = pack_fp8x2(c[mt][nt][2] + b0, c[mt][nt][3] + b1);
            uint32_t o0 = (uint32_t)r0 * 256 + ((((cl >> 4) ^ (r0 & 7)) << 4) | (cl & 15));
            uint32_t o1 = (uint32_t)r1 * 256 + ((((cl >> 4) ^ (r1 & 7)) << 4) | (cl & 15));
            *(uint16_t*)(arr + o0) = v0;
            *(uint16_t*)(arr + o1) = v1;
        }
    }
}

// ---------------------------------------------------------------------------
// top3 helper
// ---------------------------------------------------------------------------
template<int NB>
__device__ __forceinline__ float top3_sum(const float* v, int lane) {
    float am[NB];
    #pragma unroll
    for (int bi = 0; bi < NB; ++bi) am[bi] = v[bi * 32 + lane];
    unsigned msk = 0; float sum3 = 0.f;
    #pragma unroll
    for (int rr = 0; rr < 3; ++rr) {
        float bv = -1e30f; int bg = lane;
        #pragma unroll
        for (int bi = 0; bi < NB; ++bi)
            if (!((msk >> bi) & 1u) && am[bi] > bv) { bv = am[bi]; bg = (bi << 5) | lane; }
        #pragma unroll
        for (int off = 16; off; off >>= 1) {
            float ov = __shfl_xor_sync(0xffffffffu, bv, off);
            int   og = __shfl_xor_sync(0xffffffffu, bg, off);
            if (ov > bv || (ov == bv && og > bg)) { bv = ov; bg = og; }
        }
        if ((bg & 31) == lane) msk |= 1u << (bg >> 5);
        sum3 += bv;
    }
    return sum3;
}

// ---------------------------------------------------------------------------
// Kernel B1: v2t fused sim (fp8 scores). WR=2, WC=4: M=32, NT=64.
// 256 thr, 3 CTAs/SM. NITER=16, 8 slots/batch-pair.
// ---------------------------------------------------------------------------
__global__ void __launch_bounds__(256, 3)
sim_v2t(const char* __restrict__ anch_q,
        const char* __restrict__ targ_k,
        float* __restrict__ part)
{
    constexpr int WC = 4, M = 32, NT = 64, NITER = 16;
    constexpr int AMS = NT + 4;
    constexpr int OFF_B    = 0;                      // 64*256  = 16384
    constexpr int OFF_A    = OFF_B + NT * 256;       // 32*256  = 8192
    constexpr int OFF_AM   = OFF_A + M * 256;        // 32*68*4 = 8704
    constexpr int OFF_RED  = OFF_AM + M * AMS * 4;   // 2048
    constexpr int OFF_WACC = OFF_RED + 4 * WC * M * 4;

    extern __shared__ char smem[];
    const uint32_t sbase = (uint32_t)__cvta_generic_to_shared(smem);

    const int j    = blockIdx.x;
    const int z    = blockIdx.y;
    const int tid  = threadIdx.x;
    const int w    = tid >> 5;
    const int lane = tid & 31;

    {
        const char* src = targ_k + (size_t)j * NT * 256;
        #pragma unroll
        for (int id = tid; id < NT * 16; id += 256)
            cpasync16(sbase + OFF_B + id * 16, src + id * 16);
        cpasync_commit();
    }

    const int wm = (w >> 2) * 16;     // 0 or 16
    const int wn = (w & 3) * 16;      // 0,16,32,48
    const int wc = w & 3;
    const int l8  = lane & 7;
    const int sub = lane >> 3;
    const int qrow = lane >> 2;
    const int qcol = lane & 3;

    const uint32_t a_base = sbase + OFF_A + (uint32_t)(wm + l8 + (sub & 1) * 8) * 256;
    const int      a_coff = sub >> 1;
    const uint32_t b_base = sbase + OFF_B + (uint32_t)(wn + l8 + ((sub >> 1) & 1) * 8) * 256;
    const int      b_coff = sub & 1;

    float* redf  = (float*)(smem + OFF_RED);
    float* amf   = (float*)(smem + OFF_AM);
    float* waccf = (float*)(smem + OFF_WACC);

    for (int it = 0; it < NITER; ++it) {
        const int cidx = z * NITER + it;

        __syncthreads();
        {
            const char* src = anch_q + (size_t)cidx * M * 256;
            #pragma unroll
            for (int id = tid; id < M * 16; id += 256)
                cpasync16(sbase + OFF_A + id * 16, src + id * 16);
            cpasync_commit();
            cpasync_wait_all();
        }
        __syncthreads();

        float am[2][4];
        #pragma unroll
        for (int nt = 0; nt < 2; ++nt)
            #pragma unroll
            for (int e = 0; e < 4; ++e) am[nt][e] = 0.f;

        #pragma unroll
        for (int hp = 0; hp < 4; hp += 2) {
            float c[2][2][4];
            #pragma unroll
            for (int hh = 0; hh < 2; ++hh)
                #pragma unroll
                for (int nt = 0; nt < 2; ++nt)
                    #pragma unroll
                    for (int e = 0; e < 4; ++e) c[hh][nt][e] = 0.f;

            #pragma unroll
            for (int hh = 0; hh < 2; ++hh) {
                const int h = hp + hh;
                #pragma unroll
                for (int s = 0; s < 2; ++s) {
                    const int cq = h * 4 + s * 2;      // 16B chunks (head = 64B)
                    uint32_t a0, a1, a2, a3, p0, p1, p2, p3;
                    ldsm_x4(a0, a1, a2, a3, a_base + (((cq + a_coff) ^ l8) << 4));
                    ldsm_x4(p0, p1, p2, p3, b_base + (((cq + b_coff) ^ l8) << 4));
                    mma_fp8(c[hh][0], a0, a1, a2, a3, p0, p1);
                    mma_fp8(c[hh][1], a0, a1, a2, a3, p2, p3);
                }
            }

            #pragma unroll
            for (int hh = 0; hh < 2; ++hh) {
                const int h = hp + hh;
                float z0 = 0.f, z1 = 0.f;
                #pragma unroll
                for (int nt = 0; nt < 2; ++nt) {
                    c[hh][nt][0] = __expf(c[hh][nt][0] * 0.125f);
                    c[hh][nt][1] = __expf(c[hh][nt][1] * 0.125f);
                    c[hh][nt][2] = __expf(c[hh][nt][2] * 0.125f);
                    c[hh][nt][3] = __expf(c[hh][nt][3] * 0.125f);
                    z0 += c[hh][nt][0] + c[hh][nt][1];
                    z1 += c[hh][nt][2] + c[hh][nt][3];
                }
                z0 += __shfl_xor_sync(0xffffffffu, z0, 1);
                z0 += __shfl_xor_sync(0xffffffffu, z0, 2);
                z1 += __shfl_xor_sync(0xffffffffu, z1, 1);
                z1 += __shfl_xor_sync(0xffffffffu, z1, 2);
                if (qcol == 0) {
                    redf[h * WC * M + wc * M + wm + qrow]     = z0;
                    redf[h * WC * M + wc * M + wm + qrow + 8] = z1;
                }
            }
            __syncthreads();

            float rr[2][2];
            #pragma unroll
            for (int hh = 0; hh < 2; ++hh) {
                const int h = hp + hh;
                #pragma unroll
                for (int rp = 0; rp < 2; ++rp) {
                    float zz = 0.f;
                    #pragma unroll
                    for (int x = 0; x < WC; ++x)
                        zz += redf[h * WC * M + x * M + wm + qrow + rp * 8];
                    rr[hh][rp] = 0.25f / zz;
                }
            }

            #pragma unroll
            for (int nt = 0; nt < 2; ++nt) {
                am[nt][0] += c[0][nt][0] * rr[0][0] + c[1][nt][0] * rr[1][0];
                am[nt][1] += c[0][nt][1] * rr[0][0] + c[1][nt][1] * rr[1][0];
                am[nt][2] += c[0][nt][2] * rr[0][1] + c[1][nt][2] * rr[1][1];
                am[nt][3] += c[0][nt][3] * rr[0][1] + c[1][nt][3] * rr[1][1];
            }
        }

        #pragma unroll
        for (int nt = 0; nt < 2; ++nt) {
            const int colb = wn + nt * 8 + qcol * 2;
            *(float2*)&amf[(wm + qrow)     * AMS + colb] = make_float2(am[nt][0], am[nt][1]);
            *(float2*)&amf[(wm + qrow + 8) * AMS + colb] = make_float2(am[nt][2], am[nt][3]);
        }
        __syncthreads();

        float acc = 0.f;
        #pragma unroll
        for (int r2 = 0; r2 < 4; ++r2)
            acc += top3_sum<2>(&amf[(w * 4 + r2) * AMS], lane);
        if (lane == 0) waccf[w] = acc;
        __syncthreads();
        if (tid == 0) {
            float tot = 0.f;
            #pragma unroll
            for (int x = 0; x < 8; ++x) tot += waccf[x];
            const int i = cidx >> 3, slot = cidx & 7;
            part[((i * 32 + j) << 3) + slot] = tot;
        }
    }
}

// ---------------------------------------------------------------------------
// Kernel B2: t2v fused sim (fp8 scores). 256 thr, single group, M=16,
// NT=256 (WC=8). B tile 64KB -> ~88KB smem -> 2 CTAs/SM at 128 regs.
// ---------------------------------------------------------------------------
__global__ void __launch_bounds__(256, 2)
sim_t2v(const char* __restrict__ anch_q,
        const char* __restrict__ targ_k,
        float* __restrict__ part)
{
    constexpr int NT = 256, M = 16, NITER = 8, AMS = NT + 4;
    constexpr int OFF_B    = 0;                      // 256*256 = 65536
    constexpr int OFF_A    = OFF_B + NT * 256;       // 16*256  = 4096
    constexpr int OFF_AM   = OFF_A + M * 256;        // 16*260*4= 16640
    constexpr int OFF_RED  = OFF_AM + M * AMS * 4;   // 4*8*16*4= 2048
    constexpr int OFF_WACC = OFF_RED + 4 * 8 * M * 4;

    extern __shared__ char smem[];
    const uint32_t sbase = (uint32_t)__cvta_generic_to_shared(smem);

    const int j    = blockIdx.x;
    const int z    = blockIdx.y;
    const int tid  = threadIdx.x;
    const int w    = tid >> 5;
    const int lane = tid & 31;

    {
        const char* src = targ_k + (size_t)j * NT * 256;
        #pragma unroll
        for (int id = tid; id < NT * 16; id += 256)
            cpasync16(sbase + OFF_B + id * 16, src + id * 16);
        cpasync_commit();
    }

    const int wn = w * 32;
    const int l8  = lane & 7;
    const int sub = lane >> 3;
    const int qrow = lane >> 2;
    const int qcol = lane & 3;

    const uint32_t a_base = sbase + OFF_A + (uint32_t)(l8 + (sub & 1) * 8) * 256;
    const int      a_coff = sub >> 1;
    const uint32_t b_base = sbase + OFF_B + (uint32_t)(wn + l8 + ((sub >> 1) & 1) * 8) * 256;
    const int      b_coff = sub & 1;

    float* redf  = (float*)(smem + OFF_RED);
    float* amf   = (float*)(smem + OFF_AM);
    float* waccf = (float*)(smem + OFF_WACC);

    for (int it = 0; it < NITER; ++it) {
        const int cidx = z * NITER + it;

        __syncthreads();   // prev iter fully done before A/am overwrite
        {
            const char* src = anch_q + (size_t)cidx * M * 256;
            if (tid < M * 16)
                cpasync16(sbase + OFF_A + tid * 16, src + tid * 16);
            cpasync_commit();
            cpasync_wait_all();   // waits B too on first iter
        }
        __syncthreads();

        float am[4][4];
        #pragma unroll
        for (int nt = 0; nt < 4; ++nt)
            #pragma unroll
            for (int e = 0; e < 4; ++e) am[nt][e] = 0.f;

        #pragma unroll
        for (int hp = 0; hp < 4; hp += 2) {
            float c[2][4][4];
            #pragma unroll
            for (int hh = 0; hh < 2; ++hh)
                #pragma unroll
                for (int nt = 0; nt < 4; ++nt)
                    #pragma unroll
                    for (int e = 0; e < 4; ++e) c[hh][nt][e] = 0.f;

            #pragma unroll
            for (int hh = 0; hh < 2; ++hh) {
                const int h = hp + hh;
                #pragma unroll
                for (int s = 0; s < 2; ++s) {
                    const int cq = h * 4 + s * 2;
                    uint32_t a0, a1, a2, a3, p0, p1, p2, p3, q0, q1, q2, q3;
                    ldsm_x4(a0, a1, a2, a3, a_base + (((cq + a_coff) ^ l8) << 4));
                    ldsm_x4(p0, p1, p2, p3, b_base + (((cq + b_coff) ^ l8) << 4));
                    ldsm_x4(q0, q1, q2, q3, b_base + 16 * 256 + (((cq + b_coff) ^ l8) << 4));
                    mma_fp8(c[hh][0], a0, a1, a2, a3, p0, p1);
                    mma_fp8(c[hh][1], a0, a1, a2, a3, p2, p3);
                    mma_fp8(c[hh][2], a0, a1, a2, a3, q0, q1);
                    mma_fp8(c[hh][3], a0, a1, a2, a3, q2, q3);
                }
            }

            #pragma unroll
            for (int hh = 0; hh < 2; ++hh) {
                const int h = hp + hh;
                float z0 = 0.f, z1 = 0.f;
                #pragma unroll
                for (int nt = 0; nt < 4; ++nt) {
                    c[hh][nt][0] = __expf(c[hh][nt][0] * 0.125f);
                    c[hh][nt][1] = __expf(c[hh][nt][1] * 0.125f);
                    c[hh][nt][2] = __expf(c[hh][nt][2] * 0.125f);
                    c[hh][nt][3] = __expf(c[hh][nt][3] * 0.125f);
                    z0 += c[hh][nt][0] + c[hh][nt][1];
                    z1 += c[hh][nt][2] + c[hh][nt][3];
                }
                z0 += __shfl_xor_sync(0xffffffffu, z0, 1);
                z0 += __shfl_xor_sync(0xffffffffu, z0, 2);
                z1 += __shfl_xor_sync(0xffffffffu, z1, 1);
                z1 += __shfl_xor_sync(0xffffffffu, z1, 2);
                if (qcol == 0) {
                    redf[h * 8 * M + w * M + qrow]     = z0;
                    redf[h * 8 * M + w * M + qrow + 8] = z1;
                }
            }
            __syncthreads();

            float rr[2][2];
            #pragma unroll
            for (int hh = 0; hh < 2; ++hh) {
                const int h = hp + hh;
                #pragma unroll
                for (int rp = 0; rp < 2; ++rp) {
                    float zz = 0.f;
                    #pragma unroll
                    for (int x = 0; x < 8; ++x)
                        zz += redf[h * 8 * M + x * M + qrow + rp * 8];
                    rr[hh][rp] = 0.25f / zz;
                }
            }

            #pragma unroll
            for (int nt = 0; nt < 4; ++nt) {
                am[nt][0] += c[0][nt][0] * rr[0][0] + c[1][nt][0] * rr[1][0];
                am[nt][1] += c[0][nt][1] * rr[0][0] + c[1][nt][1] * rr[1][0];
                am[nt][2] += c[0][nt][2] * rr[0][1] + c[1][nt][2] * rr[1][1];
                am[nt][3] += c[0][nt][3] * rr[0][1] + c[1][nt][3] * rr[1][1];
            }
        }

        #pragma unroll
        for (int nt = 0; nt < 4; ++nt) {
            const int colb = wn + nt * 8 + qcol * 2;
            *(float2*)&amf[qrow       * AMS + colb] = make_float2(am[nt][0], am[nt][1]);
            *(float2*)&amf[(qrow + 8) * AMS + colb] = make_float2(am[nt][2], am[nt][3]);
        }
        __syncthreads();

        float acc = 0.f;
        acc += top3_sum<8>(&amf[(w * 2 + 0) * AMS], lane);
        acc += top3_sum<8>(&amf[(w * 2 + 1) * AMS], lane);
        if (lane == 0) waccf[w] = acc;
        __syncthreads();
        if (tid == 0) {
            float tot = 0.f;
            #pragma unroll
            for (int x = 0; x < 8; ++x) tot += waccf[x];
            const int i = cidx >> 2, slot = cidx & 3;
            part[((i * 32 + j) << 3) + slot] = tot;
        }
    }
}

// ---------------------------------------------------------------------------
// Kernel C: contrastive loss (8 slots per pair; unused slots stay zero)
// ---------------------------------------------------------------------------
__global__ void loss_kernel(const float* __restrict__ part, float* __restrict__ out)
{
    __shared__ float red[64];
    const int t   = threadIdx.x;
    const int dir = t >> 5;
    const int row = t & 31;
    const float* P = part + dir * 8192;
    const float scale = dir ? (100.f / (3.f * 64.f)) : (100.f / (3.f * 256.f));

    float pos = 0.f;
    float t1 = -1e30f, t2 = -1e30f, t3 = -1e30f;
    for (int j = 0; j < 32; ++j) {
        const float* q = &P[(row * 32 + j) << 3];
        float4 a = *(const float4*)q;
        float4 b = *(const float4*)(q + 4);
        float v = (a.x + a.y + a.z + a.w + b.x + b.y + b.z + b.w) * scale;
        if (j == row) { pos = v; continue; }
        if      (v > t1) { t3 = t2; t2 = t1; t1 = v; }
        else if (v > t2) { t3 = t2; t2 = v; }
        else if (v > t3) { t3 = v; }
    }
    const float invT = 1.0f / 0.07f;
    float l0 = pos * invT, l1 = t1 * invT, l2 = t2 * invT, l3 = t3 * invT;
    float m  = fmaxf(fmaxf(l0, l1), fmaxf(l2, l3));
    float Z  = expf(l0 - m) + expf(l1 - m) + expf(l2 - m) + expf(l3 - m);
    red[t] = -(l0 - m - logf(Z));
    __syncthreads();
    if (t == 0) {
        float s0 = 0.f, s1 = 0.f;
        for (int r = 0; r < 32; ++r) { s0 += red[r]; s1 += red[32 + r]; }
        out[0] = 0.5f * (s0 / 32.f) + 0.5f * (s1 / 32.f);
    }
}

// ---------------------------------------------------------------------------
// Launch: critical-path shaping (t2v needs {q_lang, k_vis} -> start early)
// ---------------------------------------------------------------------------
extern "C" void kernel_launch(void* const* d_in, const int* in_sizes, int n_in,
                              void* d_out, int out_size)
{
    const float* lang = (const float*)d_in[0];
    const float* vis  = (const float*)d_in[1];
    const float* W    = (const float*)d_in[2];
    const float* bias = (const float*)d_in[3];

    const int SM_PROJ = (128 * 68 + 64 * 68) * 4;   // 52,224
    const int SM_V2T  = 64*256 + 32*256 + 32*68*4 + 4*4*32*4 + 32;    // 35,360
    const int SM_T2V  = 256*256 + 16*256 + 16*260*4 + 4*8*16*4 + 32;  // 88,352

    static char *p_ql = nullptr, *p_kl = nullptr, *p_qv = nullptr, *p_kv = nullptr;
    static float *p_part = nullptr;
    static cudaStream_t s2;
    static cudaEvent_t evF, evLang, evT;
    if (!p_ql) {
        cudaGetSymbolAddress((void**)&p_ql, g_q_lang);
        cudaGetSymbolAddress((void**)&p_kl, g_k_lang);
        cudaGetSymbolAddress((void**)&p_qv, g_q_vis);
        cudaGetSymbolAddress((void**)&p_kv, g_k_vis);
        cudaGetSymbolAddress((void**)&p_part, g_part);
        cudaFuncSetAttribute((const void*)proj_tc,
                             cudaFuncAttributeMaxDynamicSharedMemorySize, SM_PROJ);
        cudaFuncSetAttribute((const void*)sim_v2t,
                             cudaFuncAttributeMaxDynamicSharedMemorySize, SM_V2T);
        cudaFuncSetAttribute((const void*)sim_t2v,
                             cudaFuncAttributeMaxDynamicSharedMemorySize, SM_T2V);
        cudaStreamCreateWithFlags(&s2, cudaStreamNonBlocking);
        cudaEventCreateWithFlags(&evF,    cudaEventDisableTiming);
        cudaEventCreateWithFlags(&evLang, cudaEventDisableTiming);
        cudaEventCreateWithFlags(&evT,    cudaEventDisableTiming);
    }

    // fork s2 into the captured graph
    cudaEventRecord(evF, 0);
    cudaStreamWaitEvent(s2, evF, 0);

    // s2: k-half of vis projection, then t2v (the long pole) ASAP
    proj_tc<<<dim3(4, 64), 256, SM_PROJ, s2>>>(vis, W, bias, 1, 4);   // k_vis

    // s0: lang projection (q_lang + k_lang), then q-half of vis
    proj_tc<<<dim3(8, 16), 256, SM_PROJ, 0>>>(lang, W, bias, 0, 0);   // q/k_lang
    cudaEventRecord(evLang, 0);
    proj_tc<<<dim3(4, 64), 256, SM_PROJ, 0>>>(vis, W, bias, 1, 0);    // q_vis

    // t2v: waits k_vis (s2 order) + q_lang (evLang)
    cudaStreamWaitEvent(s2, evLang, 0);
    sim_t2v<<<dim3(32, 16), 256, SM_T2V, s2>>>(p_ql, p_kv, p_part + 8192);

    // v2t: deps (k_lang, q_vis) are both earlier in s0
    sim_v2t<<<dim3(32, 16), 256, SM_V2T, 0>>>(p_qv, p_kl, p_part);

    // join before loss
    cudaEventRecord(evT, s2);
    cudaStreamWaitEvent(0, evT, 0);

    loss_kernel<<<1, 64, 0, 0>>>(p_part, (float*)d_out);
}

// round 15
// speedup vs baseline: 5.4299x; 1.1879x over previous
#include <cuda_runtime.h>
#include <cuda_bf16.h>
#include <math.h>
#include <stdint.h>

// ---------------------------------------------------------------------------
// Scratch (device globals; no allocation allowed)
// q/k stored as fp8 e4m3 in ldsm-swizzled layout: row stride 256B,
// byte_off(row, col) = row*256 + (((col>>4) ^ (row&7))<<4) + (col&15)
// ---------------------------------------------------------------------------
__device__ __align__(16) char g_q_lang[2048 * 256];
__device__ __align__(16) char g_k_lang[2048 * 256];
__device__ __align__(16) char g_q_vis [8192 * 256];
__device__ __align__(16) char g_k_vis [8192 * 256];
__device__ float g_part[2 * 32 * 32 * 8];   // [dir][i][j][slot], zero-init

// ---------------------------------------------------------------------------
// helpers
// ---------------------------------------------------------------------------
__device__ __forceinline__ uint16_t pack_fp8x2(float lo, float hi) {
    uint16_t r;
    asm("cvt.rn.satfinite.e4m3x2.f32 %0, %1, %2;" : "=h"(r) : "f"(hi), "f"(lo));
    return r;
}
__device__ __forceinline__ uint32_t f2tf32(float v) {
    uint32_t r;
    asm("cvt.rna.tf32.f32 %0, %1;" : "=r"(r) : "f"(v));
    return r;
}
__device__ __forceinline__ void mma_tf32(float c[4],
                                         uint32_t a0, uint32_t a1, uint32_t a2, uint32_t a3,
                                         uint32_t b0, uint32_t b1)
{
    asm volatile(
        "mma.sync.aligned.m16n8k8.row.col.f32.tf32.tf32.f32 "
        "{%0,%1,%2,%3}, {%4,%5,%6,%7}, {%8,%9}, {%0,%1,%2,%3};\n"
        : "+f"(c[0]), "+f"(c[1]), "+f"(c[2]), "+f"(c[3])
        : "r"(a0), "r"(a1), "r"(a2), "r"(a3), "r"(b0), "r"(b1));
}
__device__ __forceinline__ void cpasync16(uint32_t s, const void* g) {
    asm volatile("cp.async.cg.shared.global [%0], [%1], 16;\n" :: "r"(s), "l"(g));
}
__device__ __forceinline__ void cpasync_commit() {
    asm volatile("cp.async.commit_group;\n");
}
__device__ __forceinline__ void cpasync_wait_all() {
    asm volatile("cp.async.wait_group 0;\n");
}
__device__ __forceinline__ void ldsm_x4(uint32_t& r0, uint32_t& r1,
                                        uint32_t& r2, uint32_t& r3, uint32_t addr) {
    asm volatile("ldmatrix.sync.aligned.m8n8.x4.shared.b16 {%0,%1,%2,%3}, [%4];"
                 : "=r"(r0), "=r"(r1), "=r"(r2), "=r"(r3) : "r"(addr));
}
__device__ __forceinline__ void mma_fp8(float c[4],
                                        uint32_t a0, uint32_t a1, uint32_t a2, uint32_t a3,
                                        uint32_t b0, uint32_t b1) {
    asm volatile(
        "mma.sync.aligned.m16n8k32.row.col.f32.e4m3.e4m3.f32 "
        "{%0,%1,%2,%3}, {%4,%5,%6,%7}, {%8,%9}, {%0,%1,%2,%3};\n"
        : "+f"(c[0]), "+f"(c[1]), "+f"(c[2]), "+f"(c[3])
        : "r"(a0), "r"(a1), "r"(a2), "r"(a3), "r"(b0), "r"(b1));
}

// ---------------------------------------------------------------------------
// Kernel A: projection GEMM (tf32) -> fp8 swizzled q/k arrays
// ---------------------------------------------------------------------------
__global__ void __launch_bounds__(256) proj_tc(const float* __restrict__ X,
                                               const float* __restrict__ W,
                                               const float* __restrict__ bias,
                                               int which, int bx0)
{
    extern __shared__ uint32_t smemU[];
    uint32_t* As = smemU;               // [128][68]
    uint32_t* Bs = smemU + 128 * 68;    // [64][68]

    const int n0  = (blockIdx.x + bx0) * 64;
    const int m0  = blockIdx.y * 128;
    const int tid = threadIdx.x;
    const int w    = tid >> 5;
    const int lane = tid & 31;

    const int wm = (w & 3) * 32;
    const int wn = (w >> 2) * 32;
    const int qrow = lane >> 2;
    const int qcol = lane & 3;

    float c[2][4][4] = {};

    for (int k0 = 0; k0 < 256; k0 += 64) {
        __syncthreads();
        #pragma unroll
        for (int it = 0; it < 8; ++it) {
            int id = tid + it * 256;
            int r  = id >> 4;
            int q  = id & 15;
            float4 v = *(const float4*)(X + (size_t)(m0 + r) * 256 + k0 + q * 4);
            uint32_t* d = As + r * 68 + q * 4;
            d[0] = f2tf32(v.x); d[1] = f2tf32(v.y); d[2] = f2tf32(v.z); d[3] = f2tf32(v.w);
        }
        #pragma unroll
        for (int it = 0; it < 4; ++it) {
            int id = tid + it * 256;
            int r  = id >> 4;
            int q  = id & 15;
            float4 v = *(const float4*)(W + (size_t)(n0 + r) * 256 + k0 + q * 4);
            uint32_t* d = Bs + r * 68 + q * 4;
            d[0] = f2tf32(v.x); d[1] = f2tf32(v.y); d[2] = f2tf32(v.z); d[3] = f2tf32(v.w);
        }
        __syncthreads();

        const uint32_t* Aw = As + wm * 68;
        const uint32_t* Bw = Bs + wn * 68;
        #pragma unroll
        for (int kk = 0; kk < 8; ++kk) {
            uint32_t a[2][4];
            #pragma unroll
            for (int mt = 0; mt < 2; ++mt) {
                const uint32_t* p = Aw + (mt * 16 + qrow) * 68 + kk * 8 + qcol;
                a[mt][0] = p[0];
                a[mt][1] = p[8 * 68];
                a[mt][2] = p[4];
                a[mt][3] = p[8 * 68 + 4];
            }
            uint32_t b[4][2];
            #pragma unroll
            for (int nt = 0; nt < 4; ++nt) {
                const uint32_t* p = Bw + (nt * 8 + qrow) * 68 + kk * 8 + qcol;
                b[nt][0] = p[0];
                b[nt][1] = p[4];
            }
            #pragma unroll
            for (int mt = 0; mt < 2; ++mt)
                #pragma unroll
                for (int nt = 0; nt < 4; ++nt)
                    mma_tf32(c[mt][nt], a[mt][0], a[mt][1], a[mt][2], a[mt][3],
                             b[nt][0], b[nt][1]);
        }
    }

    const bool isq = (n0 < 256);
    char* arr = which ? (isq ? g_q_vis : g_k_vis) : (isq ? g_q_lang : g_k_lang);

    #pragma unroll
    for (int mt = 0; mt < 2; ++mt) {
        #pragma unroll
        for (int nt = 0; nt < 4; ++nt) {
            const int n  = n0 + wn + nt * 8 + qcol * 2;
            const int cl = n & 255;
            const float b0 = __ldg(bias + n), b1 = __ldg(bias + n + 1);
            const int r0 = m0 + wm + mt * 16 + qrow;
            const int r1 = r0 + 8;
            uint16_t v0 = pack_fp8x2(c[mt][nt][0] + b0, c[mt][nt][1] + b1);
            uint16_t v1 = pack_fp8x2(c[mt][nt][2] + b0, c[mt][nt][3] + b1);
            uint32_t o0 = (uint32_t)r0 * 256 + ((((cl >> 4) ^ (r0 & 7)) << 4) | (cl & 15));
            uint32_t o1 = (uint32_t)r1 * 256 + ((((cl >> 4) ^ (r1 & 7)) << 4) | (cl & 15));
            *(uint16_t*)(arr + o0) = v0;
            *(uint16_t*)(arr + o1) = v1;
        }
    }
}

// ---------------------------------------------------------------------------
// top3 helper — branchless sorted-triple local insert + shuffle merge.
// Merge of two descending triples (a1>=a2>=a3), (b1>=b2>=b3):
//   c1 = max(a1,b1)
//   c2 = max(min(a1,b1), max(a2,b2))
//   c3 = max(max(min(a1,b2), min(a2,b1)), max(a3,b3))
// ---------------------------------------------------------------------------
template<int NB>
__device__ __forceinline__ float top3_sum(const float* v, int lane) {
    float t1 = -1e30f, t2 = -1e30f, t3 = -1e30f;
    #pragma unroll
    for (int bi = 0; bi < NB; ++bi) {
        float x  = v[bi * 32 + lane];
        float m2 = fminf(t1, x);
        t1 = fmaxf(t1, x);
        t3 = fmaxf(t3, fminf(t2, m2));
        t2 = fmaxf(t2, m2);
    }
    #pragma unroll
    for (int off = 16; off; off >>= 1) {
        float o1 = __shfl_xor_sync(0xffffffffu, t1, off);
        float o2 = __shfl_xor_sync(0xffffffffu, t2, off);
        float o3 = __shfl_xor_sync(0xffffffffu, t3, off);
        float c1 = fmaxf(t1, o1);
        float c2 = fmaxf(fminf(t1, o1), fmaxf(t2, o2));
        float c3 = fmaxf(fmaxf(fminf(t1, o2), fminf(t2, o1)), fmaxf(t3, o3));
        t1 = c1; t2 = c2; t3 = c3;
    }
    return t1 + t2 + t3;
}

// ---------------------------------------------------------------------------
// Kernel B1: v2t fused sim (fp8 scores). WR=2, WC=4: M=32, NT=64.
// 256 thr, 3 CTAs/SM. NITER=16, 8 slots/batch-pair (256 chunks / 32 batches).
// ---------------------------------------------------------------------------
__global__ void __launch_bounds__(256, 3)
sim_v2t(const char* __restrict__ anch_q,
        const char* __restrict__ targ_k,
        float* __restrict__ part)
{
    constexpr int WC = 4, M = 32, NT = 64, NITER = 16;
    constexpr int AMS = NT + 4;
    constexpr int OFF_B    = 0;
    constexpr int OFF_A    = OFF_B + NT * 256;
    constexpr int OFF_AM   = OFF_A + M * 256;
    constexpr int OFF_RED  = OFF_AM + M * AMS * 4;
    constexpr int OFF_WACC = OFF_RED + 4 * WC * M * 4;

    extern __shared__ char smem[];
    const uint32_t sbase = (uint32_t)__cvta_generic_to_shared(smem);

    const int j    = blockIdx.x;
    const int z    = blockIdx.y;
    const int tid  = threadIdx.x;
    const int w    = tid >> 5;
    const int lane = tid & 31;

    {
        const char* src = targ_k + (size_t)j * NT * 256;
        #pragma unroll
        for (int id = tid; id < NT * 16; id += 256)
            cpasync16(sbase + OFF_B + id * 16, src + id * 16);
        cpasync_commit();
    }

    const int wm = (w >> 2) * 16;
    const int wn = (w & 3) * 16;
    const int wc = w & 3;
    const int l8  = lane & 7;
    const int sub = lane >> 3;
    const int qrow = lane >> 2;
    const int qcol = lane & 3;

    const uint32_t a_base = sbase + OFF_A + (uint32_t)(wm + l8 + (sub & 1) * 8) * 256;
    const int      a_coff = sub >> 1;
    const uint32_t b_base = sbase + OFF_B + (uint32_t)(wn + l8 + ((sub >> 1) & 1) * 8) * 256;
    const int      b_coff = sub & 1;

    float* redf  = (float*)(smem + OFF_RED);
    float* amf   = (float*)(smem + OFF_AM);
    float* waccf = (float*)(smem + OFF_WACC);

    for (int it = 0; it < NITER; ++it) {
        const int cidx = z * NITER + it;

        __syncthreads();
        {
            const char* src = anch_q + (size_t)cidx * M * 256;
            #pragma unroll
            for (int id = tid; id < M * 16; id += 256)
                cpasync16(sbase + OFF_A + id * 16, src + id * 16);
            cpasync_commit();
            cpasync_wait_all();
        }
        __syncthreads();

        float am[2][4];
        #pragma unroll
        for (int nt = 0; nt < 2; ++nt)
            #pragma unroll
            for (int e = 0; e < 4; ++e) am[nt][e] = 0.f;

        #pragma unroll
        for (int hp = 0; hp < 4; hp += 2) {
            float c[2][2][4];
            #pragma unroll
            for (int hh = 0; hh < 2; ++hh)
                #pragma unroll
                for (int nt = 0; nt < 2; ++nt)
                    #pragma unroll
                    for (int e = 0; e < 4; ++e) c[hh][nt][e] = 0.f;

            #pragma unroll
            for (int hh = 0; hh < 2; ++hh) {
                const int h = hp + hh;
                #pragma unroll
                for (int s = 0; s < 2; ++s) {
                    const int cq = h * 4 + s * 2;
                    uint32_t a0, a1, a2, a3, p0, p1, p2, p3;
                    ldsm_x4(a0, a1, a2, a3, a_base + (((cq + a_coff) ^ l8) << 4));
                    ldsm_x4(p0, p1, p2, p3, b_base + (((cq + b_coff) ^ l8) << 4));
                    mma_fp8(c[hh][0], a0, a1, a2, a3, p0, p1);
                    mma_fp8(c[hh][1], a0, a1, a2, a3, p2, p3);
                }
            }

            #pragma unroll
            for (int hh = 0; hh < 2; ++hh) {
                const int h = hp + hh;
                float z0 = 0.f, z1 = 0.f;
                #pragma unroll
                for (int nt = 0; nt < 2; ++nt) {
                    c[hh][nt][0] = __expf(c[hh][nt][0] * 0.125f);
                    c[hh][nt][1] = __expf(c[hh][nt][1] * 0.125f);
                    c[hh][nt][2] = __expf(c[hh][nt][2] * 0.125f);
                    c[hh][nt][3] = __expf(c[hh][nt][3] * 0.125f);
                    z0 += c[hh][nt][0] + c[hh][nt][1];
                    z1 += c[hh][nt][2] + c[hh][nt][3];
                }
                z0 += __shfl_xor_sync(0xffffffffu, z0, 1);
                z0 += __shfl_xor_sync(0xffffffffu, z0, 2);
                z1 += __shfl_xor_sync(0xffffffffu, z1, 1);
                z1 += __shfl_xor_sync(0xffffffffu, z1, 2);
                if (qcol == 0) {
                    redf[h * WC * M + wc * M + wm + qrow]     = z0;
                    redf[h * WC * M + wc * M + wm + qrow + 8] = z1;
                }
            }
            __syncthreads();

            float rr[2][2];
            #pragma unroll
            for (int hh = 0; hh < 2; ++hh) {
                const int h = hp + hh;
                #pragma unroll
                for (int rp = 0; rp < 2; ++rp) {
                    float zz = 0.f;
                    #pragma unroll
                    for (int x = 0; x < WC; ++x)
                        zz += redf[h * WC * M + x * M + wm + qrow + rp * 8];
                    rr[hh][rp] = 0.25f / zz;
                }
            }

            #pragma unroll
            for (int nt = 0; nt < 2; ++nt) {
                am[nt][0] += c[0][nt][0] * rr[0][0] + c[1][nt][0] * rr[1][0];
                am[nt][1] += c[0][nt][1] * rr[0][0] + c[1][nt][1] * rr[1][0];
                am[nt][2] += c[0][nt][2] * rr[0][1] + c[1][nt][2] * rr[1][1];
                am[nt][3] += c[0][nt][3] * rr[0][1] + c[1][nt][3] * rr[1][1];
            }
        }

        #pragma unroll
        for (int nt = 0; nt < 2; ++nt) {
            const int colb = wn + nt * 8 + qcol * 2;
            *(float2*)&amf[(wm + qrow)     * AMS + colb] = make_float2(am[nt][0], am[nt][1]);
            *(float2*)&amf[(wm + qrow + 8) * AMS + colb] = make_float2(am[nt][2], am[nt][3]);
        }
        __syncthreads();

        float acc = 0.f;
        #pragma unroll
        for (int r2 = 0; r2 < 4; ++r2)
            acc += top3_sum<2>(&amf[(w * 4 + r2) * AMS], lane);
        if (lane == 0) waccf[w] = acc;
        __syncthreads();
        if (tid == 0) {
            float tot = 0.f;
            #pragma unroll
            for (int x = 0; x < 8; ++x) tot += waccf[x];
            const int i = cidx >> 3, slot = cidx & 7;   // 8 chunks per batch
            part[((i * 32 + j) << 3) + slot] = tot;
        }
    }
}

// ---------------------------------------------------------------------------
// Kernel B2: t2v fused sim (fp8 scores). 256 thr, M=16, NT=256.
// grid (32,8) x NITER=16 -> 256 blocks = single wave at 2 CTAs/SM.
// Chunks per batch = 64/16 = 4 -> slot decode is >>2 / &3.
// ---------------------------------------------------------------------------
__global__ void __launch_bounds__(256, 2)
sim_t2v(const char* __restrict__ anch_q,
        const char* __restrict__ targ_k,
        float* __restrict__ part)
{
    constexpr int NT = 256, M = 16, NITER = 16, AMS = NT + 4;
    constexpr int OFF_B    = 0;
    constexpr int OFF_A    = OFF_B + NT * 256;
    constexpr int OFF_AM   = OFF_A + M * 256;
    constexpr int OFF_RED  = OFF_AM + M * AMS * 4;
    constexpr int OFF_WACC = OFF_RED + 4 * 8 * M * 4;

    extern __shared__ char smem[];
    const uint32_t sbase = (uint32_t)__cvta_generic_to_shared(smem);

    const int j    = blockIdx.x;
    const int z    = blockIdx.y;
    const int tid  = threadIdx.x;
    const int w    = tid >> 5;
    const int lane = tid & 31;

    {
        const char* src = targ_k + (size_t)j * NT * 256;
        #pragma unroll
        for (int id = tid; id < NT * 16; id += 256)
            cpasync16(sbase + OFF_B + id * 16, src + id * 16);
        cpasync_commit();
    }

    const int wn = w * 32;
    const int l8  = lane & 7;
    const int sub = lane >> 3;
    const int qrow = lane >> 2;
    const int qcol = lane & 3;

    const uint32_t a_base = sbase + OFF_A + (uint32_t)(l8 + (sub & 1) * 8) * 256;
    const int      a_coff = sub >> 1;
    const uint32_t b_base = sbase + OFF_B + (uint32_t)(wn + l8 + ((sub >> 1) & 1) * 8) * 256;
    const int      b_coff = sub & 1;

    float* redf  = (float*)(smem + OFF_RED);
    float* amf   = (float*)(smem + OFF_AM);
    float* waccf = (float*)(smem + OFF_WACC);

    for (int it = 0; it < NITER; ++it) {
        const int cidx = z * NITER + it;

        __syncthreads();
        {
            const char* src = anch_q + (size_t)cidx * M * 256;
            if (tid < M * 16)
                cpasync16(sbase + OFF_A + tid * 16, src + tid * 16);
            cpasync_commit();
            cpasync_wait_all();
        }
        __syncthreads();

        float am[4][4];
        #pragma unroll
        for (int nt = 0; nt < 4; ++nt)
            #pragma unroll
            for (int e = 0; e < 4; ++e) am[nt][e] = 0.f;

        #pragma unroll
        for (int hp = 0; hp < 4; hp += 2) {
            float c[2][4][4];
            #pragma unroll
            for (int hh = 0; hh < 2; ++hh)
                #pragma unroll
                for (int nt = 0; nt < 4; ++nt)
                    #pragma unroll
                    for (int e = 0; e < 4; ++e) c[hh][nt][e] = 0.f;

            #pragma unroll
            for (int hh = 0; hh < 2; ++hh) {
                const int h = hp + hh;
                #pragma unroll
                for (int s = 0; s < 2; ++s) {
                    const int cq = h * 4 + s * 2;
                    uint32_t a0, a1, a2, a3, p0, p1, p2, p3, q0, q1, q2, q3;
                    ldsm_x4(a0, a1, a2, a3, a_base + (((cq + a_coff) ^ l8) << 4));
                    ldsm_x4(p0, p1, p2, p3, b_base + (((cq + b_coff) ^ l8) << 4));
                    ldsm_x4(q0, q1, q2, q3, b_base + 16 * 256 + (((cq + b_coff) ^ l8) << 4));
                    mma_fp8(c[hh][0], a0, a1, a2, a3, p0, p1);
                    mma_fp8(c[hh][1], a0, a1, a2, a3, p2, p3);
                    mma_fp8(c[hh][2], a0, a1, a2, a3, q0, q1);
                    mma_fp8(c[hh][3], a0, a1, a2, a3, q2, q3);
                }
            }

            #pragma unroll
            for (int hh = 0; hh < 2; ++hh) {
                const int h = hp + hh;
                float z0 = 0.f, z1 = 0.f;
                #pragma unroll
                for (int nt = 0; nt < 4; ++nt) {
                    c[hh][nt][0] = __expf(c[hh][nt][0] * 0.125f);
                    c[hh][nt][1] = __expf(c[hh][nt][1] * 0.125f);
                    c[hh][nt][2] = __expf(c[hh][nt][2] * 0.125f);
                    c[hh][nt][3] = __expf(c[hh][nt][3] * 0.125f);
                    z0 += c[hh][nt][0] + c[hh][nt][1];
                    z1 += c[hh][nt][2] + c[hh][nt][3];
                }
                z0 += __shfl_xor_sync(0xffffffffu, z0, 1);
                z0 += __shfl_xor_sync(0xffffffffu, z0, 2);
                z1 += __shfl_xor_sync(0xffffffffu, z1, 1);
                z1 += __shfl_xor_sync(0xffffffffu, z1, 2);
                if (qcol == 0) {
                    redf[h * 8 * M + w * M + qrow]     = z0;
                    redf[h * 8 * M + w * M + qrow + 8] = z1;
                }
            }
            __syncthreads();

            float rr[2][2];
            #pragma unroll
            for (int hh = 0; hh < 2; ++hh) {
                const int h = hp + hh;
                #pragma unroll
                for (int rp = 0; rp < 2; ++rp) {
                    float zz = 0.f;
                    #pragma unroll
                    for (int x = 0; x < 8; ++x)
                        zz += redf[h * 8 * M + x * M + qrow + rp * 8];
                    rr[hh][rp] = 0.25f / zz;
                }
            }

            #pragma unroll
            for (int nt = 0; nt < 4; ++nt) {
                am[nt][0] += c[0][nt][0] * rr[0][0] + c[1][nt][0] * rr[1][0];
                am[nt][1] += c[0][nt][1] * rr[0][0] + c[1][nt][1] * rr[1][0];
                am[nt][2] += c[0][nt][2] * rr[0][1] + c[1][nt][2] * rr[1][1];
                am[nt][3] += c[0][nt][3] * rr[0][1] + c[1][nt][3] * rr[1][1];
            }
        }

        #pragma unroll
        for (int nt = 0; nt < 4; ++nt) {
            const int colb = wn + nt * 8 + qcol * 2;
            *(float2*)&amf[qrow       * AMS + colb] = make_float2(am[nt][0], am[nt][1]);
            *(float2*)&amf[(qrow + 8) * AMS + colb] = make_float2(am[nt][2], am[nt][3]);
        }
        __syncthreads();

        float acc = 0.f;
        acc += top3_sum<8>(&amf[(w * 2 + 0) * AMS], lane);
        acc += top3_sum<8>(&amf[(w * 2 + 1) * AMS], lane);
        if (lane == 0) waccf[w] = acc;
        __syncthreads();
        if (tid == 0) {
            float tot = 0.f;
            #pragma unroll
            for (int x = 0; x < 8; ++x) tot += waccf[x];
            const int i = cidx >> 2, slot = cidx & 3;   // 4 chunks per batch (FIX)
            part[((i * 32 + j) << 3) + slot] = tot;
        }
    }
}

// ---------------------------------------------------------------------------
// Kernel C: contrastive loss (8 slots per pair; unused slots stay zero)
// ---------------------------------------------------------------------------
__global__ void loss_kernel(const float* __restrict__ part, float* __restrict__ out)
{
    __shared__ float red[64];
    const int t   = threadIdx.x;
    const int dir = t >> 5;
    const int row = t & 31;
    const float* P = part + dir * 8192;
    const float scale = dir ? (100.f / (3.f * 64.f)) : (100.f / (3.f * 256.f));

    float pos = 0.f;
    float t1 = -1e30f, t2 = -1e30f, t3 = -1e30f;
    for (int j = 0; j < 32; ++j) {
        const float* q = &P[(row * 32 + j) << 3];
        float4 a = *(const float4*)q;
        float4 b = *(const float4*)(q + 4);
        float v = (a.x + a.y + a.z + a.w + b.x + b.y + b.z + b.w) * scale;
        if (j == row) { pos = v; continue; }
        if      (v > t1) { t3 = t2; t2 = t1; t1 = v; }
        else if (v > t2) { t3 = t2; t2 = v; }
        else if (v > t3) { t3 = v; }
    }
    const float invT = 1.0f / 0.07f;
    float l0 = pos * invT, l1 = t1 * invT, l2 = t2 * invT, l3 = t3 * invT;
    float m  = fmaxf(fmaxf(l0, l1), fmaxf(l2, l3));
    float Z  = expf(l0 - m) + expf(l1 - m) + expf(l2 - m) + expf(l3 - m);
    red[t] = -(l0 - m - logf(Z));
    __syncthreads();
    if (t == 0) {
        float s0 = 0.f, s1 = 0.f;
        for (int r = 0; r < 32; ++r) { s0 += red[r]; s1 += red[32 + r]; }
        out[0] = 0.5f * (s0 / 32.f) + 0.5f * (s1 / 32.f);
    }
}

// ---------------------------------------------------------------------------
// Launch: critical-path shaping (t2v needs {q_lang, k_vis} -> start early)
// ---------------------------------------------------------------------------
extern "C" void kernel_launch(void* const* d_in, const int* in_sizes, int n_in,
                              void* d_out, int out_size)
{
    const float* lang = (const float*)d_in[0];
    const float* vis  = (const float*)d_in[1];
    const float* W    = (const float*)d_in[2];
    const float* bias = (const float*)d_in[3];

    const int SM_PROJ = (128 * 68 + 64 * 68) * 4;   // 52,224
    const int SM_V2T  = 64*256 + 32*256 + 32*68*4 + 4*4*32*4 + 32;    // 35,360
    const int SM_T2V  = 256*256 + 16*256 + 16*260*4 + 4*8*16*4 + 32;  // 88,352

    static char *p_ql = nullptr, *p_kl = nullptr, *p_qv = nullptr, *p_kv = nullptr;
    static float *p_part = nullptr;
    static cudaStream_t s2;
    static cudaEvent_t evF, evLang, evT;
    if (!p_ql) {
        cudaGetSymbolAddress((void**)&p_ql, g_q_lang);
        cudaGetSymbolAddress((void**)&p_kl, g_k_lang);
        cudaGetSymbolAddress((void**)&p_qv, g_q_vis);
        cudaGetSymbolAddress((void**)&p_kv, g_k_vis);
        cudaGetSymbolAddress((void**)&p_part, g_part);
        cudaFuncSetAttribute((const void*)proj_tc,
                             cudaFuncAttributeMaxDynamicSharedMemorySize, SM_PROJ);
        cudaFuncSetAttribute((const void*)sim_v2t,
                             cudaFuncAttributeMaxDynamicSharedMemorySize, SM_V2T);
        cudaFuncSetAttribute((const void*)sim_t2v,
                             cudaFuncAttributeMaxDynamicSharedMemorySize, SM_T2V);
        cudaStreamCreateWithFlags(&s2, cudaStreamNonBlocking);
        cudaEventCreateWithFlags(&evF,    cudaEventDisableTiming);
        cudaEventCreateWithFlags(&evLang, cudaEventDisableTiming);
        cudaEventCreateWithFlags(&evT,    cudaEventDisableTiming);
    }

    // fork s2 into the captured graph
    cudaEventRecord(evF, 0);
    cudaStreamWaitEvent(s2, evF, 0);

    // s2: k-half of vis projection, then t2v (the long pole) ASAP
    proj_tc<<<dim3(4, 64), 256, SM_PROJ, s2>>>(vis, W, bias, 1, 4);   // k_vis

    // s0: lang projection (q_lang + k_lang), then q-half of vis
    proj_tc<<<dim3(8, 16), 256, SM_PROJ, 0>>>(lang, W, bias, 0, 0);   // q/k_lang
    cudaEventRecord(evLang, 0);
    proj_tc<<<dim3(4, 64), 256, SM_PROJ, 0>>>(vis, W, bias, 1, 0);    // q_vis

    // t2v: waits k_vis (s2 order) + q_lang (evLang)
    cudaStreamWaitEvent(s2, evLang, 0);
    sim_t2v<<<dim3(32, 8), 256, SM_T2V, s2>>>(p_ql, p_kv, p_part + 8192);

    // v2t: deps (k_lang, q_vis) are both earlier in s0
    sim_v2t<<<dim3(32, 16), 256, SM_V2T, 0>>>(p_qv, p_kl, p_part);

    // join before loss
    cudaEventRecord(evT, s2);
    cudaStreamWaitEvent(0, evT, 0);

    loss_kernel<<<1, 64, 0, 0>>>(p_part, (float*)d_out);
}